// round 10
// baseline (speedup 1.0000x reference)
#include <cuda_runtime.h>
#include <cuda_fp16.h>
#include <cstdint>

// ---------------------------------------------------------------------------
// BigBird transformer block on sm_103 (non-'a' target: no tcgen05/TMEM).
// R10: correction products (magnitude ~2^-11 of main) moved to fp16-acc
// HMMA (hypothesis: rt 8 vs fp32-acc rt 16). Main hi.hi products stay fp32.
// fp16 correction accumulators folded into fp32 at tile/epilogue boundaries.
// Added error ~2^-22 relative: rel_err expected unchanged (~3.2e-4).
// ---------------------------------------------------------------------------

namespace {
constexpr int Bn    = 2;
constexpr int Sn    = 4096;
constexpr int Dn    = 1024;
constexpr int Hn    = 16;
constexpr int DHn   = 64;
constexpr int NBn   = 64;
constexpr int NGn   = 2;
constexpr int NMIDn = 60;
constexpr int Mrows = Bn * Sn;              // 8192

// GEMM tiling
constexpr int BK      = 32;
constexpr int NCHUNK  = Dn / BK;             // 32
constexpr int ROWB    = 80;
constexpr int MATB    = 128 * ROWB;          // 10240
constexpr int STG     = 3 * MATB;            // 30720 B / stage
constexpr int GEMM_SMEM = 3 * STG;           // 92160 B

// attention smem
constexpr int AROW    = 144;
constexpr int AMAT    = 64 * AROW;           // 9216 B
constexpr int ASTAGE  = 4 * AMAT;            // 36864 B
constexpr int AQ_BYTES = 2 * AMAT;
constexpr int ATTN_SMEM = AQ_BYTES + 2 * ASTAGE;  // 92160 B
}

// ---- scratch (device globals) ----------------------------------------------
__device__ __half g_qhi[Bn * Hn * Sn * DHn], g_qlo[Bn * Hn * Sn * DHn];
__device__ __half g_khi[Bn * Hn * Sn * DHn], g_klo[Bn * Hn * Sn * DHn];
__device__ __half g_vhi[Bn * Hn * Sn * DHn], g_vlo[Bn * Hn * Sn * DHn];
__device__ __half g_Ahi[Mrows * Dn],  g_Alo[Mrows * Dn];
__device__ __half g_Bqkv_h[3 * Dn * Dn];
__device__ __half g_Bu_h[Dn * Dn];
__device__ __half g_Chi[Mrows * Dn],  g_Clo[Mrows * Dn];

// ---------------------------------------------------------------------------
// PTX helpers
// ---------------------------------------------------------------------------
__device__ __forceinline__ uint32_t smem_u32(const void* p) {
    uint32_t a;
    asm("{ .reg .u64 t; cvta.to.shared.u64 t, %1; cvt.u32.u64 %0, t; }" : "=r"(a) : "l"(p));
    return a;
}
__device__ __forceinline__ void cpa16(uint32_t dst, const void* src) {
    asm volatile("cp.async.cg.shared.global [%0], [%1], 16;" :: "r"(dst), "l"(src));
}
__device__ __forceinline__ void cpa_commit() {
    asm volatile("cp.async.commit_group;" ::: "memory");
}
template <int N>
__device__ __forceinline__ void cpa_wait() {
    asm volatile("cp.async.wait_group %0;" :: "n"(N) : "memory");
}
__device__ __forceinline__ void ldm4(uint32_t* r, uint32_t addr) {
    asm volatile("ldmatrix.sync.aligned.m8n8.x4.shared.b16 {%0,%1,%2,%3}, [%4];"
                 : "=r"(r[0]), "=r"(r[1]), "=r"(r[2]), "=r"(r[3]) : "r"(addr));
}
__device__ __forceinline__ void ldm4t(uint32_t* r, uint32_t addr) {
    asm volatile("ldmatrix.sync.aligned.m8n8.x4.trans.shared.b16 {%0,%1,%2,%3}, [%4];"
                 : "=r"(r[0]), "=r"(r[1]), "=r"(r[2]), "=r"(r[3]) : "r"(addr));
}
// fp32-accumulator HMMA
__device__ __forceinline__ void mma16816(float* c, const uint32_t* a,
                                         uint32_t b0, uint32_t b1) {
    asm volatile(
        "mma.sync.aligned.m16n8k16.row.col.f32.f16.f16.f32 "
        "{%0,%1,%2,%3}, {%4,%5,%6,%7}, {%8,%9}, {%0,%1,%2,%3};"
        : "+f"(c[0]), "+f"(c[1]), "+f"(c[2]), "+f"(c[3])
        : "r"(a[0]), "r"(a[1]), "r"(a[2]), "r"(a[3]), "r"(b0), "r"(b1));
}
// fp16-accumulator HMMA (corrections only)
__device__ __forceinline__ void mma16816_h(uint32_t* c, const uint32_t* a,
                                           uint32_t b0, uint32_t b1) {
    asm volatile(
        "mma.sync.aligned.m16n8k16.row.col.f16.f16.f16.f16 "
        "{%0,%1}, {%2,%3,%4,%5}, {%6,%7}, {%0,%1};"
        : "+r"(c[0]), "+r"(c[1])
        : "r"(a[0]), "r"(a[1]), "r"(a[2]), "r"(a[3]), "r"(b0), "r"(b1));
}
// fold fp16 correction accumulator into fp32 accumulator, then zero it.
// fp16 C layout: reg0 = (c0,c1) of row lane>>2; reg1 = same cols of row+8.
__device__ __forceinline__ void fold_h(float* c, uint32_t* h) {
    const __half2 a = *reinterpret_cast<__half2*>(&h[0]);
    const __half2 b = *reinterpret_cast<__half2*>(&h[1]);
    c[0] += __low2float(a);  c[1] += __high2float(a);
    c[2] += __low2float(b);  c[3] += __high2float(b);
    h[0] = 0u; h[1] = 0u;
}
__device__ __forceinline__ void hsplit(float v, __half& h, __half& l) {
    h = __float2half_rn(v);
    l = __float2half_rn(v - __half2float(h));
}
__device__ __forceinline__ void hsplit_pack(float v0, float v1,
                                            uint32_t& hp, uint32_t& lp) {
    __half2 h = __floats2half2_rn(v0, v1);
    __half2 l = __floats2half2_rn(v0 - __low2float(h), v1 - __high2float(h));
    hp = *reinterpret_cast<uint32_t*>(&h);
    lp = *reinterpret_cast<uint32_t*>(&l);
}

// ---------------------------------------------------------------------------
// prep kernels
// ---------------------------------------------------------------------------
__global__ void split_k(const float* __restrict__ X,
                        __half* __restrict__ Hi, __half* __restrict__ Lo, int n4)
{
    for (int i = blockIdx.x * blockDim.x + threadIdx.x; i < n4;
         i += gridDim.x * blockDim.x) {
        float4 v = ((const float4*)X)[i];
        __half2 h01 = __floats2half2_rn(v.x, v.y);
        __half2 h23 = __floats2half2_rn(v.z, v.w);
        __half2 l01 = __floats2half2_rn(v.x - __low2float(h01), v.y - __high2float(h01));
        __half2 l23 = __floats2half2_rn(v.z - __low2float(h23), v.w - __high2float(h23));
        *(__half2*)(Hi + 4 * i)     = h01;
        *(__half2*)(Hi + 4 * i + 2) = h23;
        *(__half2*)(Lo + 4 * i)     = l01;
        *(__half2*)(Lo + 4 * i + 2) = l23;
    }
}

__global__ void packW_all(const float* __restrict__ Wq, const float* __restrict__ Wk,
                          const float* __restrict__ Wv, const float* __restrict__ Wu)
{
    __shared__ float tile[32][33];
    const int z = blockIdx.z;
    const float* W = (z == 0) ? Wq : (z == 1) ? Wk : (z == 2) ? Wv : Wu;
    __half* Bh = (z < 3) ? g_Bqkv_h : g_Bu_h;
    const int nOff = (z < 3) ? z * 1024 : 0;

    const int tx = threadIdx.x, ty = threadIdx.y;
    const int n0 = blockIdx.x * 32, k0 = blockIdx.y * 32;
#pragma unroll
    for (int j = 0; j < 4; j++)
        tile[ty + j * 8][tx] = W[(size_t)(k0 + ty + j * 8) * Dn + n0 + tx];
    __syncthreads();
    const int kk = k0 + tx;
#pragma unroll
    for (int j = 0; j < 4; j++) {
        const int n = n0 + ty + j * 8;
        Bh[(size_t)(nOff + n) * Dn + kk] = __float2half_rn(tile[tx][ty + j * 8]);
    }
}

// ---------------------------------------------------------------------------
// GEMM: Ah.Bh in fp32-acc, Al.Bh in fp16-acc (folded at epilogue).
// ---------------------------------------------------------------------------
template <int MODE>
__global__ void __launch_bounds__(256)
hmma_gemm(const __half* __restrict__ Ahi, const __half* __restrict__ Alo,
          const __half* __restrict__ Bh,
          const float* __restrict__ bias, float* __restrict__ Cout)
{
    extern __shared__ char smem[];
    const uint32_t sb = smem_u32(smem);
    const int t    = threadIdx.x;
    const int lane = t & 31;
    const int wid  = t >> 5;
    const int wm   = (wid & 1) << 6;
    const int wn   = (wid >> 1) << 5;
    const int m0   = blockIdx.y << 7;
    const int n0   = blockIdx.x << 7;

    auto load_stage = [&](int kc, int s) {
        const int kel = kc * BK;
        const uint32_t stb = sb + s * STG;
#pragma unroll
        for (int j = 0; j < 6; j++) {
            const int idx = t + (j << 8);
            const int mat = idx >> 9;
            const int rr  = (idx >> 2) & 127;
            const int cc  = idx & 3;
            const __half* src;
            if (mat < 2)
                src = (mat ? Alo : Ahi) + (size_t)(m0 + rr) * Dn + kel + (cc << 3);
            else
                src = Bh + (size_t)(n0 + rr) * Dn + kel + (cc << 3);
            cpa16(stb + mat * MATB + rr * ROWB + (cc << 4), src);
        }
        cpa_commit();
    };

    float acc[4][4][4];
    uint32_t acc16[4][4][2];
#pragma unroll
    for (int i = 0; i < 4; i++)
#pragma unroll
        for (int j = 0; j < 4; j++) {
#pragma unroll
            for (int q = 0; q < 4; q++) acc[i][j][q] = 0.f;
            acc16[i][j][0] = 0u; acc16[i][j][1] = 0u;
        }

    load_stage(0, 0);
    load_stage(1, 1);

    for (int kc = 0; kc < NCHUNK; ++kc) {
        if (kc + 2 < NCHUNK) { load_stage(kc + 2, (kc + 2) % 3); cpa_wait<2>(); }
        else if (kc + 1 < NCHUNK) cpa_wait<1>();
        else cpa_wait<0>();
        __syncthreads();
        const uint32_t stb = sb + (kc % 3) * STG;

#pragma unroll
        for (int k16 = 0; k16 < 2; k16++) {
            uint32_t ah[16], al[16];
            const uint32_t abase = stb + (wm + (lane & 15)) * ROWB +
                                   (k16 << 5) + ((lane >> 4) << 4);
#pragma unroll
            for (int mt = 0; mt < 4; mt++) {
                ldm4(ah + 4 * mt, abase + mt * 16 * ROWB);
                ldm4(al + 4 * mt, abase + mt * 16 * ROWB + MATB);
            }
#pragma unroll
            for (int ng = 0; ng < 2; ng++) {
                uint32_t bh4[4];
                const uint32_t bbase = stb + 2 * MATB +
                                       (wn + ng * 16 + (lane & 15)) * ROWB +
                                       (k16 << 5) + ((lane >> 4) << 4);
                ldm4(bh4, bbase);
                // main products: fp32 acc
#pragma unroll
                for (int mt = 0; mt < 4; mt++) {
#pragma unroll
                    for (int nn = 0; nn < 2; nn++) {
                        mma16816(acc[mt][ng * 2 + nn], ah + 4 * mt,
                                 nn ? bh4[1] : bh4[0], nn ? bh4[3] : bh4[2]);
                    }
                }
                // correction products: fp16 acc
#pragma unroll
                for (int mt = 0; mt < 4; mt++) {
#pragma unroll
                    for (int nn = 0; nn < 2; nn++) {
                        mma16816_h(acc16[mt][ng * 2 + nn], al + 4 * mt,
                                   nn ? bh4[1] : bh4[0], nn ? bh4[3] : bh4[2]);
                    }
                }
            }
        }
        __syncthreads();
    }

    const int rbase = m0 + wm + (lane >> 2);
    const int cbase = (lane & 3) << 1;
#pragma unroll
    for (int mt = 0; mt < 4; mt++) {
#pragma unroll
        for (int nf = 0; nf < 4; nf++) {
            fold_h(acc[mt][nf], acc16[mt][nf]);
            const int n = n0 + wn + ((nf >> 1) << 4) + ((nf & 1) << 3) + cbase;
            const float* c = acc[mt][nf];
#pragma unroll
            for (int half = 0; half < 2; half++) {
                const int r = rbase + mt * 16 + half * 8;
                float v0 = c[2 * half], v1 = c[2 * half + 1];
                if (MODE == 0) {
                    *(float2*)&Cout[(size_t)r * Dn + n] =
                        make_float2(v0 + bias[n], v1 + bias[n + 1]);
                } else {
                    const int mat = n >> 10;
                    const int nn  = n & 1023;
                    const int h   = nn >> 6;
                    const int e   = nn & 63;
                    const int b   = r >> 12;
                    const int s   = r & (Sn - 1);
                    if (mat == 0) { v0 *= 0.125f; v1 *= 0.125f; }
                    __half* hi_arr = (mat == 0) ? g_qhi : (mat == 1) ? g_khi : g_vhi;
                    __half* lo_arr = (mat == 0) ? g_qlo : (mat == 1) ? g_klo : g_vlo;
                    __half h0, h1, l0, l1;
                    hsplit(v0, h0, l0);
                    hsplit(v1, h1, l1);
                    const size_t off = ((size_t)(b * Hn + h) * Sn + s) * DHn + e;
                    *(__half2*)&hi_arr[off] = __halves2half2(h0, h1);
                    *(__half2*)&lo_arr[off] = __halves2half2(l0, l1);
                }
            }
        }
    }
}

// ---------------------------------------------------------------------------
// Flash attention: main products fp32-acc, corrections fp16-acc folded per
// tile (S before mask; PV after the tile's MMAs, post-rescale -> correct).
// ---------------------------------------------------------------------------
__device__ __forceinline__ int kb_of(int jb, int kt, int& mtype, int& kc0) {
    mtype = 0; kc0 = 0;
    if (jb <= NGn) return kt * 64;
    if (jb == NBn - 1) return (kt < 2) ? kt * 64 : (Sn - 192 + (kt - 2) * 64);
    if (kt < 2) return kt * 64;
    mtype = 1; kc0 = (kt - 2) * 64;
    return (jb - 1) * 64 + (kt - 2) * 64;
}

__global__ void __launch_bounds__(128, 2)
attn_k(const float* __restrict__ to_mask,
       const float* __restrict__ band_mask,
       const float* __restrict__ from_mask)
{
    extern __shared__ char smem[];
    const uint32_t sb = smem_u32(smem);
    const int t = threadIdx.x, lane = t & 31, wid = t >> 5;
    const int idx = blockIdx.x;
    const int jb  = idx >> 5;
    const int bh  = idx & 31;
    const int b   = bh >> 4, h = bh & 15;
    const int wm  = wid << 4;

    const size_t hoff = (size_t)(b * Hn + h) * Sn * DHn;
    const __half* qhg = g_qhi + hoff + (size_t)jb * 64 * DHn;
    const __half* qlg = g_qlo + hoff + (size_t)jb * 64 * DHn;
    const __half* khg = g_khi + hoff;
    const __half* klg = g_klo + hoff;
    const __half* vhg = g_vhi + hoff;
    const __half* vlg = g_vlo + hoff;

#pragma unroll
    for (int j = 0; j < 8; j++) {
        const int i2 = t + (j << 7);
        const int mat = i2 >> 9;
        const int rr  = (i2 >> 3) & 63;
        const int cc  = i2 & 7;
        cpa16(sb + mat * AMAT + rr * AROW + (cc << 4),
              (mat ? qlg : qhg) + rr * DHn + (cc << 3));
    }
    cpa_commit();

    auto loadKV = [&](int kb, int s) {
        const uint32_t base = sb + AQ_BYTES + s * ASTAGE;
#pragma unroll
        for (int j = 0; j < 16; j++) {
            const int i2 = t + (j << 7);
            const int mat = i2 >> 9;
            const int rr  = (i2 >> 3) & 63;
            const int cc  = i2 & 7;
            const __half* src =
                (mat == 0 ? khg : mat == 1 ? klg : mat == 2 ? vhg : vlg) +
                (size_t)(kb + rr) * DHn + (cc << 3);
            cpa16(base + mat * AMAT + rr * AROW + (cc << 4), src);
        }
        cpa_commit();
    };

    const int ntiles = (jb < NGn) ? 64 : 5;
    int mty, kc0_;
    loadKV(kb_of(jb, 0, mty, kc0_), 0);

    uint32_t qh[4][4], ql[4][4];
    float pv[8][4];
    uint32_t pvc[8][2], sfc[8][2];
#pragma unroll
    for (int f = 0; f < 8; f++) {
#pragma unroll
        for (int q = 0; q < 4; q++) pv[f][q] = 0.f;
        pvc[f][0] = 0u; pvc[f][1] = 0u;
        sfc[f][0] = 0u; sfc[f][1] = 0u;
    }
    float mrow0 = -1e30f, mrow1 = -1e30f, lrow0 = 0.f, lrow1 = 0.f;

    for (int kt = 0; kt < ntiles; ++kt) {
        if (kt + 1 < ntiles) {
            int mt2, kc2;
            loadKV(kb_of(jb, kt + 1, mt2, kc2), (kt + 1) & 1);
            cpa_wait<1>();
        } else {
            cpa_wait<0>();
        }
        __syncthreads();

        if (kt == 0) {
            const uint32_t qbase = sb + (wm + (lane & 15)) * AROW + ((lane >> 4) << 4);
#pragma unroll
            for (int ks = 0; ks < 4; ks++) {
                ldm4(qh[ks], qbase + (ks << 5));
                ldm4(ql[ks], qbase + (ks << 5) + AMAT);
            }
        }

        int mtype, kcol0;
        const int kb = kb_of(jb, kt, mtype, kcol0);
        const uint32_t SK = sb + AQ_BYTES + (kt & 1) * ASTAGE;
        const uint32_t SV = SK + 2 * AMAT;

        float sf[8][4];
#pragma unroll
        for (int f = 0; f < 8; f++)
#pragma unroll
            for (int q = 0; q < 4; q++) sf[f][q] = 0.f;
#pragma unroll
        for (int ks = 0; ks < 4; ks++) {
#pragma unroll
            for (int kg = 0; kg < 4; kg++) {
                uint32_t kh4[4], kl4[4];
                const uint32_t ka = SK + (kg * 16 + (lane & 15)) * AROW +
                                    (ks << 5) + ((lane >> 4) << 4);
                ldm4(kh4, ka);
                ldm4(kl4, ka + AMAT);
                // main: fp32 acc
#pragma unroll
                for (int nn = 0; nn < 2; nn++)
                    mma16816(sf[kg * 2 + nn], qh[ks],
                             nn ? kh4[1] : kh4[0], nn ? kh4[3] : kh4[2]);
                // corrections: fp16 acc
#pragma unroll
                for (int nn = 0; nn < 2; nn++)
                    mma16816_h(sfc[kg * 2 + nn], ql[ks],
                               nn ? kh4[1] : kh4[0], nn ? kh4[3] : kh4[2]);
#pragma unroll
                for (int nn = 0; nn < 2; nn++)
                    mma16816_h(sfc[kg * 2 + nn], qh[ks],
                               nn ? kl4[1] : kl4[0], nn ? kl4[3] : kl4[2]);
            }
        }
        // fold S corrections (also zeroes sfc for next tile)
#pragma unroll
        for (int f = 0; f < 8; f++) fold_h(sf[f], sfc[f]);

        const int colb = (lane & 3) << 1;
        if (mtype == 0) {
#pragma unroll
            for (int f = 0; f < 8; f++) {
                const int key = kb + f * 8 + colb;
                const float p0 = (1.0f - to_mask[b * Sn + key]) * -10000.0f;
                const float p1 = (1.0f - to_mask[b * Sn + key + 1]) * -10000.0f;
                sf[f][0] += p0;
                sf[f][1] += p1;
                sf[f][2] += p0;
                sf[f][3] += p1;
            }
        } else {
            const int m_idx = jb - (NGn + 1);
            const int qi0 = wm + (lane >> 2);
            const float* bm0 = band_mask +
                ((size_t)(b * NMIDn + m_idx) * 64 + qi0) * 192 + kcol0 + colb;
#pragma unroll
            for (int f = 0; f < 8; f++) {
                sf[f][0] += (1.0f - bm0[f * 8]) * -10000.0f;
                sf[f][1] += (1.0f - bm0[f * 8 + 1]) * -10000.0f;
                sf[f][2] += (1.0f - bm0[8 * 192 + f * 8]) * -10000.0f;
                sf[f][3] += (1.0f - bm0[8 * 192 + f * 8 + 1]) * -10000.0f;
            }
        }

        float mx0 = -1e30f, mx1 = -1e30f;
#pragma unroll
        for (int f = 0; f < 8; f++) {
            mx0 = fmaxf(mx0, fmaxf(sf[f][0], sf[f][1]));
            mx1 = fmaxf(mx1, fmaxf(sf[f][2], sf[f][3]));
        }
        mx0 = fmaxf(mx0, __shfl_xor_sync(0xffffffffu, mx0, 1));
        mx0 = fmaxf(mx0, __shfl_xor_sync(0xffffffffu, mx0, 2));
        mx1 = fmaxf(mx1, __shfl_xor_sync(0xffffffffu, mx1, 1));
        mx1 = fmaxf(mx1, __shfl_xor_sync(0xffffffffu, mx1, 2));

        const float nm0 = fmaxf(mrow0, mx0), nm1 = fmaxf(mrow1, mx1);
        const float corr0 = __expf(mrow0 - nm0), corr1 = __expf(mrow1 - nm1);
        mrow0 = nm0; mrow1 = nm1;
        lrow0 *= corr0; lrow1 *= corr1;
#pragma unroll
        for (int f = 0; f < 8; f++) {
            pv[f][0] *= corr0; pv[f][1] *= corr0;
            pv[f][2] *= corr1; pv[f][3] *= corr1;
        }

        float rs0 = 0.f, rs1 = 0.f;
#pragma unroll
        for (int f = 0; f < 8; f++) {
            sf[f][0] = __expf(sf[f][0] - nm0);
            sf[f][1] = __expf(sf[f][1] - nm0);
            sf[f][2] = __expf(sf[f][2] - nm1);
            sf[f][3] = __expf(sf[f][3] - nm1);
            rs0 += sf[f][0] + sf[f][1];
            rs1 += sf[f][2] + sf[f][3];
        }
        rs0 += __shfl_xor_sync(0xffffffffu, rs0, 1);
        rs0 += __shfl_xor_sync(0xffffffffu, rs0, 2);
        rs1 += __shfl_xor_sync(0xffffffffu, rs1, 1);
        rs1 += __shfl_xor_sync(0xffffffffu, rs1, 2);
        lrow0 += rs0; lrow1 += rs1;

#pragma unroll
        for (int kg = 0; kg < 4; kg++) {
            uint32_t pa[4], pl[4];
            hsplit_pack(sf[2 * kg][0],     sf[2 * kg][1],     pa[0], pl[0]);
            hsplit_pack(sf[2 * kg][2],     sf[2 * kg][3],     pa[1], pl[1]);
            hsplit_pack(sf[2 * kg + 1][0], sf[2 * kg + 1][1], pa[2], pl[2]);
            hsplit_pack(sf[2 * kg + 1][2], sf[2 * kg + 1][3], pa[3], pl[3]);
#pragma unroll
            for (int eg = 0; eg < 4; eg++) {
                uint32_t vh4[4], vl4[4];
                const uint32_t va = SV +
                    (kg * 16 + (((lane >> 3) & 1) << 3) + (lane & 7)) * AROW +
                    (eg << 5) + ((lane >> 4) << 4);
                ldm4t(vh4, va);
                ldm4t(vl4, va + AMAT);
                // main: fp32 acc
#pragma unroll
                for (int nn = 0; nn < 2; nn++)
                    mma16816(pv[eg * 2 + nn], pa, vh4[nn * 2], vh4[nn * 2 + 1]);
                // corrections: fp16 acc
#pragma unroll
                for (int nn = 0; nn < 2; nn++)
                    mma16816_h(pvc[eg * 2 + nn], pl, vh4[nn * 2], vh4[nn * 2 + 1]);
#pragma unroll
                for (int nn = 0; nn < 2; nn++)
                    mma16816_h(pvc[eg * 2 + nn], pa, vl4[nn * 2], vl4[nn * 2 + 1]);
            }
        }
        // fold PV corrections for this tile (post-rescale -> no scaling error)
#pragma unroll
        for (int f = 0; f < 8; f++) fold_h(pv[f], pvc[f]);
        __syncthreads();
    }

    const int srow0 = jb * 64 + wm + (lane >> 2);
    const int srow1 = srow0 + 8;
    const float sc0 = from_mask[b * Sn + srow0] / lrow0;
    const float sc1 = from_mask[b * Sn + srow1] / lrow1;
#pragma unroll
    for (int f = 0; f < 8; f++) {
        const int e = f * 8 + ((lane & 3) << 1);
        const size_t o0 = (size_t)(b * Sn + srow0) * Dn + h * 64 + e;
        const size_t o1 = (size_t)(b * Sn + srow1) * Dn + h * 64 + e;
        uint32_t hp, lp;
        hsplit_pack(pv[f][0] * sc0, pv[f][1] * sc0, hp, lp);
        *(uint32_t*)&g_Chi[o0] = hp;
        *(uint32_t*)&g_Clo[o0] = lp;
        hsplit_pack(pv[f][2] * sc1, pv[f][3] * sc1, hp, lp);
        *(uint32_t*)&g_Chi[o1] = hp;
        *(uint32_t*)&g_Clo[o1] = lp;
    }
}

// ---------------------------------------------------------------------------
extern "C" void kernel_launch(void* const* d_in, const int* in_sizes, int n_in,
                              void* d_out, int out_size)
{
    const float* tokens    = (const float*)d_in[0];
    const float* band_mask = (const float*)d_in[1];
    const float* from_mask = (const float*)d_in[2];
    const float* to_mask   = (const float*)d_in[3];
    const float* Wq        = (const float*)d_in[4];
    const float* Wk        = (const float*)d_in[5];
    const float* Wv        = (const float*)d_in[6];
    const float* Wu        = (const float*)d_in[7];
    const float* bu        = (const float*)d_in[8];
    (void)in_sizes; (void)n_in; (void)out_size;

    __half *ahi, *alo, *bqh, *buh, *chi, *clo;
    cudaGetSymbolAddress((void**)&ahi, g_Ahi);
    cudaGetSymbolAddress((void**)&alo, g_Alo);
    cudaGetSymbolAddress((void**)&bqh, g_Bqkv_h);
    cudaGetSymbolAddress((void**)&buh, g_Bu_h);
    cudaGetSymbolAddress((void**)&chi, g_Chi);
    cudaGetSymbolAddress((void**)&clo, g_Clo);

    cudaFuncSetAttribute(attn_k, cudaFuncAttributeMaxDynamicSharedMemorySize, ATTN_SMEM);
    cudaFuncSetAttribute(hmma_gemm<0>, cudaFuncAttributeMaxDynamicSharedMemorySize, GEMM_SMEM);
    cudaFuncSetAttribute(hmma_gemm<1>, cudaFuncAttributeMaxDynamicSharedMemorySize, GEMM_SMEM);

    split_k<<<2048, 256>>>(tokens, ahi, alo, Mrows * Dn / 4);
    packW_all<<<dim3(32, 32, 4), dim3(32, 8)>>>(Wq, Wk, Wv, Wu);

    hmma_gemm<1><<<dim3(24, 64), 256, GEMM_SMEM>>>(ahi, alo, bqh, nullptr, nullptr);
    attn_k<<<Bn * Hn * NBn, 128, ATTN_SMEM>>>(to_mask, band_mask, from_mask);
    hmma_gemm<0><<<dim3(8, 64), 256, GEMM_SMEM>>>(chi, clo, buh, bu, (float*)d_out);
}

// round 11
// speedup vs baseline: 1.5712x; 1.5712x over previous
#include <cuda_runtime.h>
#include <cuda_fp16.h>
#include <cstdint>

// ---------------------------------------------------------------------------
// BigBird transformer block on sm_103 (non-'a' target: no tcgen05/TMEM).
// R11: mma.sync.16816 is a hard 16cyc/SMSP issue wall (R9/R10 falsified
// latency + fp16-acc theories) -> reduce MMA COUNT. GEMMs drop the A-side
// correction product: single fp16 product Ah.Bh (error budget measured:
// R8's symmetric B-side drop cost 3.2e-4; expect ~4.5e-4 total).
// Attention keeps 3 products. GEMM stages shrink to Ah+Bh (61KB, 2 CTA/SM).
// ---------------------------------------------------------------------------

namespace {
constexpr int Bn    = 2;
constexpr int Sn    = 4096;
constexpr int Dn    = 1024;
constexpr int Hn    = 16;
constexpr int DHn   = 64;
constexpr int NBn   = 64;
constexpr int NGn   = 2;
constexpr int NMIDn = 60;
constexpr int Mrows = Bn * Sn;              // 8192

// GEMM tiling
constexpr int BK      = 32;
constexpr int NCHUNK  = Dn / BK;             // 32
constexpr int ROWB    = 80;
constexpr int MATB    = 128 * ROWB;          // 10240
constexpr int STG     = 2 * MATB;            // Ah, Bh = 20480 B / stage
constexpr int GEMM_SMEM = 3 * STG;           // 61440 B -> 2 CTAs/SM

// attention smem
constexpr int AROW    = 144;
constexpr int AMAT    = 64 * AROW;           // 9216 B
constexpr int ASTAGE  = 4 * AMAT;            // 36864 B
constexpr int AQ_BYTES = 2 * AMAT;
constexpr int ATTN_SMEM = AQ_BYTES + 2 * ASTAGE;  // 92160 B
}

// ---- scratch (device globals) ----------------------------------------------
__device__ __half g_qhi[Bn * Hn * Sn * DHn], g_qlo[Bn * Hn * Sn * DHn];
__device__ __half g_khi[Bn * Hn * Sn * DHn], g_klo[Bn * Hn * Sn * DHn];
__device__ __half g_vhi[Bn * Hn * Sn * DHn], g_vlo[Bn * Hn * Sn * DHn];
__device__ __half g_Ahi[Mrows * Dn];
__device__ __half g_Bqkv_h[3 * Dn * Dn];
__device__ __half g_Bu_h[Dn * Dn];
__device__ __half g_Chi[Mrows * Dn];

// ---------------------------------------------------------------------------
// PTX helpers
// ---------------------------------------------------------------------------
__device__ __forceinline__ uint32_t smem_u32(const void* p) {
    uint32_t a;
    asm("{ .reg .u64 t; cvta.to.shared.u64 t, %1; cvt.u32.u64 %0, t; }" : "=r"(a) : "l"(p));
    return a;
}
__device__ __forceinline__ void cpa16(uint32_t dst, const void* src) {
    asm volatile("cp.async.cg.shared.global [%0], [%1], 16;" :: "r"(dst), "l"(src));
}
__device__ __forceinline__ void cpa_commit() {
    asm volatile("cp.async.commit_group;" ::: "memory");
}
template <int N>
__device__ __forceinline__ void cpa_wait() {
    asm volatile("cp.async.wait_group %0;" :: "n"(N) : "memory");
}
__device__ __forceinline__ void ldm4(uint32_t* r, uint32_t addr) {
    asm volatile("ldmatrix.sync.aligned.m8n8.x4.shared.b16 {%0,%1,%2,%3}, [%4];"
                 : "=r"(r[0]), "=r"(r[1]), "=r"(r[2]), "=r"(r[3]) : "r"(addr));
}
__device__ __forceinline__ void ldm4t(uint32_t* r, uint32_t addr) {
    asm volatile("ldmatrix.sync.aligned.m8n8.x4.trans.shared.b16 {%0,%1,%2,%3}, [%4];"
                 : "=r"(r[0]), "=r"(r[1]), "=r"(r[2]), "=r"(r[3]) : "r"(addr));
}
__device__ __forceinline__ void mma16816(float* c, const uint32_t* a,
                                         uint32_t b0, uint32_t b1) {
    asm volatile(
        "mma.sync.aligned.m16n8k16.row.col.f32.f16.f16.f32 "
        "{%0,%1,%2,%3}, {%4,%5,%6,%7}, {%8,%9}, {%0,%1,%2,%3};"
        : "+f"(c[0]), "+f"(c[1]), "+f"(c[2]), "+f"(c[3])
        : "r"(a[0]), "r"(a[1]), "r"(a[2]), "r"(a[3]), "r"(b0), "r"(b1));
}
__device__ __forceinline__ void hsplit(float v, __half& h, __half& l) {
    h = __float2half_rn(v);
    l = __float2half_rn(v - __half2float(h));
}
__device__ __forceinline__ void hsplit_pack(float v0, float v1,
                                            uint32_t& hp, uint32_t& lp) {
    __half2 h = __floats2half2_rn(v0, v1);
    __half2 l = __floats2half2_rn(v0 - __low2float(h), v1 - __high2float(h));
    hp = *reinterpret_cast<uint32_t*>(&h);
    lp = *reinterpret_cast<uint32_t*>(&l);
}

// ---------------------------------------------------------------------------
// prep kernels
// ---------------------------------------------------------------------------
__global__ void split_k(const float* __restrict__ X,
                        __half* __restrict__ Hi, int n4)
{
    for (int i = blockIdx.x * blockDim.x + threadIdx.x; i < n4;
         i += gridDim.x * blockDim.x) {
        float4 v = ((const float4*)X)[i];
        *(__half2*)(Hi + 4 * i)     = __floats2half2_rn(v.x, v.y);
        *(__half2*)(Hi + 4 * i + 2) = __floats2half2_rn(v.z, v.w);
    }
}

__global__ void packW_all(const float* __restrict__ Wq, const float* __restrict__ Wk,
                          const float* __restrict__ Wv, const float* __restrict__ Wu)
{
    __shared__ float tile[32][33];
    const int z = blockIdx.z;
    const float* W = (z == 0) ? Wq : (z == 1) ? Wk : (z == 2) ? Wv : Wu;
    __half* Bh = (z < 3) ? g_Bqkv_h : g_Bu_h;
    const int nOff = (z < 3) ? z * 1024 : 0;

    const int tx = threadIdx.x, ty = threadIdx.y;
    const int n0 = blockIdx.x * 32, k0 = blockIdx.y * 32;
#pragma unroll
    for (int j = 0; j < 4; j++)
        tile[ty + j * 8][tx] = W[(size_t)(k0 + ty + j * 8) * Dn + n0 + tx];
    __syncthreads();
    const int kk = k0 + tx;
#pragma unroll
    for (int j = 0; j < 4; j++) {
        const int n = n0 + ty + j * 8;
        Bh[(size_t)(nOff + n) * Dn + kk] = __float2half_rn(tile[tx][ty + j * 8]);
    }
}

// ---------------------------------------------------------------------------
// fp16 HMMA GEMM, single product Ah.Bh, 3-stage pipeline, 2 CTAs/SM.
// MODE 1: scatter q/k/v as fp16 hi/lo head layout (q pre-scaled by 1/8).
// MODE 0: d_out = D + bias.
// ---------------------------------------------------------------------------
template <int MODE>
__global__ void __launch_bounds__(256, 2)
hmma_gemm(const __half* __restrict__ Ahi, const __half* __restrict__ Bh,
          const float* __restrict__ bias, float* __restrict__ Cout)
{
    extern __shared__ char smem[];
    const uint32_t sb = smem_u32(smem);
    const int t    = threadIdx.x;
    const int lane = t & 31;
    const int wid  = t >> 5;
    const int wm   = (wid & 1) << 6;
    const int wn   = (wid >> 1) << 5;
    const int m0   = blockIdx.y << 7;
    const int n0   = blockIdx.x << 7;

    auto load_stage = [&](int kc, int s) {
        const int kel = kc * BK;
        const uint32_t stb = sb + s * STG;
        // 2 mats x 128 rows x 4 chunks = 1024
#pragma unroll
        for (int j = 0; j < 4; j++) {
            const int idx = t + (j << 8);
            const int mat = idx >> 9;
            const int rr  = (idx >> 2) & 127;
            const int cc  = idx & 3;
            const __half* src = mat
                ? Bh  + (size_t)(n0 + rr) * Dn + kel + (cc << 3)
                : Ahi + (size_t)(m0 + rr) * Dn + kel + (cc << 3);
            cpa16(stb + mat * MATB + rr * ROWB + (cc << 4), src);
        }
        cpa_commit();
    };

    float acc[4][4][4];
#pragma unroll
    for (int i = 0; i < 4; i++)
#pragma unroll
        for (int j = 0; j < 4; j++)
#pragma unroll
            for (int q = 0; q < 4; q++) acc[i][j][q] = 0.f;

    load_stage(0, 0);
    load_stage(1, 1);

    for (int kc = 0; kc < NCHUNK; ++kc) {
        if (kc + 2 < NCHUNK) { load_stage(kc + 2, (kc + 2) % 3); cpa_wait<2>(); }
        else if (kc + 1 < NCHUNK) cpa_wait<1>();
        else cpa_wait<0>();
        __syncthreads();
        const uint32_t stb = sb + (kc % 3) * STG;

#pragma unroll
        for (int k16 = 0; k16 < 2; k16++) {
            uint32_t ah[16];
            const uint32_t abase = stb + (wm + (lane & 15)) * ROWB +
                                   (k16 << 5) + ((lane >> 4) << 4);
#pragma unroll
            for (int mt = 0; mt < 4; mt++)
                ldm4(ah + 4 * mt, abase + mt * 16 * ROWB);
#pragma unroll
            for (int ng = 0; ng < 2; ng++) {
                uint32_t bh4[4];
                const uint32_t bbase = stb + MATB +
                                       (wn + ng * 16 + (lane & 15)) * ROWB +
                                       (k16 << 5) + ((lane >> 4) << 4);
                ldm4(bh4, bbase);
#pragma unroll
                for (int mt = 0; mt < 4; mt++) {
#pragma unroll
                    for (int nn = 0; nn < 2; nn++) {
                        mma16816(acc[mt][ng * 2 + nn], ah + 4 * mt,
                                 nn ? bh4[1] : bh4[0], nn ? bh4[3] : bh4[2]);
                    }
                }
            }
        }
        __syncthreads();
    }

    const int rbase = m0 + wm + (lane >> 2);
    const int cbase = (lane & 3) << 1;
#pragma unroll
    for (int mt = 0; mt < 4; mt++) {
#pragma unroll
        for (int nf = 0; nf < 4; nf++) {
            const int n = n0 + wn + ((nf >> 1) << 4) + ((nf & 1) << 3) + cbase;
            const float* c = acc[mt][nf];
#pragma unroll
            for (int half = 0; half < 2; half++) {
                const int r = rbase + mt * 16 + half * 8;
                float v0 = c[2 * half], v1 = c[2 * half + 1];
                if (MODE == 0) {
                    *(float2*)&Cout[(size_t)r * Dn + n] =
                        make_float2(v0 + bias[n], v1 + bias[n + 1]);
                } else {
                    const int mat = n >> 10;
                    const int nn  = n & 1023;
                    const int h   = nn >> 6;
                    const int e   = nn & 63;
                    const int b   = r >> 12;
                    const int s   = r & (Sn - 1);
                    if (mat == 0) { v0 *= 0.125f; v1 *= 0.125f; }
                    __half* hi_arr = (mat == 0) ? g_qhi : (mat == 1) ? g_khi : g_vhi;
                    __half* lo_arr = (mat == 0) ? g_qlo : (mat == 1) ? g_klo : g_vlo;
                    __half h0, h1, l0, l1;
                    hsplit(v0, h0, l0);
                    hsplit(v1, h1, l1);
                    const size_t off = ((size_t)(b * Hn + h) * Sn + s) * DHn + e;
                    *(__half2*)&hi_arr[off] = __halves2half2(h0, h1);
                    *(__half2*)&lo_arr[off] = __halves2half2(l0, l1);
                }
            }
        }
    }
}

// ---------------------------------------------------------------------------
// Flash attention, warp-MMA, fp16 hi/lo 3-product (R9, unchanged math).
// Epilogue writes Chi only (out GEMM is single-product).
// ---------------------------------------------------------------------------
__device__ __forceinline__ int kb_of(int jb, int kt, int& mtype, int& kc0) {
    mtype = 0; kc0 = 0;
    if (jb <= NGn) return kt * 64;
    if (jb == NBn - 1) return (kt < 2) ? kt * 64 : (Sn - 192 + (kt - 2) * 64);
    if (kt < 2) return kt * 64;
    mtype = 1; kc0 = (kt - 2) * 64;
    return (jb - 1) * 64 + (kt - 2) * 64;
}

__global__ void __launch_bounds__(128, 2)
attn_k(const float* __restrict__ to_mask,
       const float* __restrict__ band_mask,
       const float* __restrict__ from_mask)
{
    extern __shared__ char smem[];
    const uint32_t sb = smem_u32(smem);
    const int t = threadIdx.x, lane = t & 31, wid = t >> 5;
    const int idx = blockIdx.x;
    const int jb  = idx >> 5;
    const int bh  = idx & 31;
    const int b   = bh >> 4, h = bh & 15;
    const int wm  = wid << 4;

    const size_t hoff = (size_t)(b * Hn + h) * Sn * DHn;
    const __half* qhg = g_qhi + hoff + (size_t)jb * 64 * DHn;
    const __half* qlg = g_qlo + hoff + (size_t)jb * 64 * DHn;
    const __half* khg = g_khi + hoff;
    const __half* klg = g_klo + hoff;
    const __half* vhg = g_vhi + hoff;
    const __half* vlg = g_vlo + hoff;

#pragma unroll
    for (int j = 0; j < 8; j++) {
        const int i2 = t + (j << 7);
        const int mat = i2 >> 9;
        const int rr  = (i2 >> 3) & 63;
        const int cc  = i2 & 7;
        cpa16(sb + mat * AMAT + rr * AROW + (cc << 4),
              (mat ? qlg : qhg) + rr * DHn + (cc << 3));
    }
    cpa_commit();

    auto loadKV = [&](int kb, int s) {
        const uint32_t base = sb + AQ_BYTES + s * ASTAGE;
#pragma unroll
        for (int j = 0; j < 16; j++) {
            const int i2 = t + (j << 7);
            const int mat = i2 >> 9;
            const int rr  = (i2 >> 3) & 63;
            const int cc  = i2 & 7;
            const __half* src =
                (mat == 0 ? khg : mat == 1 ? klg : mat == 2 ? vhg : vlg) +
                (size_t)(kb + rr) * DHn + (cc << 3);
            cpa16(base + mat * AMAT + rr * AROW + (cc << 4), src);
        }
        cpa_commit();
    };

    const int ntiles = (jb < NGn) ? 64 : 5;
    int mty, kc0_;
    loadKV(kb_of(jb, 0, mty, kc0_), 0);

    uint32_t qh[4][4], ql[4][4];
    float pv[8][4];
#pragma unroll
    for (int f = 0; f < 8; f++)
#pragma unroll
        for (int q = 0; q < 4; q++) pv[f][q] = 0.f;
    float mrow0 = -1e30f, mrow1 = -1e30f, lrow0 = 0.f, lrow1 = 0.f;

    for (int kt = 0; kt < ntiles; ++kt) {
        if (kt + 1 < ntiles) {
            int mt2, kc2;
            loadKV(kb_of(jb, kt + 1, mt2, kc2), (kt + 1) & 1);
            cpa_wait<1>();
        } else {
            cpa_wait<0>();
        }
        __syncthreads();

        if (kt == 0) {
            const uint32_t qbase = sb + (wm + (lane & 15)) * AROW + ((lane >> 4) << 4);
#pragma unroll
            for (int ks = 0; ks < 4; ks++) {
                ldm4(qh[ks], qbase + (ks << 5));
                ldm4(ql[ks], qbase + (ks << 5) + AMAT);
            }
        }

        int mtype, kcol0;
        const int kb = kb_of(jb, kt, mtype, kcol0);
        const uint32_t SK = sb + AQ_BYTES + (kt & 1) * ASTAGE;
        const uint32_t SV = SK + 2 * AMAT;

        float sf[8][4];
#pragma unroll
        for (int f = 0; f < 8; f++)
#pragma unroll
            for (int q = 0; q < 4; q++) sf[f][q] = 0.f;
#pragma unroll
        for (int ks = 0; ks < 4; ks++) {
#pragma unroll
            for (int kg = 0; kg < 4; kg++) {
                uint32_t kh4[4], kl4[4];
                const uint32_t ka = SK + (kg * 16 + (lane & 15)) * AROW +
                                    (ks << 5) + ((lane >> 4) << 4);
                ldm4(kh4, ka);
                ldm4(kl4, ka + AMAT);
#pragma unroll
                for (int nn = 0; nn < 2; nn++)
                    mma16816(sf[kg * 2 + nn], qh[ks],
                             nn ? kh4[1] : kh4[0], nn ? kh4[3] : kh4[2]);
#pragma unroll
                for (int nn = 0; nn < 2; nn++)
                    mma16816(sf[kg * 2 + nn], ql[ks],
                             nn ? kh4[1] : kh4[0], nn ? kh4[3] : kh4[2]);
#pragma unroll
                for (int nn = 0; nn < 2; nn++)
                    mma16816(sf[kg * 2 + nn], qh[ks],
                             nn ? kl4[1] : kl4[0], nn ? kl4[3] : kl4[2]);
            }
        }

        const int colb = (lane & 3) << 1;
        if (mtype == 0) {
#pragma unroll
            for (int f = 0; f < 8; f++) {
                const int key = kb + f * 8 + colb;
                const float p0 = (1.0f - to_mask[b * Sn + key]) * -10000.0f;
                const float p1 = (1.0f - to_mask[b * Sn + key + 1]) * -10000.0f;
                sf[f][0] += p0;
                sf[f][1] += p1;
                sf[f][2] += p0;
                sf[f][3] += p1;
            }
        } else {
            const int m_idx = jb - (NGn + 1);
            const int qi0 = wm + (lane >> 2);
            const float* bm0 = band_mask +
                ((size_t)(b * NMIDn + m_idx) * 64 + qi0) * 192 + kcol0 + colb;
#pragma unroll
            for (int f = 0; f < 8; f++) {
                sf[f][0] += (1.0f - bm0[f * 8]) * -10000.0f;
                sf[f][1] += (1.0f - bm0[f * 8 + 1]) * -10000.0f;
                sf[f][2] += (1.0f - bm0[8 * 192 + f * 8]) * -10000.0f;
                sf[f][3] += (1.0f - bm0[8 * 192 + f * 8 + 1]) * -10000.0f;
            }
        }

        float mx0 = -1e30f, mx1 = -1e30f;
#pragma unroll
        for (int f = 0; f < 8; f++) {
            mx0 = fmaxf(mx0, fmaxf(sf[f][0], sf[f][1]));
            mx1 = fmaxf(mx1, fmaxf(sf[f][2], sf[f][3]));
        }
        mx0 = fmaxf(mx0, __shfl_xor_sync(0xffffffffu, mx0, 1));
        mx0 = fmaxf(mx0, __shfl_xor_sync(0xffffffffu, mx0, 2));
        mx1 = fmaxf(mx1, __shfl_xor_sync(0xffffffffu, mx1, 1));
        mx1 = fmaxf(mx1, __shfl_xor_sync(0xffffffffu, mx1, 2));

        const float nm0 = fmaxf(mrow0, mx0), nm1 = fmaxf(mrow1, mx1);
        const float corr0 = __expf(mrow0 - nm0), corr1 = __expf(mrow1 - nm1);
        mrow0 = nm0; mrow1 = nm1;
        lrow0 *= corr0; lrow1 *= corr1;
#pragma unroll
        for (int f = 0; f < 8; f++) {
            pv[f][0] *= corr0; pv[f][1] *= corr0;
            pv[f][2] *= corr1; pv[f][3] *= corr1;
        }

        float rs0 = 0.f, rs1 = 0.f;
#pragma unroll
        for (int f = 0; f < 8; f++) {
            sf[f][0] = __expf(sf[f][0] - nm0);
            sf[f][1] = __expf(sf[f][1] - nm0);
            sf[f][2] = __expf(sf[f][2] - nm1);
            sf[f][3] = __expf(sf[f][3] - nm1);
            rs0 += sf[f][0] + sf[f][1];
            rs1 += sf[f][2] + sf[f][3];
        }
        rs0 += __shfl_xor_sync(0xffffffffu, rs0, 1);
        rs0 += __shfl_xor_sync(0xffffffffu, rs0, 2);
        rs1 += __shfl_xor_sync(0xffffffffu, rs1, 1);
        rs1 += __shfl_xor_sync(0xffffffffu, rs1, 2);
        lrow0 += rs0; lrow1 += rs1;

#pragma unroll
        for (int kg = 0; kg < 4; kg++) {
            uint32_t pa[4], pl[4];
            hsplit_pack(sf[2 * kg][0],     sf[2 * kg][1],     pa[0], pl[0]);
            hsplit_pack(sf[2 * kg][2],     sf[2 * kg][3],     pa[1], pl[1]);
            hsplit_pack(sf[2 * kg + 1][0], sf[2 * kg + 1][1], pa[2], pl[2]);
            hsplit_pack(sf[2 * kg + 1][2], sf[2 * kg + 1][3], pa[3], pl[3]);
#pragma unroll
            for (int eg = 0; eg < 4; eg++) {
                uint32_t vh4[4], vl4[4];
                const uint32_t va = SV +
                    (kg * 16 + (((lane >> 3) & 1) << 3) + (lane & 7)) * AROW +
                    (eg << 5) + ((lane >> 4) << 4);
                ldm4t(vh4, va);
                ldm4t(vl4, va + AMAT);
#pragma unroll
                for (int nn = 0; nn < 2; nn++)
                    mma16816(pv[eg * 2 + nn], pa, vh4[nn * 2], vh4[nn * 2 + 1]);
#pragma unroll
                for (int nn = 0; nn < 2; nn++)
                    mma16816(pv[eg * 2 + nn], pl, vh4[nn * 2], vh4[nn * 2 + 1]);
#pragma unroll
                for (int nn = 0; nn < 2; nn++)
                    mma16816(pv[eg * 2 + nn], pa, vl4[nn * 2], vl4[nn * 2 + 1]);
            }
        }
        __syncthreads();
    }

    const int srow0 = jb * 64 + wm + (lane >> 2);
    const int srow1 = srow0 + 8;
    const float sc0 = from_mask[b * Sn + srow0] / lrow0;
    const float sc1 = from_mask[b * Sn + srow1] / lrow1;
#pragma unroll
    for (int f = 0; f < 8; f++) {
        const int e = f * 8 + ((lane & 3) << 1);
        const size_t o0 = (size_t)(b * Sn + srow0) * Dn + h * 64 + e;
        const size_t o1 = (size_t)(b * Sn + srow1) * Dn + h * 64 + e;
        *(__half2*)&g_Chi[o0] = __floats2half2_rn(pv[f][0] * sc0, pv[f][1] * sc0);
        *(__half2*)&g_Chi[o1] = __floats2half2_rn(pv[f][2] * sc1, pv[f][3] * sc1);
    }
}

// ---------------------------------------------------------------------------
extern "C" void kernel_launch(void* const* d_in, const int* in_sizes, int n_in,
                              void* d_out, int out_size)
{
    const float* tokens    = (const float*)d_in[0];
    const float* band_mask = (const float*)d_in[1];
    const float* from_mask = (const float*)d_in[2];
    const float* to_mask   = (const float*)d_in[3];
    const float* Wq        = (const float*)d_in[4];
    const float* Wk        = (const float*)d_in[5];
    const float* Wv        = (const float*)d_in[6];
    const float* Wu        = (const float*)d_in[7];
    const float* bu        = (const float*)d_in[8];
    (void)in_sizes; (void)n_in; (void)out_size;

    __half *ahi, *bqh, *buh, *chi;
    cudaGetSymbolAddress((void**)&ahi, g_Ahi);
    cudaGetSymbolAddress((void**)&bqh, g_Bqkv_h);
    cudaGetSymbolAddress((void**)&buh, g_Bu_h);
    cudaGetSymbolAddress((void**)&chi, g_Chi);

    cudaFuncSetAttribute(attn_k, cudaFuncAttributeMaxDynamicSharedMemorySize, ATTN_SMEM);
    cudaFuncSetAttribute(hmma_gemm<0>, cudaFuncAttributeMaxDynamicSharedMemorySize, GEMM_SMEM);
    cudaFuncSetAttribute(hmma_gemm<1>, cudaFuncAttributeMaxDynamicSharedMemorySize, GEMM_SMEM);

    split_k<<<2048, 256>>>(tokens, ahi, Mrows * Dn / 4);
    packW_all<<<dim3(32, 32, 4), dim3(32, 8)>>>(Wq, Wk, Wv, Wu);

    hmma_gemm<1><<<dim3(24, 64), 256, GEMM_SMEM>>>(ahi, bqh, nullptr, nullptr);
    attn_k<<<Bn * Hn * NBn, 128, ATTN_SMEM>>>(to_mask, band_mask, from_mask);
    hmma_gemm<0><<<dim3(8, 64), 256, GEMM_SMEM>>>(chi, buh, bu, (float*)d_out);
}

// round 12
// speedup vs baseline: 1.8077x; 1.1505x over previous
#include <cuda_runtime.h>
#include <cuda_fp16.h>
#include <cstdint>

// ---------------------------------------------------------------------------
// BigBird transformer block on sm_103 (non-'a' target: no tcgen05/TMEM).
// R12: 2-product attention. K and V are fp16-only (hi); S = qh.kh + ql.kh
// (exact vs stored k), PV = Ph.Vh + Pl.Vh (exact vs stored v). Calibrated
// error model: each dropped correction ~2.5e-4 independent -> predicted
// rel_err ~5.7e-4. KV smem stage halves (18.4KB), ldmatrix stream halves.
// GEMMs stay single-product Ah.Bh (R11).
// ---------------------------------------------------------------------------

namespace {
constexpr int Bn    = 2;
constexpr int Sn    = 4096;
constexpr int Dn    = 1024;
constexpr int Hn    = 16;
constexpr int DHn   = 64;
constexpr int NBn   = 64;
constexpr int NGn   = 2;
constexpr int NMIDn = 60;
constexpr int Mrows = Bn * Sn;              // 8192

// GEMM tiling
constexpr int BK      = 32;
constexpr int NCHUNK  = Dn / BK;             // 32
constexpr int ROWB    = 80;
constexpr int MATB    = 128 * ROWB;          // 10240
constexpr int STG     = 2 * MATB;            // Ah, Bh = 20480 B / stage
constexpr int GEMM_SMEM = 3 * STG;           // 61440 B -> 2 CTAs/SM

// attention smem
constexpr int AROW    = 144;
constexpr int AMAT    = 64 * AROW;           // 9216 B
constexpr int ASTAGE  = 2 * AMAT;            // Kh, Vh = 18432 B
constexpr int AQ_BYTES = 2 * AMAT;           // Qh, Ql
constexpr int ATTN_SMEM = AQ_BYTES + 2 * ASTAGE;  // 55296 B
}

// ---- scratch (device globals) ----------------------------------------------
__device__ __half g_qhi[Bn * Hn * Sn * DHn], g_qlo[Bn * Hn * Sn * DHn];
__device__ __half g_khi[Bn * Hn * Sn * DHn];
__device__ __half g_vhi[Bn * Hn * Sn * DHn];
__device__ __half g_Ahi[Mrows * Dn];
__device__ __half g_Bqkv_h[3 * Dn * Dn];
__device__ __half g_Bu_h[Dn * Dn];
__device__ __half g_Chi[Mrows * Dn];

// ---------------------------------------------------------------------------
// PTX helpers
// ---------------------------------------------------------------------------
__device__ __forceinline__ uint32_t smem_u32(const void* p) {
    uint32_t a;
    asm("{ .reg .u64 t; cvta.to.shared.u64 t, %1; cvt.u32.u64 %0, t; }" : "=r"(a) : "l"(p));
    return a;
}
__device__ __forceinline__ void cpa16(uint32_t dst, const void* src) {
    asm volatile("cp.async.cg.shared.global [%0], [%1], 16;" :: "r"(dst), "l"(src));
}
__device__ __forceinline__ void cpa_commit() {
    asm volatile("cp.async.commit_group;" ::: "memory");
}
template <int N>
__device__ __forceinline__ void cpa_wait() {
    asm volatile("cp.async.wait_group %0;" :: "n"(N) : "memory");
}
__device__ __forceinline__ void ldm4(uint32_t* r, uint32_t addr) {
    asm volatile("ldmatrix.sync.aligned.m8n8.x4.shared.b16 {%0,%1,%2,%3}, [%4];"
                 : "=r"(r[0]), "=r"(r[1]), "=r"(r[2]), "=r"(r[3]) : "r"(addr));
}
__device__ __forceinline__ void ldm4t(uint32_t* r, uint32_t addr) {
    asm volatile("ldmatrix.sync.aligned.m8n8.x4.trans.shared.b16 {%0,%1,%2,%3}, [%4];"
                 : "=r"(r[0]), "=r"(r[1]), "=r"(r[2]), "=r"(r[3]) : "r"(addr));
}
__device__ __forceinline__ void mma16816(float* c, const uint32_t* a,
                                         uint32_t b0, uint32_t b1) {
    asm volatile(
        "mma.sync.aligned.m16n8k16.row.col.f32.f16.f16.f32 "
        "{%0,%1,%2,%3}, {%4,%5,%6,%7}, {%8,%9}, {%0,%1,%2,%3};"
        : "+f"(c[0]), "+f"(c[1]), "+f"(c[2]), "+f"(c[3])
        : "r"(a[0]), "r"(a[1]), "r"(a[2]), "r"(a[3]), "r"(b0), "r"(b1));
}
__device__ __forceinline__ void hsplit(float v, __half& h, __half& l) {
    h = __float2half_rn(v);
    l = __float2half_rn(v - __half2float(h));
}
__device__ __forceinline__ void hsplit_pack(float v0, float v1,
                                            uint32_t& hp, uint32_t& lp) {
    __half2 h = __floats2half2_rn(v0, v1);
    __half2 l = __floats2half2_rn(v0 - __low2float(h), v1 - __high2float(h));
    hp = *reinterpret_cast<uint32_t*>(&h);
    lp = *reinterpret_cast<uint32_t*>(&l);
}

// ---------------------------------------------------------------------------
// prep kernels
// ---------------------------------------------------------------------------
__global__ void split_k(const float* __restrict__ X,
                        __half* __restrict__ Hi, int n4)
{
    for (int i = blockIdx.x * blockDim.x + threadIdx.x; i < n4;
         i += gridDim.x * blockDim.x) {
        float4 v = ((const float4*)X)[i];
        *(__half2*)(Hi + 4 * i)     = __floats2half2_rn(v.x, v.y);
        *(__half2*)(Hi + 4 * i + 2) = __floats2half2_rn(v.z, v.w);
    }
}

__global__ void packW_all(const float* __restrict__ Wq, const float* __restrict__ Wk,
                          const float* __restrict__ Wv, const float* __restrict__ Wu)
{
    __shared__ float tile[32][33];
    const int z = blockIdx.z;
    const float* W = (z == 0) ? Wq : (z == 1) ? Wk : (z == 2) ? Wv : Wu;
    __half* Bh = (z < 3) ? g_Bqkv_h : g_Bu_h;
    const int nOff = (z < 3) ? z * 1024 : 0;

    const int tx = threadIdx.x, ty = threadIdx.y;
    const int n0 = blockIdx.x * 32, k0 = blockIdx.y * 32;
#pragma unroll
    for (int j = 0; j < 4; j++)
        tile[ty + j * 8][tx] = W[(size_t)(k0 + ty + j * 8) * Dn + n0 + tx];
    __syncthreads();
    const int kk = k0 + tx;
#pragma unroll
    for (int j = 0; j < 4; j++) {
        const int n = n0 + ty + j * 8;
        Bh[(size_t)(nOff + n) * Dn + kk] = __float2half_rn(tile[tx][ty + j * 8]);
    }
}

// ---------------------------------------------------------------------------
// fp16 HMMA GEMM, single product Ah.Bh, 3-stage pipeline, 2 CTAs/SM.
// MODE 1: scatter q (hi/lo, pre-scaled 1/8), k (hi), v (hi) head layout.
// MODE 0: d_out = D + bias.
// ---------------------------------------------------------------------------
template <int MODE>
__global__ void __launch_bounds__(256, 2)
hmma_gemm(const __half* __restrict__ Ahi, const __half* __restrict__ Bh,
          const float* __restrict__ bias, float* __restrict__ Cout)
{
    extern __shared__ char smem[];
    const uint32_t sb = smem_u32(smem);
    const int t    = threadIdx.x;
    const int lane = t & 31;
    const int wid  = t >> 5;
    const int wm   = (wid & 1) << 6;
    const int wn   = (wid >> 1) << 5;
    const int m0   = blockIdx.y << 7;
    const int n0   = blockIdx.x << 7;

    auto load_stage = [&](int kc, int s) {
        const int kel = kc * BK;
        const uint32_t stb = sb + s * STG;
#pragma unroll
        for (int j = 0; j < 4; j++) {
            const int idx = t + (j << 8);
            const int mat = idx >> 9;
            const int rr  = (idx >> 2) & 127;
            const int cc  = idx & 3;
            const __half* src = mat
                ? Bh  + (size_t)(n0 + rr) * Dn + kel + (cc << 3)
                : Ahi + (size_t)(m0 + rr) * Dn + kel + (cc << 3);
            cpa16(stb + mat * MATB + rr * ROWB + (cc << 4), src);
        }
        cpa_commit();
    };

    float acc[4][4][4];
#pragma unroll
    for (int i = 0; i < 4; i++)
#pragma unroll
        for (int j = 0; j < 4; j++)
#pragma unroll
            for (int q = 0; q < 4; q++) acc[i][j][q] = 0.f;

    load_stage(0, 0);
    load_stage(1, 1);

    for (int kc = 0; kc < NCHUNK; ++kc) {
        if (kc + 2 < NCHUNK) { load_stage(kc + 2, (kc + 2) % 3); cpa_wait<2>(); }
        else if (kc + 1 < NCHUNK) cpa_wait<1>();
        else cpa_wait<0>();
        __syncthreads();
        const uint32_t stb = sb + (kc % 3) * STG;

#pragma unroll
        for (int k16 = 0; k16 < 2; k16++) {
            uint32_t ah[16];
            const uint32_t abase = stb + (wm + (lane & 15)) * ROWB +
                                   (k16 << 5) + ((lane >> 4) << 4);
#pragma unroll
            for (int mt = 0; mt < 4; mt++)
                ldm4(ah + 4 * mt, abase + mt * 16 * ROWB);
#pragma unroll
            for (int ng = 0; ng < 2; ng++) {
                uint32_t bh4[4];
                const uint32_t bbase = stb + MATB +
                                       (wn + ng * 16 + (lane & 15)) * ROWB +
                                       (k16 << 5) + ((lane >> 4) << 4);
                ldm4(bh4, bbase);
#pragma unroll
                for (int mt = 0; mt < 4; mt++) {
#pragma unroll
                    for (int nn = 0; nn < 2; nn++) {
                        mma16816(acc[mt][ng * 2 + nn], ah + 4 * mt,
                                 nn ? bh4[1] : bh4[0], nn ? bh4[3] : bh4[2]);
                    }
                }
            }
        }
        __syncthreads();
    }

    const int rbase = m0 + wm + (lane >> 2);
    const int cbase = (lane & 3) << 1;
#pragma unroll
    for (int mt = 0; mt < 4; mt++) {
#pragma unroll
        for (int nf = 0; nf < 4; nf++) {
            const int n = n0 + wn + ((nf >> 1) << 4) + ((nf & 1) << 3) + cbase;
            const float* c = acc[mt][nf];
#pragma unroll
            for (int half = 0; half < 2; half++) {
                const int r = rbase + mt * 16 + half * 8;
                float v0 = c[2 * half], v1 = c[2 * half + 1];
                if (MODE == 0) {
                    *(float2*)&Cout[(size_t)r * Dn + n] =
                        make_float2(v0 + bias[n], v1 + bias[n + 1]);
                } else {
                    const int mat = n >> 10;
                    const int nn  = n & 1023;
                    const int h   = nn >> 6;
                    const int e   = nn & 63;
                    const int b   = r >> 12;
                    const int s   = r & (Sn - 1);
                    const size_t off = ((size_t)(b * Hn + h) * Sn + s) * DHn + e;
                    if (mat == 0) {
                        v0 *= 0.125f; v1 *= 0.125f;   // fold 1/sqrt(d) into q
                        __half h0, h1, l0, l1;
                        hsplit(v0, h0, l0);
                        hsplit(v1, h1, l1);
                        *(__half2*)&g_qhi[off] = __halves2half2(h0, h1);
                        *(__half2*)&g_qlo[off] = __halves2half2(l0, l1);
                    } else {
                        __half* arr = (mat == 1) ? g_khi : g_vhi;
                        *(__half2*)&arr[off] = __floats2half2_rn(v0, v1);
                    }
                }
            }
        }
    }
}

// ---------------------------------------------------------------------------
// Flash attention: S = qh.kh + ql.kh, PV = Ph.Vh + Pl.Vh (k,v fp16-only).
// ---------------------------------------------------------------------------
__device__ __forceinline__ int kb_of(int jb, int kt, int& mtype, int& kc0) {
    mtype = 0; kc0 = 0;
    if (jb <= NGn) return kt * 64;
    if (jb == NBn - 1) return (kt < 2) ? kt * 64 : (Sn - 192 + (kt - 2) * 64);
    if (kt < 2) return kt * 64;
    mtype = 1; kc0 = (kt - 2) * 64;
    return (jb - 1) * 64 + (kt - 2) * 64;
}

__global__ void __launch_bounds__(128, 2)
attn_k(const float* __restrict__ to_mask,
       const float* __restrict__ band_mask,
       const float* __restrict__ from_mask)
{
    extern __shared__ char smem[];
    const uint32_t sb = smem_u32(smem);
    const int t = threadIdx.x, lane = t & 31, wid = t >> 5;
    const int idx = blockIdx.x;
    const int jb  = idx >> 5;
    const int bh  = idx & 31;
    const int b   = bh >> 4, h = bh & 15;
    const int wm  = wid << 4;

    const size_t hoff = (size_t)(b * Hn + h) * Sn * DHn;
    const __half* qhg = g_qhi + hoff + (size_t)jb * 64 * DHn;
    const __half* qlg = g_qlo + hoff + (size_t)jb * 64 * DHn;
    const __half* khg = g_khi + hoff;
    const __half* vhg = g_vhi + hoff;

    // Q tiles (hi at 0, lo at AMAT): 2 mats x 64 rows x 8 chunks
#pragma unroll
    for (int j = 0; j < 8; j++) {
        const int i2 = t + (j << 7);
        const int mat = i2 >> 9;
        const int rr  = (i2 >> 3) & 63;
        const int cc  = i2 & 7;
        cpa16(sb + mat * AMAT + rr * AROW + (cc << 4),
              (mat ? qlg : qhg) + rr * DHn + (cc << 3));
    }
    cpa_commit();

    auto loadKV = [&](int kb, int s) {
        const uint32_t base = sb + AQ_BYTES + s * ASTAGE;
        // 2 mats (Kh, Vh) x 64 rows x 8 chunks = 1024
#pragma unroll
        for (int j = 0; j < 8; j++) {
            const int i2 = t + (j << 7);
            const int mat = i2 >> 9;
            const int rr  = (i2 >> 3) & 63;
            const int cc  = i2 & 7;
            const __half* src = (mat ? vhg : khg) +
                (size_t)(kb + rr) * DHn + (cc << 3);
            cpa16(base + mat * AMAT + rr * AROW + (cc << 4), src);
        }
        cpa_commit();
    };

    const int ntiles = (jb < NGn) ? 64 : 5;
    int mty, kc0_;
    loadKV(kb_of(jb, 0, mty, kc0_), 0);

    uint32_t qh[4][4], ql[4][4];
    float pv[8][4];
#pragma unroll
    for (int f = 0; f < 8; f++)
#pragma unroll
        for (int q = 0; q < 4; q++) pv[f][q] = 0.f;
    float mrow0 = -1e30f, mrow1 = -1e30f, lrow0 = 0.f, lrow1 = 0.f;

    for (int kt = 0; kt < ntiles; ++kt) {
        if (kt + 1 < ntiles) {
            int mt2, kc2;
            loadKV(kb_of(jb, kt + 1, mt2, kc2), (kt + 1) & 1);
            cpa_wait<1>();
        } else {
            cpa_wait<0>();
        }
        __syncthreads();

        if (kt == 0) {
            const uint32_t qbase = sb + (wm + (lane & 15)) * AROW + ((lane >> 4) << 4);
#pragma unroll
            for (int ks = 0; ks < 4; ks++) {
                ldm4(qh[ks], qbase + (ks << 5));
                ldm4(ql[ks], qbase + (ks << 5) + AMAT);
            }
        }

        int mtype, kcol0;
        const int kb = kb_of(jb, kt, mtype, kcol0);
        const uint32_t SK = sb + AQ_BYTES + (kt & 1) * ASTAGE;
        const uint32_t SV = SK + AMAT;

        float sf[8][4];
#pragma unroll
        for (int f = 0; f < 8; f++)
#pragma unroll
            for (int q = 0; q < 4; q++) sf[f][q] = 0.f;
#pragma unroll
        for (int ks = 0; ks < 4; ks++) {
#pragma unroll
            for (int kg = 0; kg < 4; kg++) {
                uint32_t kh4[4];
                const uint32_t ka = SK + (kg * 16 + (lane & 15)) * AROW +
                                    (ks << 5) + ((lane >> 4) << 4);
                ldm4(kh4, ka);
#pragma unroll
                for (int nn = 0; nn < 2; nn++)
                    mma16816(sf[kg * 2 + nn], qh[ks],
                             nn ? kh4[1] : kh4[0], nn ? kh4[3] : kh4[2]);
#pragma unroll
                for (int nn = 0; nn < 2; nn++)
                    mma16816(sf[kg * 2 + nn], ql[ks],
                             nn ? kh4[1] : kh4[0], nn ? kh4[3] : kh4[2]);
            }
        }

        const int colb = (lane & 3) << 1;
        if (mtype == 0) {
#pragma unroll
            for (int f = 0; f < 8; f++) {
                const int key = kb + f * 8 + colb;
                const float p0 = (1.0f - to_mask[b * Sn + key]) * -10000.0f;
                const float p1 = (1.0f - to_mask[b * Sn + key + 1]) * -10000.0f;
                sf[f][0] += p0;
                sf[f][1] += p1;
                sf[f][2] += p0;
                sf[f][3] += p1;
            }
        } else {
            const int m_idx = jb - (NGn + 1);
            const int qi0 = wm + (lane >> 2);
            const float* bm0 = band_mask +
                ((size_t)(b * NMIDn + m_idx) * 64 + qi0) * 192 + kcol0 + colb;
#pragma unroll
            for (int f = 0; f < 8; f++) {
                sf[f][0] += (1.0f - bm0[f * 8]) * -10000.0f;
                sf[f][1] += (1.0f - bm0[f * 8 + 1]) * -10000.0f;
                sf[f][2] += (1.0f - bm0[8 * 192 + f * 8]) * -10000.0f;
                sf[f][3] += (1.0f - bm0[8 * 192 + f * 8 + 1]) * -10000.0f;
            }
        }

        float mx0 = -1e30f, mx1 = -1e30f;
#pragma unroll
        for (int f = 0; f < 8; f++) {
            mx0 = fmaxf(mx0, fmaxf(sf[f][0], sf[f][1]));
            mx1 = fmaxf(mx1, fmaxf(sf[f][2], sf[f][3]));
        }
        mx0 = fmaxf(mx0, __shfl_xor_sync(0xffffffffu, mx0, 1));
        mx0 = fmaxf(mx0, __shfl_xor_sync(0xffffffffu, mx0, 2));
        mx1 = fmaxf(mx1, __shfl_xor_sync(0xffffffffu, mx1, 1));
        mx1 = fmaxf(mx1, __shfl_xor_sync(0xffffffffu, mx1, 2));

        const float nm0 = fmaxf(mrow0, mx0), nm1 = fmaxf(mrow1, mx1);
        const float corr0 = __expf(mrow0 - nm0), corr1 = __expf(mrow1 - nm1);
        mrow0 = nm0; mrow1 = nm1;
        lrow0 *= corr0; lrow1 *= corr1;
#pragma unroll
        for (int f = 0; f < 8; f++) {
            pv[f][0] *= corr0; pv[f][1] *= corr0;
            pv[f][2] *= corr1; pv[f][3] *= corr1;
        }

        float rs0 = 0.f, rs1 = 0.f;
#pragma unroll
        for (int f = 0; f < 8; f++) {
            sf[f][0] = __expf(sf[f][0] - nm0);
            sf[f][1] = __expf(sf[f][1] - nm0);
            sf[f][2] = __expf(sf[f][2] - nm1);
            sf[f][3] = __expf(sf[f][3] - nm1);
            rs0 += sf[f][0] + sf[f][1];
            rs1 += sf[f][2] + sf[f][3];
        }
        rs0 += __shfl_xor_sync(0xffffffffu, rs0, 1);
        rs0 += __shfl_xor_sync(0xffffffffu, rs0, 2);
        rs1 += __shfl_xor_sync(0xffffffffu, rs1, 1);
        rs1 += __shfl_xor_sync(0xffffffffu, rs1, 2);
        lrow0 += rs0; lrow1 += rs1;

#pragma unroll
        for (int kg = 0; kg < 4; kg++) {
            uint32_t pa[4], pl[4];
            hsplit_pack(sf[2 * kg][0],     sf[2 * kg][1],     pa[0], pl[0]);
            hsplit_pack(sf[2 * kg][2],     sf[2 * kg][3],     pa[1], pl[1]);
            hsplit_pack(sf[2 * kg + 1][0], sf[2 * kg + 1][1], pa[2], pl[2]);
            hsplit_pack(sf[2 * kg + 1][2], sf[2 * kg + 1][3], pa[3], pl[3]);
#pragma unroll
            for (int eg = 0; eg < 4; eg++) {
                uint32_t vh4[4];
                const uint32_t va = SV +
                    (kg * 16 + (((lane >> 3) & 1) << 3) + (lane & 7)) * AROW +
                    (eg << 5) + ((lane >> 4) << 4);
                ldm4t(vh4, va);
#pragma unroll
                for (int nn = 0; nn < 2; nn++)
                    mma16816(pv[eg * 2 + nn], pa, vh4[nn * 2], vh4[nn * 2 + 1]);
#pragma unroll
                for (int nn = 0; nn < 2; nn++)
                    mma16816(pv[eg * 2 + nn], pl, vh4[nn * 2], vh4[nn * 2 + 1]);
            }
        }
        __syncthreads();
    }

    const int srow0 = jb * 64 + wm + (lane >> 2);
    const int srow1 = srow0 + 8;
    const float sc0 = from_mask[b * Sn + srow0] / lrow0;
    const float sc1 = from_mask[b * Sn + srow1] / lrow1;
#pragma unroll
    for (int f = 0; f < 8; f++) {
        const int e = f * 8 + ((lane & 3) << 1);
        const size_t o0 = (size_t)(b * Sn + srow0) * Dn + h * 64 + e;
        const size_t o1 = (size_t)(b * Sn + srow1) * Dn + h * 64 + e;
        *(__half2*)&g_Chi[o0] = __floats2half2_rn(pv[f][0] * sc0, pv[f][1] * sc0);
        *(__half2*)&g_Chi[o1] = __floats2half2_rn(pv[f][2] * sc1, pv[f][3] * sc1);
    }
}

// ---------------------------------------------------------------------------
extern "C" void kernel_launch(void* const* d_in, const int* in_sizes, int n_in,
                              void* d_out, int out_size)
{
    const float* tokens    = (const float*)d_in[0];
    const float* band_mask = (const float*)d_in[1];
    const float* from_mask = (const float*)d_in[2];
    const float* to_mask   = (const float*)d_in[3];
    const float* Wq        = (const float*)d_in[4];
    const float* Wk        = (const float*)d_in[5];
    const float* Wv        = (const float*)d_in[6];
    const float* Wu        = (const float*)d_in[7];
    const float* bu        = (const float*)d_in[8];
    (void)in_sizes; (void)n_in; (void)out_size;

    __half *ahi, *bqh, *buh, *chi;
    cudaGetSymbolAddress((void**)&ahi, g_Ahi);
    cudaGetSymbolAddress((void**)&bqh, g_Bqkv_h);
    cudaGetSymbolAddress((void**)&buh, g_Bu_h);
    cudaGetSymbolAddress((void**)&chi, g_Chi);

    cudaFuncSetAttribute(attn_k, cudaFuncAttributeMaxDynamicSharedMemorySize, ATTN_SMEM);
    cudaFuncSetAttribute(hmma_gemm<0>, cudaFuncAttributeMaxDynamicSharedMemorySize, GEMM_SMEM);
    cudaFuncSetAttribute(hmma_gemm<1>, cudaFuncAttributeMaxDynamicSharedMemorySize, GEMM_SMEM);

    split_k<<<2048, 256>>>(tokens, ahi, Mrows * Dn / 4);
    packW_all<<<dim3(32, 32, 4), dim3(32, 8)>>>(Wq, Wk, Wv, Wu);

    hmma_gemm<1><<<dim3(24, 64), 256, GEMM_SMEM>>>(ahi, bqh, nullptr, nullptr);
    attn_k<<<Bn * Hn * NBn, 128, ATTN_SMEM>>>(to_mask, band_mask, from_mask);
    hmma_gemm<0><<<dim3(8, 64), 256, GEMM_SMEM>>>(chi, buh, bu, (float*)d_out);
}

// round 13
// speedup vs baseline: 1.8646x; 1.0315x over previous
#include <cuda_runtime.h>
#include <cuda_fp16.h>
#include <cstdint>

// ---------------------------------------------------------------------------
// BigBird transformer block on sm_103 (non-'a' target: no tcgen05/TMEM).
// R13: single-product attention. q and P are fp16-only: S = qh.kh,
// PV = Ph.Vh. Calibrated error model: two more ~2.5e-4 independent drops
// -> predicted rel_err ~6.1e-4 (threshold 1e-3). Attention MMA floor
// halves; Q smem halves; P split cost removed.
// GEMMs stay single-product Ah.Bh (at the mma.sync rt=16 issue wall).
// ---------------------------------------------------------------------------

namespace {
constexpr int Bn    = 2;
constexpr int Sn    = 4096;
constexpr int Dn    = 1024;
constexpr int Hn    = 16;
constexpr int DHn   = 64;
constexpr int NBn   = 64;
constexpr int NGn   = 2;
constexpr int NMIDn = 60;
constexpr int Mrows = Bn * Sn;              // 8192

// GEMM tiling
constexpr int BK      = 32;
constexpr int NCHUNK  = Dn / BK;             // 32
constexpr int ROWB    = 80;
constexpr int MATB    = 128 * ROWB;          // 10240
constexpr int STG     = 2 * MATB;            // Ah, Bh = 20480 B / stage
constexpr int GEMM_SMEM = 3 * STG;           // 61440 B -> 2 CTAs/SM

// attention smem
constexpr int AROW    = 144;
constexpr int AMAT    = 64 * AROW;           // 9216 B
constexpr int ASTAGE  = 2 * AMAT;            // Kh, Vh = 18432 B
constexpr int AQ_BYTES = AMAT;               // Qh only
constexpr int ATTN_SMEM = AQ_BYTES + 2 * ASTAGE;  // 46080 B
}

// ---- scratch (device globals) ----------------------------------------------
__device__ __half g_qhi[Bn * Hn * Sn * DHn];
__device__ __half g_khi[Bn * Hn * Sn * DHn];
__device__ __half g_vhi[Bn * Hn * Sn * DHn];
__device__ __half g_Ahi[Mrows * Dn];
__device__ __half g_Bqkv_h[3 * Dn * Dn];
__device__ __half g_Bu_h[Dn * Dn];
__device__ __half g_Chi[Mrows * Dn];

// ---------------------------------------------------------------------------
// PTX helpers
// ---------------------------------------------------------------------------
__device__ __forceinline__ uint32_t smem_u32(const void* p) {
    uint32_t a;
    asm("{ .reg .u64 t; cvta.to.shared.u64 t, %1; cvt.u32.u64 %0, t; }" : "=r"(a) : "l"(p));
    return a;
}
__device__ __forceinline__ void cpa16(uint32_t dst, const void* src) {
    asm volatile("cp.async.cg.shared.global [%0], [%1], 16;" :: "r"(dst), "l"(src));
}
__device__ __forceinline__ void cpa_commit() {
    asm volatile("cp.async.commit_group;" ::: "memory");
}
template <int N>
__device__ __forceinline__ void cpa_wait() {
    asm volatile("cp.async.wait_group %0;" :: "n"(N) : "memory");
}
__device__ __forceinline__ void ldm4(uint32_t* r, uint32_t addr) {
    asm volatile("ldmatrix.sync.aligned.m8n8.x4.shared.b16 {%0,%1,%2,%3}, [%4];"
                 : "=r"(r[0]), "=r"(r[1]), "=r"(r[2]), "=r"(r[3]) : "r"(addr));
}
__device__ __forceinline__ void ldm4t(uint32_t* r, uint32_t addr) {
    asm volatile("ldmatrix.sync.aligned.m8n8.x4.trans.shared.b16 {%0,%1,%2,%3}, [%4];"
                 : "=r"(r[0]), "=r"(r[1]), "=r"(r[2]), "=r"(r[3]) : "r"(addr));
}
__device__ __forceinline__ void mma16816(float* c, const uint32_t* a,
                                         uint32_t b0, uint32_t b1) {
    asm volatile(
        "mma.sync.aligned.m16n8k16.row.col.f32.f16.f16.f32 "
        "{%0,%1,%2,%3}, {%4,%5,%6,%7}, {%8,%9}, {%0,%1,%2,%3};"
        : "+f"(c[0]), "+f"(c[1]), "+f"(c[2]), "+f"(c[3])
        : "r"(a[0]), "r"(a[1]), "r"(a[2]), "r"(a[3]), "r"(b0), "r"(b1));
}
__device__ __forceinline__ uint32_t hpack(float v0, float v1) {
    __half2 h = __floats2half2_rn(v0, v1);
    return *reinterpret_cast<uint32_t*>(&h);
}

// ---------------------------------------------------------------------------
// prep kernels
// ---------------------------------------------------------------------------
__global__ void split_k(const float* __restrict__ X,
                        __half* __restrict__ Hi, int n4)
{
    for (int i = blockIdx.x * blockDim.x + threadIdx.x; i < n4;
         i += gridDim.x * blockDim.x) {
        float4 v = ((const float4*)X)[i];
        *(__half2*)(Hi + 4 * i)     = __floats2half2_rn(v.x, v.y);
        *(__half2*)(Hi + 4 * i + 2) = __floats2half2_rn(v.z, v.w);
    }
}

__global__ void packW_all(const float* __restrict__ Wq, const float* __restrict__ Wk,
                          const float* __restrict__ Wv, const float* __restrict__ Wu)
{
    __shared__ float tile[32][33];
    const int z = blockIdx.z;
    const float* W = (z == 0) ? Wq : (z == 1) ? Wk : (z == 2) ? Wv : Wu;
    __half* Bh = (z < 3) ? g_Bqkv_h : g_Bu_h;
    const int nOff = (z < 3) ? z * 1024 : 0;

    const int tx = threadIdx.x, ty = threadIdx.y;
    const int n0 = blockIdx.x * 32, k0 = blockIdx.y * 32;
#pragma unroll
    for (int j = 0; j < 4; j++)
        tile[ty + j * 8][tx] = W[(size_t)(k0 + ty + j * 8) * Dn + n0 + tx];
    __syncthreads();
    const int kk = k0 + tx;
#pragma unroll
    for (int j = 0; j < 4; j++) {
        const int n = n0 + ty + j * 8;
        Bh[(size_t)(nOff + n) * Dn + kk] = __float2half_rn(tile[tx][ty + j * 8]);
    }
}

// ---------------------------------------------------------------------------
// fp16 HMMA GEMM, single product Ah.Bh, 3-stage pipeline, 2 CTAs/SM.
// MODE 1: scatter q (pre-scaled 1/8), k, v as fp16 head layout.
// MODE 0: d_out = D + bias.
// ---------------------------------------------------------------------------
template <int MODE>
__global__ void __launch_bounds__(256, 2)
hmma_gemm(const __half* __restrict__ Ahi, const __half* __restrict__ Bh,
          const float* __restrict__ bias, float* __restrict__ Cout)
{
    extern __shared__ char smem[];
    const uint32_t sb = smem_u32(smem);
    const int t    = threadIdx.x;
    const int lane = t & 31;
    const int wid  = t >> 5;
    const int wm   = (wid & 1) << 6;
    const int wn   = (wid >> 1) << 5;
    const int m0   = blockIdx.y << 7;
    const int n0   = blockIdx.x << 7;

    auto load_stage = [&](int kc, int s) {
        const int kel = kc * BK;
        const uint32_t stb = sb + s * STG;
#pragma unroll
        for (int j = 0; j < 4; j++) {
            const int idx = t + (j << 8);
            const int mat = idx >> 9;
            const int rr  = (idx >> 2) & 127;
            const int cc  = idx & 3;
            const __half* src = mat
                ? Bh  + (size_t)(n0 + rr) * Dn + kel + (cc << 3)
                : Ahi + (size_t)(m0 + rr) * Dn + kel + (cc << 3);
            cpa16(stb + mat * MATB + rr * ROWB + (cc << 4), src);
        }
        cpa_commit();
    };

    float acc[4][4][4];
#pragma unroll
    for (int i = 0; i < 4; i++)
#pragma unroll
        for (int j = 0; j < 4; j++)
#pragma unroll
            for (int q = 0; q < 4; q++) acc[i][j][q] = 0.f;

    load_stage(0, 0);
    load_stage(1, 1);

    for (int kc = 0; kc < NCHUNK; ++kc) {
        if (kc + 2 < NCHUNK) { load_stage(kc + 2, (kc + 2) % 3); cpa_wait<2>(); }
        else if (kc + 1 < NCHUNK) cpa_wait<1>();
        else cpa_wait<0>();
        __syncthreads();
        const uint32_t stb = sb + (kc % 3) * STG;

#pragma unroll
        for (int k16 = 0; k16 < 2; k16++) {
            uint32_t ah[16];
            const uint32_t abase = stb + (wm + (lane & 15)) * ROWB +
                                   (k16 << 5) + ((lane >> 4) << 4);
#pragma unroll
            for (int mt = 0; mt < 4; mt++)
                ldm4(ah + 4 * mt, abase + mt * 16 * ROWB);
#pragma unroll
            for (int ng = 0; ng < 2; ng++) {
                uint32_t bh4[4];
                const uint32_t bbase = stb + MATB +
                                       (wn + ng * 16 + (lane & 15)) * ROWB +
                                       (k16 << 5) + ((lane >> 4) << 4);
                ldm4(bh4, bbase);
#pragma unroll
                for (int mt = 0; mt < 4; mt++) {
#pragma unroll
                    for (int nn = 0; nn < 2; nn++) {
                        mma16816(acc[mt][ng * 2 + nn], ah + 4 * mt,
                                 nn ? bh4[1] : bh4[0], nn ? bh4[3] : bh4[2]);
                    }
                }
            }
        }
        __syncthreads();
    }

    const int rbase = m0 + wm + (lane >> 2);
    const int cbase = (lane & 3) << 1;
#pragma unroll
    for (int mt = 0; mt < 4; mt++) {
#pragma unroll
        for (int nf = 0; nf < 4; nf++) {
            const int n = n0 + wn + ((nf >> 1) << 4) + ((nf & 1) << 3) + cbase;
            const float* c = acc[mt][nf];
#pragma unroll
            for (int half = 0; half < 2; half++) {
                const int r = rbase + mt * 16 + half * 8;
                float v0 = c[2 * half], v1 = c[2 * half + 1];
                if (MODE == 0) {
                    *(float2*)&Cout[(size_t)r * Dn + n] =
                        make_float2(v0 + bias[n], v1 + bias[n + 1]);
                } else {
                    const int mat = n >> 10;
                    const int nn  = n & 1023;
                    const int h   = nn >> 6;
                    const int e   = nn & 63;
                    const int b   = r >> 12;
                    const int s   = r & (Sn - 1);
                    const size_t off = ((size_t)(b * Hn + h) * Sn + s) * DHn + e;
                    if (mat == 0) { v0 *= 0.125f; v1 *= 0.125f; }
                    __half* arr = (mat == 0) ? g_qhi : (mat == 1) ? g_khi : g_vhi;
                    *(__half2*)&arr[off] = __floats2half2_rn(v0, v1);
                }
            }
        }
    }
}

// ---------------------------------------------------------------------------
// Flash attention, single product: S = qh.kh, PV = Ph.Vh.
// ---------------------------------------------------------------------------
__device__ __forceinline__ int kb_of(int jb, int kt, int& mtype, int& kc0) {
    mtype = 0; kc0 = 0;
    if (jb <= NGn) return kt * 64;
    if (jb == NBn - 1) return (kt < 2) ? kt * 64 : (Sn - 192 + (kt - 2) * 64);
    if (kt < 2) return kt * 64;
    mtype = 1; kc0 = (kt - 2) * 64;
    return (jb - 1) * 64 + (kt - 2) * 64;
}

__global__ void __launch_bounds__(128, 2)
attn_k(const float* __restrict__ to_mask,
       const float* __restrict__ band_mask,
       const float* __restrict__ from_mask)
{
    extern __shared__ char smem[];
    const uint32_t sb = smem_u32(smem);
    const int t = threadIdx.x, lane = t & 31, wid = t >> 5;
    const int idx = blockIdx.x;
    const int jb  = idx >> 5;             // global blocks first
    const int bh  = idx & 31;
    const int b   = bh >> 4, h = bh & 15;
    const int wm  = wid << 4;

    const size_t hoff = (size_t)(b * Hn + h) * Sn * DHn;
    const __half* qhg = g_qhi + hoff + (size_t)jb * 64 * DHn;
    const __half* khg = g_khi + hoff;
    const __half* vhg = g_vhi + hoff;

    // Q tile: 64 rows x 8 chunks = 512
#pragma unroll
    for (int j = 0; j < 4; j++) {
        const int i2 = t + (j << 7);
        const int rr  = (i2 >> 3) & 63;
        const int cc  = i2 & 7;
        cpa16(sb + rr * AROW + (cc << 4), qhg + rr * DHn + (cc << 3));
    }
    cpa_commit();

    auto loadKV = [&](int kb, int s) {
        const uint32_t base = sb + AQ_BYTES + s * ASTAGE;
#pragma unroll
        for (int j = 0; j < 8; j++) {
            const int i2 = t + (j << 7);
            const int mat = i2 >> 9;
            const int rr  = (i2 >> 3) & 63;
            const int cc  = i2 & 7;
            const __half* src = (mat ? vhg : khg) +
                (size_t)(kb + rr) * DHn + (cc << 3);
            cpa16(base + mat * AMAT + rr * AROW + (cc << 4), src);
        }
        cpa_commit();
    };

    const int ntiles = (jb < NGn) ? 64 : 5;
    int mty, kc0_;
    loadKV(kb_of(jb, 0, mty, kc0_), 0);

    uint32_t qh[4][4];
    float pv[8][4];
#pragma unroll
    for (int f = 0; f < 8; f++)
#pragma unroll
        for (int q = 0; q < 4; q++) pv[f][q] = 0.f;
    float mrow0 = -1e30f, mrow1 = -1e30f, lrow0 = 0.f, lrow1 = 0.f;

    for (int kt = 0; kt < ntiles; ++kt) {
        if (kt + 1 < ntiles) {
            int mt2, kc2;
            loadKV(kb_of(jb, kt + 1, mt2, kc2), (kt + 1) & 1);
            cpa_wait<1>();
        } else {
            cpa_wait<0>();
        }
        __syncthreads();

        if (kt == 0) {
            const uint32_t qbase = sb + (wm + (lane & 15)) * AROW + ((lane >> 4) << 4);
#pragma unroll
            for (int ks = 0; ks < 4; ks++)
                ldm4(qh[ks], qbase + (ks << 5));
        }

        int mtype, kcol0;
        const int kb = kb_of(jb, kt, mtype, kcol0);
        const uint32_t SK = sb + AQ_BYTES + (kt & 1) * ASTAGE;
        const uint32_t SV = SK + AMAT;

        float sf[8][4];
#pragma unroll
        for (int f = 0; f < 8; f++)
#pragma unroll
            for (int q = 0; q < 4; q++) sf[f][q] = 0.f;
#pragma unroll
        for (int ks = 0; ks < 4; ks++) {
#pragma unroll
            for (int kg = 0; kg < 4; kg++) {
                uint32_t kh4[4];
                const uint32_t ka = SK + (kg * 16 + (lane & 15)) * AROW +
                                    (ks << 5) + ((lane >> 4) << 4);
                ldm4(kh4, ka);
#pragma unroll
                for (int nn = 0; nn < 2; nn++)
                    mma16816(sf[kg * 2 + nn], qh[ks],
                             nn ? kh4[1] : kh4[0], nn ? kh4[3] : kh4[2]);
            }
        }

        const int colb = (lane & 3) << 1;
        if (mtype == 0) {
#pragma unroll
            for (int f = 0; f < 8; f++) {
                const int key = kb + f * 8 + colb;
                const float p0 = (1.0f - to_mask[b * Sn + key]) * -10000.0f;
                const float p1 = (1.0f - to_mask[b * Sn + key + 1]) * -10000.0f;
                sf[f][0] += p0;
                sf[f][1] += p1;
                sf[f][2] += p0;
                sf[f][3] += p1;
            }
        } else {
            const int m_idx = jb - (NGn + 1);
            const int qi0 = wm + (lane >> 2);
            const float* bm0 = band_mask +
                ((size_t)(b * NMIDn + m_idx) * 64 + qi0) * 192 + kcol0 + colb;
#pragma unroll
            for (int f = 0; f < 8; f++) {
                sf[f][0] += (1.0f - bm0[f * 8]) * -10000.0f;
                sf[f][1] += (1.0f - bm0[f * 8 + 1]) * -10000.0f;
                sf[f][2] += (1.0f - bm0[8 * 192 + f * 8]) * -10000.0f;
                sf[f][3] += (1.0f - bm0[8 * 192 + f * 8 + 1]) * -10000.0f;
            }
        }

        float mx0 = -1e30f, mx1 = -1e30f;
#pragma unroll
        for (int f = 0; f < 8; f++) {
            mx0 = fmaxf(mx0, fmaxf(sf[f][0], sf[f][1]));
            mx1 = fmaxf(mx1, fmaxf(sf[f][2], sf[f][3]));
        }
        mx0 = fmaxf(mx0, __shfl_xor_sync(0xffffffffu, mx0, 1));
        mx0 = fmaxf(mx0, __shfl_xor_sync(0xffffffffu, mx0, 2));
        mx1 = fmaxf(mx1, __shfl_xor_sync(0xffffffffu, mx1, 1));
        mx1 = fmaxf(mx1, __shfl_xor_sync(0xffffffffu, mx1, 2));

        const float nm0 = fmaxf(mrow0, mx0), nm1 = fmaxf(mrow1, mx1);
        const float corr0 = __expf(mrow0 - nm0), corr1 = __expf(mrow1 - nm1);
        mrow0 = nm0; mrow1 = nm1;
        lrow0 *= corr0; lrow1 *= corr1;
#pragma unroll
        for (int f = 0; f < 8; f++) {
            pv[f][0] *= corr0; pv[f][1] *= corr0;
            pv[f][2] *= corr1; pv[f][3] *= corr1;
        }

        float rs0 = 0.f, rs1 = 0.f;
#pragma unroll
        for (int f = 0; f < 8; f++) {
            sf[f][0] = __expf(sf[f][0] - nm0);
            sf[f][1] = __expf(sf[f][1] - nm0);
            sf[f][2] = __expf(sf[f][2] - nm1);
            sf[f][3] = __expf(sf[f][3] - nm1);
            rs0 += sf[f][0] + sf[f][1];
            rs1 += sf[f][2] + sf[f][3];
        }
        rs0 += __shfl_xor_sync(0xffffffffu, rs0, 1);
        rs0 += __shfl_xor_sync(0xffffffffu, rs0, 2);
        rs1 += __shfl_xor_sync(0xffffffffu, rs1, 1);
        rs1 += __shfl_xor_sync(0xffffffffu, rs1, 2);
        lrow0 += rs0; lrow1 += rs1;

        // P (fp16 pack only) @ V
#pragma unroll
        for (int kg = 0; kg < 4; kg++) {
            uint32_t pa[4];
            pa[0] = hpack(sf[2 * kg][0],     sf[2 * kg][1]);
            pa[1] = hpack(sf[2 * kg][2],     sf[2 * kg][3]);
            pa[2] = hpack(sf[2 * kg + 1][0], sf[2 * kg + 1][1]);
            pa[3] = hpack(sf[2 * kg + 1][2], sf[2 * kg + 1][3]);
#pragma unroll
            for (int eg = 0; eg < 4; eg++) {
                uint32_t vh4[4];
                const uint32_t va = SV +
                    (kg * 16 + (((lane >> 3) & 1) << 3) + (lane & 7)) * AROW +
                    (eg << 5) + ((lane >> 4) << 4);
                ldm4t(vh4, va);
#pragma unroll
                for (int nn = 0; nn < 2; nn++)
                    mma16816(pv[eg * 2 + nn], pa, vh4[nn * 2], vh4[nn * 2 + 1]);
            }
        }
        __syncthreads();
    }

    const int srow0 = jb * 64 + wm + (lane >> 2);
    const int srow1 = srow0 + 8;
    const float sc0 = from_mask[b * Sn + srow0] / lrow0;
    const float sc1 = from_mask[b * Sn + srow1] / lrow1;
#pragma unroll
    for (int f = 0; f < 8; f++) {
        const int e = f * 8 + ((lane & 3) << 1);
        const size_t o0 = (size_t)(b * Sn + srow0) * Dn + h * 64 + e;
        const size_t o1 = (size_t)(b * Sn + srow1) * Dn + h * 64 + e;
        *(__half2*)&g_Chi[o0] = __floats2half2_rn(pv[f][0] * sc0, pv[f][1] * sc0);
        *(__half2*)&g_Chi[o1] = __floats2half2_rn(pv[f][2] * sc1, pv[f][3] * sc1);
    }
}

// ---------------------------------------------------------------------------
extern "C" void kernel_launch(void* const* d_in, const int* in_sizes, int n_in,
                              void* d_out, int out_size)
{
    const float* tokens    = (const float*)d_in[0];
    const float* band_mask = (const float*)d_in[1];
    const float* from_mask = (const float*)d_in[2];
    const float* to_mask   = (const float*)d_in[3];
    const float* Wq        = (const float*)d_in[4];
    const float* Wk        = (const float*)d_in[5];
    const float* Wv        = (const float*)d_in[6];
    const float* Wu        = (const float*)d_in[7];
    const float* bu        = (const float*)d_in[8];
    (void)in_sizes; (void)n_in; (void)out_size;

    __half *ahi, *bqh, *buh, *chi;
    cudaGetSymbolAddress((void**)&ahi, g_Ahi);
    cudaGetSymbolAddress((void**)&bqh, g_Bqkv_h);
    cudaGetSymbolAddress((void**)&buh, g_Bu_h);
    cudaGetSymbolAddress((void**)&chi, g_Chi);

    cudaFuncSetAttribute(attn_k, cudaFuncAttributeMaxDynamicSharedMemorySize, ATTN_SMEM);
    cudaFuncSetAttribute(hmma_gemm<0>, cudaFuncAttributeMaxDynamicSharedMemorySize, GEMM_SMEM);
    cudaFuncSetAttribute(hmma_gemm<1>, cudaFuncAttributeMaxDynamicSharedMemorySize, GEMM_SMEM);

    split_k<<<2048, 256>>>(tokens, ahi, Mrows * Dn / 4);
    packW_all<<<dim3(32, 32, 4), dim3(32, 8)>>>(Wq, Wk, Wv, Wu);

    hmma_gemm<1><<<dim3(24, 64), 256, GEMM_SMEM>>>(ahi, bqh, nullptr, nullptr);
    attn_k<<<Bn * Hn * NBn, 128, ATTN_SMEM>>>(to_mask, band_mask, from_mask);
    hmma_gemm<0><<<dim3(8, 64), 256, GEMM_SMEM>>>(chi, buh, bu, (float*)d_out);
}

// round 14
// speedup vs baseline: 1.9184x; 1.0288x over previous
#include <cuda_runtime.h>
#include <cuda_fp16.h>
#include <cstdint>

// ---------------------------------------------------------------------------
// BigBird transformer block on sm_103 (non-'a' target: no tcgen05/TMEM).
// R14: split-K for the global query blocks. R13 left attention bound by the
// 64-tile serial path of the 64 global-block CTAs (tensor only 23%).
// Each (jb<2, b, h) now runs as 8 CTAs x 8 key-tiles producing flash
// partials (pv, m, l) in scratch; attn_reduce merges 8 partials exactly.
// GEMMs unchanged (at the mma.sync rt=16 issue wall).
// ---------------------------------------------------------------------------

namespace {
constexpr int Bn    = 2;
constexpr int Sn    = 4096;
constexpr int Dn    = 1024;
constexpr int Hn    = 16;
constexpr int DHn   = 64;
constexpr int NBn   = 64;
constexpr int NGn   = 2;
constexpr int NMIDn = 60;
constexpr int Mrows = Bn * Sn;              // 8192

// GEMM tiling
constexpr int BK      = 32;
constexpr int NCHUNK  = Dn / BK;             // 32
constexpr int ROWB    = 80;
constexpr int MATB    = 128 * ROWB;          // 10240
constexpr int STG     = 2 * MATB;            // 20480 B / stage
constexpr int GEMM_SMEM = 3 * STG;           // 61440 B

// attention smem
constexpr int AROW    = 144;
constexpr int AMAT    = 64 * AROW;           // 9216 B
constexpr int ASTAGE  = 2 * AMAT;            // Kh, Vh = 18432 B
constexpr int AQ_BYTES = AMAT;               // Qh only
constexpr int ATTN_SMEM = AQ_BYTES + 2 * ASTAGE;  // 46080 B

// split-K for global blocks: 2 jb x 32 bh x 8 chunks = 512 partial CTAs
constexpr int NSPLIT  = 8;
constexpr int NPART   = 512;
constexpr int NGRID_A = NPART + (NBn - NGn) * 32;  // 512 + 1984 = 2496
}

// ---- scratch (device globals) ----------------------------------------------
__device__ __half g_qhi[Bn * Hn * Sn * DHn];
__device__ __half g_khi[Bn * Hn * Sn * DHn];
__device__ __half g_vhi[Bn * Hn * Sn * DHn];
__device__ __half g_Ahi[Mrows * Dn];
__device__ __half g_Bqkv_h[3 * Dn * Dn];
__device__ __half g_Bu_h[Dn * Dn];
__device__ __half g_Chi[Mrows * Dn];
__device__ float  g_pm[NPART * 64];
__device__ float  g_pl[NPART * 64];
__device__ float  g_ppv[(size_t)NPART * 64 * 64];   // 8.4 MB

// ---------------------------------------------------------------------------
// PTX helpers
// ---------------------------------------------------------------------------
__device__ __forceinline__ uint32_t smem_u32(const void* p) {
    uint32_t a;
    asm("{ .reg .u64 t; cvta.to.shared.u64 t, %1; cvt.u32.u64 %0, t; }" : "=r"(a) : "l"(p));
    return a;
}
__device__ __forceinline__ void cpa16(uint32_t dst, const void* src) {
    asm volatile("cp.async.cg.shared.global [%0], [%1], 16;" :: "r"(dst), "l"(src));
}
__device__ __forceinline__ void cpa_commit() {
    asm volatile("cp.async.commit_group;" ::: "memory");
}
template <int N>
__device__ __forceinline__ void cpa_wait() {
    asm volatile("cp.async.wait_group %0;" :: "n"(N) : "memory");
}
__device__ __forceinline__ void ldm4(uint32_t* r, uint32_t addr) {
    asm volatile("ldmatrix.sync.aligned.m8n8.x4.shared.b16 {%0,%1,%2,%3}, [%4];"
                 : "=r"(r[0]), "=r"(r[1]), "=r"(r[2]), "=r"(r[3]) : "r"(addr));
}
__device__ __forceinline__ void ldm4t(uint32_t* r, uint32_t addr) {
    asm volatile("ldmatrix.sync.aligned.m8n8.x4.trans.shared.b16 {%0,%1,%2,%3}, [%4];"
                 : "=r"(r[0]), "=r"(r[1]), "=r"(r[2]), "=r"(r[3]) : "r"(addr));
}
__device__ __forceinline__ void mma16816(float* c, const uint32_t* a,
                                         uint32_t b0, uint32_t b1) {
    asm volatile(
        "mma.sync.aligned.m16n8k16.row.col.f32.f16.f16.f32 "
        "{%0,%1,%2,%3}, {%4,%5,%6,%7}, {%8,%9}, {%0,%1,%2,%3};"
        : "+f"(c[0]), "+f"(c[1]), "+f"(c[2]), "+f"(c[3])
        : "r"(a[0]), "r"(a[1]), "r"(a[2]), "r"(a[3]), "r"(b0), "r"(b1));
}
__device__ __forceinline__ uint32_t hpack(float v0, float v1) {
    __half2 h = __floats2half2_rn(v0, v1);
    return *reinterpret_cast<uint32_t*>(&h);
}

// ---------------------------------------------------------------------------
// prep kernels
// ---------------------------------------------------------------------------
__global__ void split_k(const float* __restrict__ X,
                        __half* __restrict__ Hi, int n4)
{
    for (int i = blockIdx.x * blockDim.x + threadIdx.x; i < n4;
         i += gridDim.x * blockDim.x) {
        float4 v = ((const float4*)X)[i];
        *(__half2*)(Hi + 4 * i)     = __floats2half2_rn(v.x, v.y);
        *(__half2*)(Hi + 4 * i + 2) = __floats2half2_rn(v.z, v.w);
    }
}

__global__ void packW_all(const float* __restrict__ Wq, const float* __restrict__ Wk,
                          const float* __restrict__ Wv, const float* __restrict__ Wu)
{
    __shared__ float tile[32][33];
    const int z = blockIdx.z;
    const float* W = (z == 0) ? Wq : (z == 1) ? Wk : (z == 2) ? Wv : Wu;
    __half* Bh = (z < 3) ? g_Bqkv_h : g_Bu_h;
    const int nOff = (z < 3) ? z * 1024 : 0;

    const int tx = threadIdx.x, ty = threadIdx.y;
    const int n0 = blockIdx.x * 32, k0 = blockIdx.y * 32;
#pragma unroll
    for (int j = 0; j < 4; j++)
        tile[ty + j * 8][tx] = W[(size_t)(k0 + ty + j * 8) * Dn + n0 + tx];
    __syncthreads();
    const int kk = k0 + tx;
#pragma unroll
    for (int j = 0; j < 4; j++) {
        const int n = n0 + ty + j * 8;
        Bh[(size_t)(nOff + n) * Dn + kk] = __float2half_rn(tile[tx][ty + j * 8]);
    }
}

// ---------------------------------------------------------------------------
// fp16 HMMA GEMM, single product Ah.Bh, 3-stage pipeline, 2 CTAs/SM.
// ---------------------------------------------------------------------------
template <int MODE>
__global__ void __launch_bounds__(256, 2)
hmma_gemm(const __half* __restrict__ Ahi, const __half* __restrict__ Bh,
          const float* __restrict__ bias, float* __restrict__ Cout)
{
    extern __shared__ char smem[];
    const uint32_t sb = smem_u32(smem);
    const int t    = threadIdx.x;
    const int lane = t & 31;
    const int wid  = t >> 5;
    const int wm   = (wid & 1) << 6;
    const int wn   = (wid >> 1) << 5;
    const int m0   = blockIdx.y << 7;
    const int n0   = blockIdx.x << 7;

    auto load_stage = [&](int kc, int s) {
        const int kel = kc * BK;
        const uint32_t stb = sb + s * STG;
#pragma unroll
        for (int j = 0; j < 4; j++) {
            const int idx = t + (j << 8);
            const int mat = idx >> 9;
            const int rr  = (idx >> 2) & 127;
            const int cc  = idx & 3;
            const __half* src = mat
                ? Bh  + (size_t)(n0 + rr) * Dn + kel + (cc << 3)
                : Ahi + (size_t)(m0 + rr) * Dn + kel + (cc << 3);
            cpa16(stb + mat * MATB + rr * ROWB + (cc << 4), src);
        }
        cpa_commit();
    };

    float acc[4][4][4];
#pragma unroll
    for (int i = 0; i < 4; i++)
#pragma unroll
        for (int j = 0; j < 4; j++)
#pragma unroll
            for (int q = 0; q < 4; q++) acc[i][j][q] = 0.f;

    load_stage(0, 0);
    load_stage(1, 1);

    for (int kc = 0; kc < NCHUNK; ++kc) {
        if (kc + 2 < NCHUNK) { load_stage(kc + 2, (kc + 2) % 3); cpa_wait<2>(); }
        else if (kc + 1 < NCHUNK) cpa_wait<1>();
        else cpa_wait<0>();
        __syncthreads();
        const uint32_t stb = sb + (kc % 3) * STG;

#pragma unroll
        for (int k16 = 0; k16 < 2; k16++) {
            uint32_t ah[16];
            const uint32_t abase = stb + (wm + (lane & 15)) * ROWB +
                                   (k16 << 5) + ((lane >> 4) << 4);
#pragma unroll
            for (int mt = 0; mt < 4; mt++)
                ldm4(ah + 4 * mt, abase + mt * 16 * ROWB);
#pragma unroll
            for (int ng = 0; ng < 2; ng++) {
                uint32_t bh4[4];
                const uint32_t bbase = stb + MATB +
                                       (wn + ng * 16 + (lane & 15)) * ROWB +
                                       (k16 << 5) + ((lane >> 4) << 4);
                ldm4(bh4, bbase);
#pragma unroll
                for (int mt = 0; mt < 4; mt++) {
#pragma unroll
                    for (int nn = 0; nn < 2; nn++) {
                        mma16816(acc[mt][ng * 2 + nn], ah + 4 * mt,
                                 nn ? bh4[1] : bh4[0], nn ? bh4[3] : bh4[2]);
                    }
                }
            }
        }
        __syncthreads();
    }

    const int rbase = m0 + wm + (lane >> 2);
    const int cbase = (lane & 3) << 1;
#pragma unroll
    for (int mt = 0; mt < 4; mt++) {
#pragma unroll
        for (int nf = 0; nf < 4; nf++) {
            const int n = n0 + wn + ((nf >> 1) << 4) + ((nf & 1) << 3) + cbase;
            const float* c = acc[mt][nf];
#pragma unroll
            for (int half = 0; half < 2; half++) {
                const int r = rbase + mt * 16 + half * 8;
                float v0 = c[2 * half], v1 = c[2 * half + 1];
                if (MODE == 0) {
                    *(float2*)&Cout[(size_t)r * Dn + n] =
                        make_float2(v0 + bias[n], v1 + bias[n + 1]);
                } else {
                    const int mat = n >> 10;
                    const int nn  = n & 1023;
                    const int h   = nn >> 6;
                    const int e   = nn & 63;
                    const int b   = r >> 12;
                    const int s   = r & (Sn - 1);
                    const size_t off = ((size_t)(b * Hn + h) * Sn + s) * DHn + e;
                    if (mat == 0) { v0 *= 0.125f; v1 *= 0.125f; }
                    __half* arr = (mat == 0) ? g_qhi : (mat == 1) ? g_khi : g_vhi;
                    *(__half2*)&arr[off] = __floats2half2_rn(v0, v1);
                }
            }
        }
    }
}

// ---------------------------------------------------------------------------
// Flash attention, single product. Block types:
//   idx < 512 : partial for global blocks. idx = jb*256 + bh*8 + c;
//               processes key-tiles [c*8, c*8+8), writes (pv, m, l) scratch.
//   idx >= 512: mid/last blocks (jb >= 2) as before, 5 tiles, writes ctx.
// ---------------------------------------------------------------------------
__device__ __forceinline__ int kb_of(int jb, int kt, int& mtype, int& kc0) {
    mtype = 0; kc0 = 0;
    if (jb <= NGn) return kt * 64;
    if (jb == NBn - 1) return (kt < 2) ? kt * 64 : (Sn - 192 + (kt - 2) * 64);
    if (kt < 2) return kt * 64;
    mtype = 1; kc0 = (kt - 2) * 64;
    return (jb - 1) * 64 + (kt - 2) * 64;
}

__global__ void __launch_bounds__(128, 2)
attn_k(const float* __restrict__ to_mask,
       const float* __restrict__ band_mask,
       const float* __restrict__ from_mask)
{
    extern __shared__ char smem[];
    const uint32_t sb = smem_u32(smem);
    const int t = threadIdx.x, lane = t & 31, wid = t >> 5;
    const int idx = blockIdx.x;

    int jb, bh, kt0, ntiles;
    bool gmode;
    if (idx < NPART) {
        gmode = true;
        jb  = idx >> 8;            // 0 or 1
        bh  = (idx >> 3) & 31;
        kt0 = (idx & 7) * NSPLIT;  // 8 tiles per chunk
        ntiles = NSPLIT;
    } else {
        gmode = false;
        const int i2 = idx - NPART;
        jb  = (i2 >> 5) + NGn;     // 2..63
        bh  = i2 & 31;
        kt0 = 0;
        ntiles = 5;
    }
    const int b = bh >> 4, h = bh & 15;
    const int wm = wid << 4;

    const size_t hoff = (size_t)(b * Hn + h) * Sn * DHn;
    const __half* qhg = g_qhi + hoff + (size_t)jb * 64 * DHn;
    const __half* khg = g_khi + hoff;
    const __half* vhg = g_vhi + hoff;

    // Q tile: 64 rows x 8 chunks
#pragma unroll
    for (int j = 0; j < 4; j++) {
        const int i2 = t + (j << 7);
        const int rr  = (i2 >> 3) & 63;
        const int cc  = i2 & 7;
        cpa16(sb + rr * AROW + (cc << 4), qhg + rr * DHn + (cc << 3));
    }
    cpa_commit();

    auto loadKV = [&](int kb, int s) {
        const uint32_t base = sb + AQ_BYTES + s * ASTAGE;
#pragma unroll
        for (int j = 0; j < 8; j++) {
            const int i2 = t + (j << 7);
            const int mat = i2 >> 9;
            const int rr  = (i2 >> 3) & 63;
            const int cc  = i2 & 7;
            const __half* src = (mat ? vhg : khg) +
                (size_t)(kb + rr) * DHn + (cc << 3);
            cpa16(base + mat * AMAT + rr * AROW + (cc << 4), src);
        }
        cpa_commit();
    };

    int mty, kc0_;
    loadKV(kb_of(jb, kt0, mty, kc0_), 0);

    uint32_t qh[4][4];
    float pv[8][4];
#pragma unroll
    for (int f = 0; f < 8; f++)
#pragma unroll
        for (int q = 0; q < 4; q++) pv[f][q] = 0.f;
    float mrow0 = -1e30f, mrow1 = -1e30f, lrow0 = 0.f, lrow1 = 0.f;

    for (int kt = 0; kt < ntiles; ++kt) {
        if (kt + 1 < ntiles) {
            int mt2, kc2;
            loadKV(kb_of(jb, kt0 + kt + 1, mt2, kc2), (kt + 1) & 1);
            cpa_wait<1>();
        } else {
            cpa_wait<0>();
        }
        __syncthreads();

        if (kt == 0) {
            const uint32_t qbase = sb + (wm + (lane & 15)) * AROW + ((lane >> 4) << 4);
#pragma unroll
            for (int ks = 0; ks < 4; ks++)
                ldm4(qh[ks], qbase + (ks << 5));
        }

        int mtype, kcol0;
        const int kb = kb_of(jb, kt0 + kt, mtype, kcol0);
        const uint32_t SK = sb + AQ_BYTES + (kt & 1) * ASTAGE;
        const uint32_t SV = SK + AMAT;

        float sf[8][4];
#pragma unroll
        for (int f = 0; f < 8; f++)
#pragma unroll
            for (int q = 0; q < 4; q++) sf[f][q] = 0.f;
#pragma unroll
        for (int ks = 0; ks < 4; ks++) {
#pragma unroll
            for (int kg = 0; kg < 4; kg++) {
                uint32_t kh4[4];
                const uint32_t ka = SK + (kg * 16 + (lane & 15)) * AROW +
                                    (ks << 5) + ((lane >> 4) << 4);
                ldm4(kh4, ka);
#pragma unroll
                for (int nn = 0; nn < 2; nn++)
                    mma16816(sf[kg * 2 + nn], qh[ks],
                             nn ? kh4[1] : kh4[0], nn ? kh4[3] : kh4[2]);
            }
        }

        const int colb = (lane & 3) << 1;
        if (mtype == 0) {
#pragma unroll
            for (int f = 0; f < 8; f++) {
                const int key = kb + f * 8 + colb;
                const float p0 = (1.0f - to_mask[b * Sn + key]) * -10000.0f;
                const float p1 = (1.0f - to_mask[b * Sn + key + 1]) * -10000.0f;
                sf[f][0] += p0;
                sf[f][1] += p1;
                sf[f][2] += p0;
                sf[f][3] += p1;
            }
        } else {
            const int m_idx = jb - (NGn + 1);
            const int qi0 = wm + (lane >> 2);
            const float* bm0 = band_mask +
                ((size_t)(b * NMIDn + m_idx) * 64 + qi0) * 192 + kcol0 + colb;
#pragma unroll
            for (int f = 0; f < 8; f++) {
                sf[f][0] += (1.0f - bm0[f * 8]) * -10000.0f;
                sf[f][1] += (1.0f - bm0[f * 8 + 1]) * -10000.0f;
                sf[f][2] += (1.0f - bm0[8 * 192 + f * 8]) * -10000.0f;
                sf[f][3] += (1.0f - bm0[8 * 192 + f * 8 + 1]) * -10000.0f;
            }
        }

        float mx0 = -1e30f, mx1 = -1e30f;
#pragma unroll
        for (int f = 0; f < 8; f++) {
            mx0 = fmaxf(mx0, fmaxf(sf[f][0], sf[f][1]));
            mx1 = fmaxf(mx1, fmaxf(sf[f][2], sf[f][3]));
        }
        mx0 = fmaxf(mx0, __shfl_xor_sync(0xffffffffu, mx0, 1));
        mx0 = fmaxf(mx0, __shfl_xor_sync(0xffffffffu, mx0, 2));
        mx1 = fmaxf(mx1, __shfl_xor_sync(0xffffffffu, mx1, 1));
        mx1 = fmaxf(mx1, __shfl_xor_sync(0xffffffffu, mx1, 2));

        const float nm0 = fmaxf(mrow0, mx0), nm1 = fmaxf(mrow1, mx1);
        const float corr0 = __expf(mrow0 - nm0), corr1 = __expf(mrow1 - nm1);
        mrow0 = nm0; mrow1 = nm1;
        lrow0 *= corr0; lrow1 *= corr1;
#pragma unroll
        for (int f = 0; f < 8; f++) {
            pv[f][0] *= corr0; pv[f][1] *= corr0;
            pv[f][2] *= corr1; pv[f][3] *= corr1;
        }

        float rs0 = 0.f, rs1 = 0.f;
#pragma unroll
        for (int f = 0; f < 8; f++) {
            sf[f][0] = __expf(sf[f][0] - nm0);
            sf[f][1] = __expf(sf[f][1] - nm0);
            sf[f][2] = __expf(sf[f][2] - nm1);
            sf[f][3] = __expf(sf[f][3] - nm1);
            rs0 += sf[f][0] + sf[f][1];
            rs1 += sf[f][2] + sf[f][3];
        }
        rs0 += __shfl_xor_sync(0xffffffffu, rs0, 1);
        rs0 += __shfl_xor_sync(0xffffffffu, rs0, 2);
        rs1 += __shfl_xor_sync(0xffffffffu, rs1, 1);
        rs1 += __shfl_xor_sync(0xffffffffu, rs1, 2);
        lrow0 += rs0; lrow1 += rs1;

        // P (fp16) @ V
#pragma unroll
        for (int kg = 0; kg < 4; kg++) {
            uint32_t pa[4];
            pa[0] = hpack(sf[2 * kg][0],     sf[2 * kg][1]);
            pa[1] = hpack(sf[2 * kg][2],     sf[2 * kg][3]);
            pa[2] = hpack(sf[2 * kg + 1][0], sf[2 * kg + 1][1]);
            pa[3] = hpack(sf[2 * kg + 1][2], sf[2 * kg + 1][3]);
#pragma unroll
            for (int eg = 0; eg < 4; eg++) {
                uint32_t vh4[4];
                const uint32_t va = SV +
                    (kg * 16 + (((lane >> 3) & 1) << 3) + (lane & 7)) * AROW +
                    (eg << 5) + ((lane >> 4) << 4);
                ldm4t(vh4, va);
#pragma unroll
                for (int nn = 0; nn < 2; nn++)
                    mma16816(pv[eg * 2 + nn], pa, vh4[nn * 2], vh4[nn * 2 + 1]);
            }
        }
        __syncthreads();
    }

    const int r0 = wm + (lane >> 2);
    const int r1 = r0 + 8;
    if (gmode) {
        // write unnormalized partials to scratch
        if ((lane & 3) == 0) {
            g_pm[idx * 64 + r0] = mrow0;  g_pl[idx * 64 + r0] = lrow0;
            g_pm[idx * 64 + r1] = mrow1;  g_pl[idx * 64 + r1] = lrow1;
        }
#pragma unroll
        for (int f = 0; f < 8; f++) {
            const int e = f * 8 + ((lane & 3) << 1);
            *(float2*)&g_ppv[((size_t)idx * 64 + r0) * 64 + e] =
                make_float2(pv[f][0], pv[f][1]);
            *(float2*)&g_ppv[((size_t)idx * 64 + r1) * 64 + e] =
                make_float2(pv[f][2], pv[f][3]);
        }
    } else {
        const int srow0 = jb * 64 + r0;
        const int srow1 = jb * 64 + r1;
        const float sc0 = from_mask[b * Sn + srow0] / lrow0;
        const float sc1 = from_mask[b * Sn + srow1] / lrow1;
#pragma unroll
        for (int f = 0; f < 8; f++) {
            const int e = f * 8 + ((lane & 3) << 1);
            const size_t o0 = (size_t)(b * Sn + srow0) * Dn + h * 64 + e;
            const size_t o1 = (size_t)(b * Sn + srow1) * Dn + h * 64 + e;
            *(__half2*)&g_Chi[o0] = __floats2half2_rn(pv[f][0] * sc0, pv[f][1] * sc0);
            *(__half2*)&g_Chi[o1] = __floats2half2_rn(pv[f][2] * sc1, pv[f][3] * sc1);
        }
    }
}

// ---------------------------------------------------------------------------
// Reduce: merge 8 flash partials per (jb<2, b, h) and write ctx.
// 64 blocks x 256 threads; thread -> (row = t>>2, 16-col strip = (t&3)*16).
// ---------------------------------------------------------------------------
__global__ void __launch_bounds__(256)
attn_reduce(const float* __restrict__ from_mask)
{
    const int g  = blockIdx.x;        // 0..63
    const int jb = g >> 5, bh = g & 31;
    const int b  = bh >> 4, h = bh & 15;
    const int t  = threadIdx.x;
    const int row = t >> 2, q = t & 3;
    const int slot0 = jb * 256 + bh * 8;

    float m = -1e30f;
#pragma unroll
    for (int c = 0; c < NSPLIT; c++)
        m = fmaxf(m, g_pm[(slot0 + c) * 64 + row]);

    float l = 0.f;
    float acc[16];
#pragma unroll
    for (int i = 0; i < 16; i++) acc[i] = 0.f;

#pragma unroll
    for (int c = 0; c < NSPLIT; c++) {
        const int sl = slot0 + c;
        const float w = __expf(g_pm[sl * 64 + row] - m);
        l += g_pl[sl * 64 + row] * w;
        const float* pp = &g_ppv[((size_t)sl * 64 + row) * 64 + q * 16];
#pragma unroll
        for (int i = 0; i < 16; i += 4) {
            float4 v = *(const float4*)(pp + i);
            acc[i]     += v.x * w;
            acc[i + 1] += v.y * w;
            acc[i + 2] += v.z * w;
            acc[i + 3] += v.w * w;
        }
    }

    const int srow = jb * 64 + row;
    const float sc = from_mask[b * Sn + srow] / l;
    __half* dst = &g_Chi[(size_t)(b * Sn + srow) * Dn + h * 64 + q * 16];
#pragma unroll
    for (int i = 0; i < 16; i += 2)
        *(__half2*)(dst + i) = __floats2half2_rn(acc[i] * sc, acc[i + 1] * sc);
}

// ---------------------------------------------------------------------------
extern "C" void kernel_launch(void* const* d_in, const int* in_sizes, int n_in,
                              void* d_out, int out_size)
{
    const float* tokens    = (const float*)d_in[0];
    const float* band_mask = (const float*)d_in[1];
    const float* from_mask = (const float*)d_in[2];
    const float* to_mask   = (const float*)d_in[3];
    const float* Wq        = (const float*)d_in[4];
    const float* Wk        = (const float*)d_in[5];
    const float* Wv        = (const float*)d_in[6];
    const float* Wu        = (const float*)d_in[7];
    const float* bu        = (const float*)d_in[8];
    (void)in_sizes; (void)n_in; (void)out_size;

    __half *ahi, *bqh, *buh, *chi;
    cudaGetSymbolAddress((void**)&ahi, g_Ahi);
    cudaGetSymbolAddress((void**)&bqh, g_Bqkv_h);
    cudaGetSymbolAddress((void**)&buh, g_Bu_h);
    cudaGetSymbolAddress((void**)&chi, g_Chi);

    cudaFuncSetAttribute(attn_k, cudaFuncAttributeMaxDynamicSharedMemorySize, ATTN_SMEM);
    cudaFuncSetAttribute(hmma_gemm<0>, cudaFuncAttributeMaxDynamicSharedMemorySize, GEMM_SMEM);
    cudaFuncSetAttribute(hmma_gemm<1>, cudaFuncAttributeMaxDynamicSharedMemorySize, GEMM_SMEM);

    split_k<<<2048, 256>>>(tokens, ahi, Mrows * Dn / 4);
    packW_all<<<dim3(32, 32, 4), dim3(32, 8)>>>(Wq, Wk, Wv, Wu);

    hmma_gemm<1><<<dim3(24, 64), 256, GEMM_SMEM>>>(ahi, bqh, nullptr, nullptr);
    attn_k<<<NGRID_A, 128, ATTN_SMEM>>>(to_mask, band_mask, from_mask);
    attn_reduce<<<64, 256>>>(from_mask);
    hmma_gemm<0><<<dim3(8, 64), 256, GEMM_SMEM>>>(chi, buh, bu, (float*)d_out);
}

// round 15
// speedup vs baseline: 1.9287x; 1.0054x over previous
#include <cuda_runtime.h>
#include <cuda_fp16.h>
#include <cstdint>

// ---------------------------------------------------------------------------
// BigBird transformer block on sm_103 (non-'a' target: no tcgen05/TMEM).
// R15: attention occupancy 2->3 CTAs/SM (L1-bound at occ 17.7% in R14) and
// fp16 split-K partials (halves scratch traffic). Everything else as R14:
// single-product fp16 HMMA GEMMs (at the mma.sync rt=16 issue wall),
// single-product attention with 8-way split-K on global query blocks.
// ---------------------------------------------------------------------------

namespace {
constexpr int Bn    = 2;
constexpr int Sn    = 4096;
constexpr int Dn    = 1024;
constexpr int Hn    = 16;
constexpr int DHn   = 64;
constexpr int NBn   = 64;
constexpr int NGn   = 2;
constexpr int NMIDn = 60;
constexpr int Mrows = Bn * Sn;              // 8192

// GEMM tiling
constexpr int BK      = 32;
constexpr int NCHUNK  = Dn / BK;             // 32
constexpr int ROWB    = 80;
constexpr int MATB    = 128 * ROWB;          // 10240
constexpr int STG     = 2 * MATB;            // 20480 B / stage
constexpr int GEMM_SMEM = 3 * STG;           // 61440 B

// attention smem
constexpr int AROW    = 144;
constexpr int AMAT    = 64 * AROW;           // 9216 B
constexpr int ASTAGE  = 2 * AMAT;            // Kh, Vh = 18432 B
constexpr int AQ_BYTES = AMAT;               // Qh only
constexpr int ATTN_SMEM = AQ_BYTES + 2 * ASTAGE;  // 46080 B

// split-K for global blocks
constexpr int NSPLIT  = 8;
constexpr int NPART   = 512;
constexpr int NGRID_A = NPART + (NBn - NGn) * 32;  // 2496
}

// ---- scratch (device globals) ----------------------------------------------
__device__ __half g_qhi[Bn * Hn * Sn * DHn];
__device__ __half g_khi[Bn * Hn * Sn * DHn];
__device__ __half g_vhi[Bn * Hn * Sn * DHn];
__device__ __half g_Ahi[Mrows * Dn];
__device__ __half g_Bqkv_h[3 * Dn * Dn];
__device__ __half g_Bu_h[Dn * Dn];
__device__ __half g_Chi[Mrows * Dn];
__device__ float  g_pm[NPART * 64];
__device__ float  g_pl[NPART * 64];
__device__ __half g_ppv[(size_t)NPART * 64 * 64];   // 4.2 MB fp16 partials

// ---------------------------------------------------------------------------
// PTX helpers
// ---------------------------------------------------------------------------
__device__ __forceinline__ uint32_t smem_u32(const void* p) {
    uint32_t a;
    asm("{ .reg .u64 t; cvta.to.shared.u64 t, %1; cvt.u32.u64 %0, t; }" : "=r"(a) : "l"(p));
    return a;
}
__device__ __forceinline__ void cpa16(uint32_t dst, const void* src) {
    asm volatile("cp.async.cg.shared.global [%0], [%1], 16;" :: "r"(dst), "l"(src));
}
__device__ __forceinline__ void cpa_commit() {
    asm volatile("cp.async.commit_group;" ::: "memory");
}
template <int N>
__device__ __forceinline__ void cpa_wait() {
    asm volatile("cp.async.wait_group %0;" :: "n"(N) : "memory");
}
__device__ __forceinline__ void ldm4(uint32_t* r, uint32_t addr) {
    asm volatile("ldmatrix.sync.aligned.m8n8.x4.shared.b16 {%0,%1,%2,%3}, [%4];"
                 : "=r"(r[0]), "=r"(r[1]), "=r"(r[2]), "=r"(r[3]) : "r"(addr));
}
__device__ __forceinline__ void ldm4t(uint32_t* r, uint32_t addr) {
    asm volatile("ldmatrix.sync.aligned.m8n8.x4.trans.shared.b16 {%0,%1,%2,%3}, [%4];"
                 : "=r"(r[0]), "=r"(r[1]), "=r"(r[2]), "=r"(r[3]) : "r"(addr));
}
__device__ __forceinline__ void mma16816(float* c, const uint32_t* a,
                                         uint32_t b0, uint32_t b1) {
    asm volatile(
        "mma.sync.aligned.m16n8k16.row.col.f32.f16.f16.f32 "
        "{%0,%1,%2,%3}, {%4,%5,%6,%7}, {%8,%9}, {%0,%1,%2,%3};"
        : "+f"(c[0]), "+f"(c[1]), "+f"(c[2]), "+f"(c[3])
        : "r"(a[0]), "r"(a[1]), "r"(a[2]), "r"(a[3]), "r"(b0), "r"(b1));
}
__device__ __forceinline__ uint32_t hpack(float v0, float v1) {
    __half2 h = __floats2half2_rn(v0, v1);
    return *reinterpret_cast<uint32_t*>(&h);
}

// ---------------------------------------------------------------------------
// prep kernels
// ---------------------------------------------------------------------------
__global__ void split_k(const float* __restrict__ X,
                        __half* __restrict__ Hi, int n4)
{
    for (int i = blockIdx.x * blockDim.x + threadIdx.x; i < n4;
         i += gridDim.x * blockDim.x) {
        float4 v = ((const float4*)X)[i];
        *(__half2*)(Hi + 4 * i)     = __floats2half2_rn(v.x, v.y);
        *(__half2*)(Hi + 4 * i + 2) = __floats2half2_rn(v.z, v.w);
    }
}

__global__ void packW_all(const float* __restrict__ Wq, const float* __restrict__ Wk,
                          const float* __restrict__ Wv, const float* __restrict__ Wu)
{
    __shared__ float tile[32][33];
    const int z = blockIdx.z;
    const float* W = (z == 0) ? Wq : (z == 1) ? Wk : (z == 2) ? Wv : Wu;
    __half* Bh = (z < 3) ? g_Bqkv_h : g_Bu_h;
    const int nOff = (z < 3) ? z * 1024 : 0;

    const int tx = threadIdx.x, ty = threadIdx.y;
    const int n0 = blockIdx.x * 32, k0 = blockIdx.y * 32;
#pragma unroll
    for (int j = 0; j < 4; j++)
        tile[ty + j * 8][tx] = W[(size_t)(k0 + ty + j * 8) * Dn + n0 + tx];
    __syncthreads();
    const int kk = k0 + tx;
#pragma unroll
    for (int j = 0; j < 4; j++) {
        const int n = n0 + ty + j * 8;
        Bh[(size_t)(nOff + n) * Dn + kk] = __float2half_rn(tile[tx][ty + j * 8]);
    }
}

// ---------------------------------------------------------------------------
// fp16 HMMA GEMM, single product Ah.Bh, 3-stage pipeline, 2 CTAs/SM.
// ---------------------------------------------------------------------------
template <int MODE>
__global__ void __launch_bounds__(256, 2)
hmma_gemm(const __half* __restrict__ Ahi, const __half* __restrict__ Bh,
          const float* __restrict__ bias, float* __restrict__ Cout)
{
    extern __shared__ char smem[];
    const uint32_t sb = smem_u32(smem);
    const int t    = threadIdx.x;
    const int lane = t & 31;
    const int wid  = t >> 5;
    const int wm   = (wid & 1) << 6;
    const int wn   = (wid >> 1) << 5;
    const int m0   = blockIdx.y << 7;
    const int n0   = blockIdx.x << 7;

    auto load_stage = [&](int kc, int s) {
        const int kel = kc * BK;
        const uint32_t stb = sb + s * STG;
#pragma unroll
        for (int j = 0; j < 4; j++) {
            const int idx = t + (j << 8);
            const int mat = idx >> 9;
            const int rr  = (idx >> 2) & 127;
            const int cc  = idx & 3;
            const __half* src = mat
                ? Bh  + (size_t)(n0 + rr) * Dn + kel + (cc << 3)
                : Ahi + (size_t)(m0 + rr) * Dn + kel + (cc << 3);
            cpa16(stb + mat * MATB + rr * ROWB + (cc << 4), src);
        }
        cpa_commit();
    };

    float acc[4][4][4];
#pragma unroll
    for (int i = 0; i < 4; i++)
#pragma unroll
        for (int j = 0; j < 4; j++)
#pragma unroll
            for (int q = 0; q < 4; q++) acc[i][j][q] = 0.f;

    load_stage(0, 0);
    load_stage(1, 1);

    for (int kc = 0; kc < NCHUNK; ++kc) {
        if (kc + 2 < NCHUNK) { load_stage(kc + 2, (kc + 2) % 3); cpa_wait<2>(); }
        else if (kc + 1 < NCHUNK) cpa_wait<1>();
        else cpa_wait<0>();
        __syncthreads();
        const uint32_t stb = sb + (kc % 3) * STG;

#pragma unroll
        for (int k16 = 0; k16 < 2; k16++) {
            uint32_t ah[16];
            const uint32_t abase = stb + (wm + (lane & 15)) * ROWB +
                                   (k16 << 5) + ((lane >> 4) << 4);
#pragma unroll
            for (int mt = 0; mt < 4; mt++)
                ldm4(ah + 4 * mt, abase + mt * 16 * ROWB);
#pragma unroll
            for (int ng = 0; ng < 2; ng++) {
                uint32_t bh4[4];
                const uint32_t bbase = stb + MATB +
                                       (wn + ng * 16 + (lane & 15)) * ROWB +
                                       (k16 << 5) + ((lane >> 4) << 4);
                ldm4(bh4, bbase);
#pragma unroll
                for (int mt = 0; mt < 4; mt++) {
#pragma unroll
                    for (int nn = 0; nn < 2; nn++) {
                        mma16816(acc[mt][ng * 2 + nn], ah + 4 * mt,
                                 nn ? bh4[1] : bh4[0], nn ? bh4[3] : bh4[2]);
                    }
                }
            }
        }
        __syncthreads();
    }

    const int rbase = m0 + wm + (lane >> 2);
    const int cbase = (lane & 3) << 1;
#pragma unroll
    for (int mt = 0; mt < 4; mt++) {
#pragma unroll
        for (int nf = 0; nf < 4; nf++) {
            const int n = n0 + wn + ((nf >> 1) << 4) + ((nf & 1) << 3) + cbase;
            const float* c = acc[mt][nf];
#pragma unroll
            for (int half = 0; half < 2; half++) {
                const int r = rbase + mt * 16 + half * 8;
                float v0 = c[2 * half], v1 = c[2 * half + 1];
                if (MODE == 0) {
                    *(float2*)&Cout[(size_t)r * Dn + n] =
                        make_float2(v0 + bias[n], v1 + bias[n + 1]);
                } else {
                    const int mat = n >> 10;
                    const int nn  = n & 1023;
                    const int h   = nn >> 6;
                    const int e   = nn & 63;
                    const int b   = r >> 12;
                    const int s   = r & (Sn - 1);
                    const size_t off = ((size_t)(b * Hn + h) * Sn + s) * DHn + e;
                    if (mat == 0) { v0 *= 0.125f; v1 *= 0.125f; }
                    __half* arr = (mat == 0) ? g_qhi : (mat == 1) ? g_khi : g_vhi;
                    *(__half2*)&arr[off] = __floats2half2_rn(v0, v1);
                }
            }
        }
    }
}

// ---------------------------------------------------------------------------
// Flash attention, single product, split-K on global blocks (R14 layout).
// ---------------------------------------------------------------------------
__device__ __forceinline__ int kb_of(int jb, int kt, int& mtype, int& kc0) {
    mtype = 0; kc0 = 0;
    if (jb <= NGn) return kt * 64;
    if (jb == NBn - 1) return (kt < 2) ? kt * 64 : (Sn - 192 + (kt - 2) * 64);
    if (kt < 2) return kt * 64;
    mtype = 1; kc0 = (kt - 2) * 64;
    return (jb - 1) * 64 + (kt - 2) * 64;
}

__global__ void __launch_bounds__(128, 3)
attn_k(const float* __restrict__ to_mask,
       const float* __restrict__ band_mask,
       const float* __restrict__ from_mask)
{
    extern __shared__ char smem[];
    const uint32_t sb = smem_u32(smem);
    const int t = threadIdx.x, lane = t & 31, wid = t >> 5;
    const int idx = blockIdx.x;

    int jb, bh, kt0, ntiles;
    bool gmode;
    if (idx < NPART) {
        gmode = true;
        jb  = idx >> 8;
        bh  = (idx >> 3) & 31;
        kt0 = (idx & 7) * NSPLIT;
        ntiles = NSPLIT;
    } else {
        gmode = false;
        const int i2 = idx - NPART;
        jb  = (i2 >> 5) + NGn;
        bh  = i2 & 31;
        kt0 = 0;
        ntiles = 5;
    }
    const int b = bh >> 4, h = bh & 15;
    const int wm = wid << 4;

    const size_t hoff = (size_t)(b * Hn + h) * Sn * DHn;
    const __half* qhg = g_qhi + hoff + (size_t)jb * 64 * DHn;
    const __half* khg = g_khi + hoff;
    const __half* vhg = g_vhi + hoff;

#pragma unroll
    for (int j = 0; j < 4; j++) {
        const int i2 = t + (j << 7);
        const int rr  = (i2 >> 3) & 63;
        const int cc  = i2 & 7;
        cpa16(sb + rr * AROW + (cc << 4), qhg + rr * DHn + (cc << 3));
    }
    cpa_commit();

    auto loadKV = [&](int kb, int s) {
        const uint32_t base = sb + AQ_BYTES + s * ASTAGE;
#pragma unroll
        for (int j = 0; j < 8; j++) {
            const int i2 = t + (j << 7);
            const int mat = i2 >> 9;
            const int rr  = (i2 >> 3) & 63;
            const int cc  = i2 & 7;
            const __half* src = (mat ? vhg : khg) +
                (size_t)(kb + rr) * DHn + (cc << 3);
            cpa16(base + mat * AMAT + rr * AROW + (cc << 4), src);
        }
        cpa_commit();
    };

    int mty, kc0_;
    loadKV(kb_of(jb, kt0, mty, kc0_), 0);

    uint32_t qh[4][4];
    float pv[8][4];
#pragma unroll
    for (int f = 0; f < 8; f++)
#pragma unroll
        for (int q = 0; q < 4; q++) pv[f][q] = 0.f;
    float mrow0 = -1e30f, mrow1 = -1e30f, lrow0 = 0.f, lrow1 = 0.f;

    for (int kt = 0; kt < ntiles; ++kt) {
        if (kt + 1 < ntiles) {
            int mt2, kc2;
            loadKV(kb_of(jb, kt0 + kt + 1, mt2, kc2), (kt + 1) & 1);
            cpa_wait<1>();
        } else {
            cpa_wait<0>();
        }
        __syncthreads();

        if (kt == 0) {
            const uint32_t qbase = sb + (wm + (lane & 15)) * AROW + ((lane >> 4) << 4);
#pragma unroll
            for (int ks = 0; ks < 4; ks++)
                ldm4(qh[ks], qbase + (ks << 5));
        }

        int mtype, kcol0;
        const int kb = kb_of(jb, kt0 + kt, mtype, kcol0);
        const uint32_t SK = sb + AQ_BYTES + (kt & 1) * ASTAGE;
        const uint32_t SV = SK + AMAT;

        float sf[8][4];
#pragma unroll
        for (int f = 0; f < 8; f++)
#pragma unroll
            for (int q = 0; q < 4; q++) sf[f][q] = 0.f;
#pragma unroll
        for (int ks = 0; ks < 4; ks++) {
#pragma unroll
            for (int kg = 0; kg < 4; kg++) {
                uint32_t kh4[4];
                const uint32_t ka = SK + (kg * 16 + (lane & 15)) * AROW +
                                    (ks << 5) + ((lane >> 4) << 4);
                ldm4(kh4, ka);
#pragma unroll
                for (int nn = 0; nn < 2; nn++)
                    mma16816(sf[kg * 2 + nn], qh[ks],
                             nn ? kh4[1] : kh4[0], nn ? kh4[3] : kh4[2]);
            }
        }

        const int colb = (lane & 3) << 1;
        if (mtype == 0) {
#pragma unroll
            for (int f = 0; f < 8; f++) {
                const int key = kb + f * 8 + colb;
                const float p0 = (1.0f - to_mask[b * Sn + key]) * -10000.0f;
                const float p1 = (1.0f - to_mask[b * Sn + key + 1]) * -10000.0f;
                sf[f][0] += p0;
                sf[f][1] += p1;
                sf[f][2] += p0;
                sf[f][3] += p1;
            }
        } else {
            const int m_idx = jb - (NGn + 1);
            const int qi0 = wm + (lane >> 2);
            const float* bm0 = band_mask +
                ((size_t)(b * NMIDn + m_idx) * 64 + qi0) * 192 + kcol0 + colb;
#pragma unroll
            for (int f = 0; f < 8; f++) {
                sf[f][0] += (1.0f - bm0[f * 8]) * -10000.0f;
                sf[f][1] += (1.0f - bm0[f * 8 + 1]) * -10000.0f;
                sf[f][2] += (1.0f - bm0[8 * 192 + f * 8]) * -10000.0f;
                sf[f][3] += (1.0f - bm0[8 * 192 + f * 8 + 1]) * -10000.0f;
            }
        }

        float mx0 = -1e30f, mx1 = -1e30f;
#pragma unroll
        for (int f = 0; f < 8; f++) {
            mx0 = fmaxf(mx0, fmaxf(sf[f][0], sf[f][1]));
            mx1 = fmaxf(mx1, fmaxf(sf[f][2], sf[f][3]));
        }
        mx0 = fmaxf(mx0, __shfl_xor_sync(0xffffffffu, mx0, 1));
        mx0 = fmaxf(mx0, __shfl_xor_sync(0xffffffffu, mx0, 2));
        mx1 = fmaxf(mx1, __shfl_xor_sync(0xffffffffu, mx1, 1));
        mx1 = fmaxf(mx1, __shfl_xor_sync(0xffffffffu, mx1, 2));

        const float nm0 = fmaxf(mrow0, mx0), nm1 = fmaxf(mrow1, mx1);
        const float corr0 = __expf(mrow0 - nm0), corr1 = __expf(mrow1 - nm1);
        mrow0 = nm0; mrow1 = nm1;
        lrow0 *= corr0; lrow1 *= corr1;
#pragma unroll
        for (int f = 0; f < 8; f++) {
            pv[f][0] *= corr0; pv[f][1] *= corr0;
            pv[f][2] *= corr1; pv[f][3] *= corr1;
        }

        float rs0 = 0.f, rs1 = 0.f;
#pragma unroll
        for (int f = 0; f < 8; f++) {
            sf[f][0] = __expf(sf[f][0] - nm0);
            sf[f][1] = __expf(sf[f][1] - nm0);
            sf[f][2] = __expf(sf[f][2] - nm1);
            sf[f][3] = __expf(sf[f][3] - nm1);
            rs0 += sf[f][0] + sf[f][1];
            rs1 += sf[f][2] + sf[f][3];
        }
        rs0 += __shfl_xor_sync(0xffffffffu, rs0, 1);
        rs0 += __shfl_xor_sync(0xffffffffu, rs0, 2);
        rs1 += __shfl_xor_sync(0xffffffffu, rs1, 1);
        rs1 += __shfl_xor_sync(0xffffffffu, rs1, 2);
        lrow0 += rs0; lrow1 += rs1;

#pragma unroll
        for (int kg = 0; kg < 4; kg++) {
            uint32_t pa[4];
            pa[0] = hpack(sf[2 * kg][0],     sf[2 * kg][1]);
            pa[1] = hpack(sf[2 * kg][2],     sf[2 * kg][3]);
            pa[2] = hpack(sf[2 * kg + 1][0], sf[2 * kg + 1][1]);
            pa[3] = hpack(sf[2 * kg + 1][2], sf[2 * kg + 1][3]);
#pragma unroll
            for (int eg = 0; eg < 4; eg++) {
                uint32_t vh4[4];
                const uint32_t va = SV +
                    (kg * 16 + (((lane >> 3) & 1) << 3) + (lane & 7)) * AROW +
                    (eg << 5) + ((lane >> 4) << 4);
                ldm4t(vh4, va);
#pragma unroll
                for (int nn = 0; nn < 2; nn++)
                    mma16816(pv[eg * 2 + nn], pa, vh4[nn * 2], vh4[nn * 2 + 1]);
            }
        }
        __syncthreads();
    }

    const int r0 = wm + (lane >> 2);
    const int r1 = r0 + 8;
    if (gmode) {
        if ((lane & 3) == 0) {
            g_pm[idx * 64 + r0] = mrow0;  g_pl[idx * 64 + r0] = lrow0;
            g_pm[idx * 64 + r1] = mrow1;  g_pl[idx * 64 + r1] = lrow1;
        }
#pragma unroll
        for (int f = 0; f < 8; f++) {
            const int e = f * 8 + ((lane & 3) << 1);
            *(__half2*)&g_ppv[((size_t)idx * 64 + r0) * 64 + e] =
                __floats2half2_rn(pv[f][0], pv[f][1]);
            *(__half2*)&g_ppv[((size_t)idx * 64 + r1) * 64 + e] =
                __floats2half2_rn(pv[f][2], pv[f][3]);
        }
    } else {
        const int srow0 = jb * 64 + r0;
        const int srow1 = jb * 64 + r1;
        const float sc0 = from_mask[b * Sn + srow0] / lrow0;
        const float sc1 = from_mask[b * Sn + srow1] / lrow1;
#pragma unroll
        for (int f = 0; f < 8; f++) {
            const int e = f * 8 + ((lane & 3) << 1);
            const size_t o0 = (size_t)(b * Sn + srow0) * Dn + h * 64 + e;
            const size_t o1 = (size_t)(b * Sn + srow1) * Dn + h * 64 + e;
            *(__half2*)&g_Chi[o0] = __floats2half2_rn(pv[f][0] * sc0, pv[f][1] * sc0);
            *(__half2*)&g_Chi[o1] = __floats2half2_rn(pv[f][2] * sc1, pv[f][3] * sc1);
        }
    }
}

// ---------------------------------------------------------------------------
// Reduce: merge 8 fp16 flash partials per (jb<2, b, h), write ctx.
// ---------------------------------------------------------------------------
__global__ void __launch_bounds__(256)
attn_reduce(const float* __restrict__ from_mask)
{
    const int g  = blockIdx.x;        // 0..63
    const int jb = g >> 5, bh = g & 31;
    const int b  = bh >> 4, h = bh & 15;
    const int t  = threadIdx.x;
    const int row = t >> 2, q = t & 3;
    const int slot0 = jb * 256 + bh * 8;

    float m = -1e30f;
#pragma unroll
    for (int c = 0; c < NSPLIT; c++)
        m = fmaxf(m, g_pm[(slot0 + c) * 64 + row]);

    float l = 0.f;
    float acc[16];
#pragma unroll
    for (int i = 0; i < 16; i++) acc[i] = 0.f;

#pragma unroll
    for (int c = 0; c < NSPLIT; c++) {
        const int sl = slot0 + c;
        const float w = __expf(g_pm[sl * 64 + row] - m);
        l += g_pl[sl * 64 + row] * w;
        const __half* pp = &g_ppv[((size_t)sl * 64 + row) * 64 + q * 16];
#pragma unroll
        for (int i = 0; i < 16; i += 2) {
            const __half2 v = *(const __half2*)(pp + i);
            acc[i]     += __low2float(v)  * w;
            acc[i + 1] += __high2float(v) * w;
        }
    }

    const int srow = jb * 64 + row;
    const float sc = from_mask[b * Sn + srow] / l;
    __half* dst = &g_Chi[(size_t)(b * Sn + srow) * Dn + h * 64 + q * 16];
#pragma unroll
    for (int i = 0; i < 16; i += 2)
        *(__half2*)(dst + i) = __floats2half2_rn(acc[i] * sc, acc[i + 1] * sc);
}

// ---------------------------------------------------------------------------
extern "C" void kernel_launch(void* const* d_in, const int* in_sizes, int n_in,
                              void* d_out, int out_size)
{
    const float* tokens    = (const float*)d_in[0];
    const float* band_mask = (const float*)d_in[1];
    const float* from_mask = (const float*)d_in[2];
    const float* to_mask   = (const float*)d_in[3];
    const float* Wq        = (const float*)d_in[4];
    const float* Wk        = (const float*)d_in[5];
    const float* Wv        = (const float*)d_in[6];
    const float* Wu        = (const float*)d_in[7];
    const float* bu        = (const float*)d_in[8];
    (void)in_sizes; (void)n_in; (void)out_size;

    __half *ahi, *bqh, *buh, *chi;
    cudaGetSymbolAddress((void**)&ahi, g_Ahi);
    cudaGetSymbolAddress((void**)&bqh, g_Bqkv_h);
    cudaGetSymbolAddress((void**)&buh, g_Bu_h);
    cudaGetSymbolAddress((void**)&chi, g_Chi);

    cudaFuncSetAttribute(attn_k, cudaFuncAttributeMaxDynamicSharedMemorySize, ATTN_SMEM);
    cudaFuncSetAttribute(hmma_gemm<0>, cudaFuncAttributeMaxDynamicSharedMemorySize, GEMM_SMEM);
    cudaFuncSetAttribute(hmma_gemm<1>, cudaFuncAttributeMaxDynamicSharedMemorySize, GEMM_SMEM);

    split_k<<<2048, 256>>>(tokens, ahi, Mrows * Dn / 4);
    packW_all<<<dim3(32, 32, 4), dim3(32, 8)>>>(Wq, Wk, Wv, Wu);

    hmma_gemm<1><<<dim3(24, 64), 256, GEMM_SMEM>>>(ahi, bqh, nullptr, nullptr);
    attn_k<<<NGRID_A, 128, ATTN_SMEM>>>(to_mask, band_mask, from_mask);
    attn_reduce<<<64, 256>>>(from_mask);
    hmma_gemm<0><<<dim3(8, 64), 256, GEMM_SMEM>>>(chi, buh, bu, (float*)d_out);
}

// round 16
// speedup vs baseline: 1.9506x; 1.0113x over previous
#include <cuda_runtime.h>
#include <cuda_fp16.h>
#include <cstdint>

// ---------------------------------------------------------------------------
// BigBird transformer block on sm_103 (non-'a' target: no tcgen05/TMEM).
// R16: mask penalties precomputed to fp16 arrays (pen = (1-mask)*-1e4).
// Attention mask step: scalar fp32 LDG + FFMA chain -> half2 loads + add
// (2-4x fewer loads on the per-tile critical path). Rest as R15:
// single-product fp16 HMMA GEMMs + split-K single-product attention.
// ---------------------------------------------------------------------------

namespace {
constexpr int Bn    = 2;
constexpr int Sn    = 4096;
constexpr int Dn    = 1024;
constexpr int Hn    = 16;
constexpr int DHn   = 64;
constexpr int NBn   = 64;
constexpr int NGn   = 2;
constexpr int NMIDn = 60;
constexpr int Mrows = Bn * Sn;              // 8192

// GEMM tiling
constexpr int BK      = 32;
constexpr int NCHUNK  = Dn / BK;             // 32
constexpr int ROWB    = 80;
constexpr int MATB    = 128 * ROWB;          // 10240
constexpr int STG     = 2 * MATB;            // 20480 B / stage
constexpr int GEMM_SMEM = 3 * STG;           // 61440 B

// attention smem
constexpr int AROW    = 144;
constexpr int AMAT    = 64 * AROW;           // 9216 B
constexpr int ASTAGE  = 2 * AMAT;            // Kh, Vh = 18432 B
constexpr int AQ_BYTES = AMAT;               // Qh only
constexpr int ATTN_SMEM = AQ_BYTES + 2 * ASTAGE;  // 46080 B

// split-K for global blocks
constexpr int NSPLIT  = 8;
constexpr int NPART   = 512;
constexpr int NGRID_A = NPART + (NBn - NGn) * 32;  // 2496

constexpr int BANDSZ  = Bn * NMIDn * 64 * 192;     // 1474560
}

// ---- scratch (device globals) ----------------------------------------------
__device__ __half g_qhi[Bn * Hn * Sn * DHn];
__device__ __half g_khi[Bn * Hn * Sn * DHn];
__device__ __half g_vhi[Bn * Hn * Sn * DHn];
__device__ __half g_Ahi[Mrows * Dn];
__device__ __half g_Bqkv_h[3 * Dn * Dn];
__device__ __half g_Bu_h[Dn * Dn];
__device__ __half g_Chi[Mrows * Dn];
__device__ float  g_pm[NPART * 64];
__device__ float  g_pl[NPART * 64];
__device__ __half g_ppv[(size_t)NPART * 64 * 64];
__device__ __half g_pen_to[Bn * Sn];
__device__ __half g_pen_band[BANDSZ];

// ---------------------------------------------------------------------------
// PTX helpers
// ---------------------------------------------------------------------------
__device__ __forceinline__ uint32_t smem_u32(const void* p) {
    uint32_t a;
    asm("{ .reg .u64 t; cvta.to.shared.u64 t, %1; cvt.u32.u64 %0, t; }" : "=r"(a) : "l"(p));
    return a;
}
__device__ __forceinline__ void cpa16(uint32_t dst, const void* src) {
    asm volatile("cp.async.cg.shared.global [%0], [%1], 16;" :: "r"(dst), "l"(src));
}
__device__ __forceinline__ void cpa_commit() {
    asm volatile("cp.async.commit_group;" ::: "memory");
}
template <int N>
__device__ __forceinline__ void cpa_wait() {
    asm volatile("cp.async.wait_group %0;" :: "n"(N) : "memory");
}
__device__ __forceinline__ void ldm4(uint32_t* r, uint32_t addr) {
    asm volatile("ldmatrix.sync.aligned.m8n8.x4.shared.b16 {%0,%1,%2,%3}, [%4];"
                 : "=r"(r[0]), "=r"(r[1]), "=r"(r[2]), "=r"(r[3]) : "r"(addr));
}
__device__ __forceinline__ void ldm4t(uint32_t* r, uint32_t addr) {
    asm volatile("ldmatrix.sync.aligned.m8n8.x4.trans.shared.b16 {%0,%1,%2,%3}, [%4];"
                 : "=r"(r[0]), "=r"(r[1]), "=r"(r[2]), "=r"(r[3]) : "r"(addr));
}
__device__ __forceinline__ void mma16816(float* c, const uint32_t* a,
                                         uint32_t b0, uint32_t b1) {
    asm volatile(
        "mma.sync.aligned.m16n8k16.row.col.f32.f16.f16.f32 "
        "{%0,%1,%2,%3}, {%4,%5,%6,%7}, {%8,%9}, {%0,%1,%2,%3};"
        : "+f"(c[0]), "+f"(c[1]), "+f"(c[2]), "+f"(c[3])
        : "r"(a[0]), "r"(a[1]), "r"(a[2]), "r"(a[3]), "r"(b0), "r"(b1));
}
__device__ __forceinline__ uint32_t hpack(float v0, float v1) {
    __half2 h = __floats2half2_rn(v0, v1);
    return *reinterpret_cast<uint32_t*>(&h);
}

// ---------------------------------------------------------------------------
// prep kernels
// ---------------------------------------------------------------------------
__global__ void split_k(const float* __restrict__ X,
                        __half* __restrict__ Hi, int n4)
{
    for (int i = blockIdx.x * blockDim.x + threadIdx.x; i < n4;
         i += gridDim.x * blockDim.x) {
        float4 v = ((const float4*)X)[i];
        *(__half2*)(Hi + 4 * i)     = __floats2half2_rn(v.x, v.y);
        *(__half2*)(Hi + 4 * i + 2) = __floats2half2_rn(v.z, v.w);
    }
}

// mask -> fp16 penalty arrays
__global__ void pen_k(const float* __restrict__ tm, const float* __restrict__ bm)
{
    const int tid = blockIdx.x * blockDim.x + threadIdx.x;
    const int stride = gridDim.x * blockDim.x;
    for (int i = tid; i < Bn * Sn / 4; i += stride) {
        float4 v = ((const float4*)tm)[i];
        *(__half2*)&g_pen_to[4 * i] =
            __floats2half2_rn((1.f - v.x) * -10000.f, (1.f - v.y) * -10000.f);
        *(__half2*)&g_pen_to[4 * i + 2] =
            __floats2half2_rn((1.f - v.z) * -10000.f, (1.f - v.w) * -10000.f);
    }
    for (int i = tid; i < BANDSZ / 4; i += stride) {
        float4 v = ((const float4*)bm)[i];
        *(__half2*)&g_pen_band[4 * i] =
            __floats2half2_rn((1.f - v.x) * -10000.f, (1.f - v.y) * -10000.f);
        *(__half2*)&g_pen_band[4 * i + 2] =
            __floats2half2_rn((1.f - v.z) * -10000.f, (1.f - v.w) * -10000.f);
    }
}

__global__ void packW_all(const float* __restrict__ Wq, const float* __restrict__ Wk,
                          const float* __restrict__ Wv, const float* __restrict__ Wu)
{
    __shared__ float tile[32][33];
    const int z = blockIdx.z;
    const float* W = (z == 0) ? Wq : (z == 1) ? Wk : (z == 2) ? Wv : Wu;
    __half* Bh = (z < 3) ? g_Bqkv_h : g_Bu_h;
    const int nOff = (z < 3) ? z * 1024 : 0;

    const int tx = threadIdx.x, ty = threadIdx.y;
    const int n0 = blockIdx.x * 32, k0 = blockIdx.y * 32;
#pragma unroll
    for (int j = 0; j < 4; j++)
        tile[ty + j * 8][tx] = W[(size_t)(k0 + ty + j * 8) * Dn + n0 + tx];
    __syncthreads();
    const int kk = k0 + tx;
#pragma unroll
    for (int j = 0; j < 4; j++) {
        const int n = n0 + ty + j * 8;
        Bh[(size_t)(nOff + n) * Dn + kk] = __float2half_rn(tile[tx][ty + j * 8]);
    }
}

// ---------------------------------------------------------------------------
// fp16 HMMA GEMM, single product Ah.Bh, 3-stage pipeline, 2 CTAs/SM.
// ---------------------------------------------------------------------------
template <int MODE>
__global__ void __launch_bounds__(256, 2)
hmma_gemm(const __half* __restrict__ Ahi, const __half* __restrict__ Bh,
          const float* __restrict__ bias, float* __restrict__ Cout)
{
    extern __shared__ char smem[];
    const uint32_t sb = smem_u32(smem);
    const int t    = threadIdx.x;
    const int lane = t & 31;
    const int wid  = t >> 5;
    const int wm   = (wid & 1) << 6;
    const int wn   = (wid >> 1) << 5;
    const int m0   = blockIdx.y << 7;
    const int n0   = blockIdx.x << 7;

    auto load_stage = [&](int kc, int s) {
        const int kel = kc * BK;
        const uint32_t stb = sb + s * STG;
#pragma unroll
        for (int j = 0; j < 4; j++) {
            const int idx = t + (j << 8);
            const int mat = idx >> 9;
            const int rr  = (idx >> 2) & 127;
            const int cc  = idx & 3;
            const __half* src = mat
                ? Bh  + (size_t)(n0 + rr) * Dn + kel + (cc << 3)
                : Ahi + (size_t)(m0 + rr) * Dn + kel + (cc << 3);
            cpa16(stb + mat * MATB + rr * ROWB + (cc << 4), src);
        }
        cpa_commit();
    };

    float acc[4][4][4];
#pragma unroll
    for (int i = 0; i < 4; i++)
#pragma unroll
        for (int j = 0; j < 4; j++)
#pragma unroll
            for (int q = 0; q < 4; q++) acc[i][j][q] = 0.f;

    load_stage(0, 0);
    load_stage(1, 1);

    for (int kc = 0; kc < NCHUNK; ++kc) {
        if (kc + 2 < NCHUNK) { load_stage(kc + 2, (kc + 2) % 3); cpa_wait<2>(); }
        else if (kc + 1 < NCHUNK) cpa_wait<1>();
        else cpa_wait<0>();
        __syncthreads();
        const uint32_t stb = sb + (kc % 3) * STG;

#pragma unroll
        for (int k16 = 0; k16 < 2; k16++) {
            uint32_t ah[16];
            const uint32_t abase = stb + (wm + (lane & 15)) * ROWB +
                                   (k16 << 5) + ((lane >> 4) << 4);
#pragma unroll
            for (int mt = 0; mt < 4; mt++)
                ldm4(ah + 4 * mt, abase + mt * 16 * ROWB);
#pragma unroll
            for (int ng = 0; ng < 2; ng++) {
                uint32_t bh4[4];
                const uint32_t bbase = stb + MATB +
                                       (wn + ng * 16 + (lane & 15)) * ROWB +
                                       (k16 << 5) + ((lane >> 4) << 4);
                ldm4(bh4, bbase);
#pragma unroll
                for (int mt = 0; mt < 4; mt++) {
#pragma unroll
                    for (int nn = 0; nn < 2; nn++) {
                        mma16816(acc[mt][ng * 2 + nn], ah + 4 * mt,
                                 nn ? bh4[1] : bh4[0], nn ? bh4[3] : bh4[2]);
                    }
                }
            }
        }
        __syncthreads();
    }

    const int rbase = m0 + wm + (lane >> 2);
    const int cbase = (lane & 3) << 1;
#pragma unroll
    for (int mt = 0; mt < 4; mt++) {
#pragma unroll
        for (int nf = 0; nf < 4; nf++) {
            const int n = n0 + wn + ((nf >> 1) << 4) + ((nf & 1) << 3) + cbase;
            const float* c = acc[mt][nf];
#pragma unroll
            for (int half = 0; half < 2; half++) {
                const int r = rbase + mt * 16 + half * 8;
                float v0 = c[2 * half], v1 = c[2 * half + 1];
                if (MODE == 0) {
                    *(float2*)&Cout[(size_t)r * Dn + n] =
                        make_float2(v0 + bias[n], v1 + bias[n + 1]);
                } else {
                    const int mat = n >> 10;
                    const int nn  = n & 1023;
                    const int h   = nn >> 6;
                    const int e   = nn & 63;
                    const int b   = r >> 12;
                    const int s   = r & (Sn - 1);
                    const size_t off = ((size_t)(b * Hn + h) * Sn + s) * DHn + e;
                    if (mat == 0) { v0 *= 0.125f; v1 *= 0.125f; }
                    __half* arr = (mat == 0) ? g_qhi : (mat == 1) ? g_khi : g_vhi;
                    *(__half2*)&arr[off] = __floats2half2_rn(v0, v1);
                }
            }
        }
    }
}

// ---------------------------------------------------------------------------
// Flash attention, single product, split-K on global blocks.
// Mask step reads precomputed fp16 penalties (half2 loads).
// ---------------------------------------------------------------------------
__device__ __forceinline__ int kb_of(int jb, int kt, int& mtype, int& kc0) {
    mtype = 0; kc0 = 0;
    if (jb <= NGn) return kt * 64;
    if (jb == NBn - 1) return (kt < 2) ? kt * 64 : (Sn - 192 + (kt - 2) * 64);
    if (kt < 2) return kt * 64;
    mtype = 1; kc0 = (kt - 2) * 64;
    return (jb - 1) * 64 + (kt - 2) * 64;
}

__global__ void __launch_bounds__(128, 3)
attn_k(const float* __restrict__ from_mask)
{
    extern __shared__ char smem[];
    const uint32_t sb = smem_u32(smem);
    const int t = threadIdx.x, lane = t & 31, wid = t >> 5;
    const int idx = blockIdx.x;

    int jb, bh, kt0, ntiles;
    bool gmode;
    if (idx < NPART) {
        gmode = true;
        jb  = idx >> 8;
        bh  = (idx >> 3) & 31;
        kt0 = (idx & 7) * NSPLIT;
        ntiles = NSPLIT;
    } else {
        gmode = false;
        const int i2 = idx - NPART;
        jb  = (i2 >> 5) + NGn;
        bh  = i2 & 31;
        kt0 = 0;
        ntiles = 5;
    }
    const int b = bh >> 4, h = bh & 15;
    const int wm = wid << 4;

    const size_t hoff = (size_t)(b * Hn + h) * Sn * DHn;
    const __half* qhg = g_qhi + hoff + (size_t)jb * 64 * DHn;
    const __half* khg = g_khi + hoff;
    const __half* vhg = g_vhi + hoff;

#pragma unroll
    for (int j = 0; j < 4; j++) {
        const int i2 = t + (j << 7);
        const int rr  = (i2 >> 3) & 63;
        const int cc  = i2 & 7;
        cpa16(sb + rr * AROW + (cc << 4), qhg + rr * DHn + (cc << 3));
    }
    cpa_commit();

    auto loadKV = [&](int kb, int s) {
        const uint32_t base = sb + AQ_BYTES + s * ASTAGE;
#pragma unroll
        for (int j = 0; j < 8; j++) {
            const int i2 = t + (j << 7);
            const int mat = i2 >> 9;
            const int rr  = (i2 >> 3) & 63;
            const int cc  = i2 & 7;
            const __half* src = (mat ? vhg : khg) +
                (size_t)(kb + rr) * DHn + (cc << 3);
            cpa16(base + mat * AMAT + rr * AROW + (cc << 4), src);
        }
        cpa_commit();
    };

    int mty, kc0_;
    loadKV(kb_of(jb, kt0, mty, kc0_), 0);

    uint32_t qh[4][4];
    float pv[8][4];
#pragma unroll
    for (int f = 0; f < 8; f++)
#pragma unroll
        for (int q = 0; q < 4; q++) pv[f][q] = 0.f;
    float mrow0 = -1e30f, mrow1 = -1e30f, lrow0 = 0.f, lrow1 = 0.f;

    for (int kt = 0; kt < ntiles; ++kt) {
        if (kt + 1 < ntiles) {
            int mt2, kc2;
            loadKV(kb_of(jb, kt0 + kt + 1, mt2, kc2), (kt + 1) & 1);
            cpa_wait<1>();
        } else {
            cpa_wait<0>();
        }
        __syncthreads();

        if (kt == 0) {
            const uint32_t qbase = sb + (wm + (lane & 15)) * AROW + ((lane >> 4) << 4);
#pragma unroll
            for (int ks = 0; ks < 4; ks++)
                ldm4(qh[ks], qbase + (ks << 5));
        }

        int mtype, kcol0;
        const int kb = kb_of(jb, kt0 + kt, mtype, kcol0);
        const uint32_t SK = sb + AQ_BYTES + (kt & 1) * ASTAGE;
        const uint32_t SV = SK + AMAT;

        float sf[8][4];
#pragma unroll
        for (int f = 0; f < 8; f++)
#pragma unroll
            for (int q = 0; q < 4; q++) sf[f][q] = 0.f;
#pragma unroll
        for (int ks = 0; ks < 4; ks++) {
#pragma unroll
            for (int kg = 0; kg < 4; kg++) {
                uint32_t kh4[4];
                const uint32_t ka = SK + (kg * 16 + (lane & 15)) * AROW +
                                    (ks << 5) + ((lane >> 4) << 4);
                ldm4(kh4, ka);
#pragma unroll
                for (int nn = 0; nn < 2; nn++)
                    mma16816(sf[kg * 2 + nn], qh[ks],
                             nn ? kh4[1] : kh4[0], nn ? kh4[3] : kh4[2]);
            }
        }

        const int colb = (lane & 3) << 1;
        if (mtype == 0) {
            const __half* pt = &g_pen_to[b * Sn + kb + colb];
#pragma unroll
            for (int f = 0; f < 8; f++) {
                const float2 p = __half22float2(*(const __half2*)&pt[f * 8]);
                sf[f][0] += p.x;
                sf[f][1] += p.y;
                sf[f][2] += p.x;
                sf[f][3] += p.y;
            }
        } else {
            const int m_idx = jb - (NGn + 1);
            const int qi0 = wm + (lane >> 2);
            const __half* bm0 = g_pen_band +
                ((size_t)(b * NMIDn + m_idx) * 64 + qi0) * 192 + kcol0 + colb;
#pragma unroll
            for (int f = 0; f < 8; f++) {
                const float2 p0 = __half22float2(*(const __half2*)&bm0[f * 8]);
                const float2 p1 = __half22float2(*(const __half2*)&bm0[8 * 192 + f * 8]);
                sf[f][0] += p0.x;
                sf[f][1] += p0.y;
                sf[f][2] += p1.x;
                sf[f][3] += p1.y;
            }
        }

        float mx0 = -1e30f, mx1 = -1e30f;
#pragma unroll
        for (int f = 0; f < 8; f++) {
            mx0 = fmaxf(mx0, fmaxf(sf[f][0], sf[f][1]));
            mx1 = fmaxf(mx1, fmaxf(sf[f][2], sf[f][3]));
        }
        mx0 = fmaxf(mx0, __shfl_xor_sync(0xffffffffu, mx0, 1));
        mx0 = fmaxf(mx0, __shfl_xor_sync(0xffffffffu, mx0, 2));
        mx1 = fmaxf(mx1, __shfl_xor_sync(0xffffffffu, mx1, 1));
        mx1 = fmaxf(mx1, __shfl_xor_sync(0xffffffffu, mx1, 2));

        const float nm0 = fmaxf(mrow0, mx0), nm1 = fmaxf(mrow1, mx1);
        const float corr0 = __expf(mrow0 - nm0), corr1 = __expf(mrow1 - nm1);
        mrow0 = nm0; mrow1 = nm1;
        lrow0 *= corr0; lrow1 *= corr1;
#pragma unroll
        for (int f = 0; f < 8; f++) {
            pv[f][0] *= corr0; pv[f][1] *= corr0;
            pv[f][2] *= corr1; pv[f][3] *= corr1;
        }

        float rs0 = 0.f, rs1 = 0.f;
#pragma unroll
        for (int f = 0; f < 8; f++) {
            sf[f][0] = __expf(sf[f][0] - nm0);
            sf[f][1] = __expf(sf[f][1] - nm0);
            sf[f][2] = __expf(sf[f][2] - nm1);
            sf[f][3] = __expf(sf[f][3] - nm1);
            rs0 += sf[f][0] + sf[f][1];
            rs1 += sf[f][2] + sf[f][3];
        }
        rs0 += __shfl_xor_sync(0xffffffffu, rs0, 1);
        rs0 += __shfl_xor_sync(0xffffffffu, rs0, 2);
        rs1 += __shfl_xor_sync(0xffffffffu, rs1, 1);
        rs1 += __shfl_xor_sync(0xffffffffu, rs1, 2);
        lrow0 += rs0; lrow1 += rs1;

#pragma unroll
        for (int kg = 0; kg < 4; kg++) {
            uint32_t pa[4];
            pa[0] = hpack(sf[2 * kg][0],     sf[2 * kg][1]);
            pa[1] = hpack(sf[2 * kg][2],     sf[2 * kg][3]);
            pa[2] = hpack(sf[2 * kg + 1][0], sf[2 * kg + 1][1]);
            pa[3] = hpack(sf[2 * kg + 1][2], sf[2 * kg + 1][3]);
#pragma unroll
            for (int eg = 0; eg < 4; eg++) {
                uint32_t vh4[4];
                const uint32_t va = SV +
                    (kg * 16 + (((lane >> 3) & 1) << 3) + (lane & 7)) * AROW +
                    (eg << 5) + ((lane >> 4) << 4);
                ldm4t(vh4, va);
#pragma unroll
                for (int nn = 0; nn < 2; nn++)
                    mma16816(pv[eg * 2 + nn], pa, vh4[nn * 2], vh4[nn * 2 + 1]);
            }
        }
        __syncthreads();
    }

    const int r0 = wm + (lane >> 2);
    const int r1 = r0 + 8;
    if (gmode) {
        if ((lane & 3) == 0) {
            g_pm[idx * 64 + r0] = mrow0;  g_pl[idx * 64 + r0] = lrow0;
            g_pm[idx * 64 + r1] = mrow1;  g_pl[idx * 64 + r1] = lrow1;
        }
#pragma unroll
        for (int f = 0; f < 8; f++) {
            const int e = f * 8 + ((lane & 3) << 1);
            *(__half2*)&g_ppv[((size_t)idx * 64 + r0) * 64 + e] =
                __floats2half2_rn(pv[f][0], pv[f][1]);
            *(__half2*)&g_ppv[((size_t)idx * 64 + r1) * 64 + e] =
                __floats2half2_rn(pv[f][2], pv[f][3]);
        }
    } else {
        const int srow0 = jb * 64 + r0;
        const int srow1 = jb * 64 + r1;
        const float sc0 = from_mask[b * Sn + srow0] / lrow0;
        const float sc1 = from_mask[b * Sn + srow1] / lrow1;
#pragma unroll
        for (int f = 0; f < 8; f++) {
            const int e = f * 8 + ((lane & 3) << 1);
            const size_t o0 = (size_t)(b * Sn + srow0) * Dn + h * 64 + e;
            const size_t o1 = (size_t)(b * Sn + srow1) * Dn + h * 64 + e;
            *(__half2*)&g_Chi[o0] = __floats2half2_rn(pv[f][0] * sc0, pv[f][1] * sc0);
            *(__half2*)&g_Chi[o1] = __floats2half2_rn(pv[f][2] * sc1, pv[f][3] * sc1);
        }
    }
}

// ---------------------------------------------------------------------------
// Reduce: merge 8 fp16 flash partials per (jb<2, b, h), write ctx.
// ---------------------------------------------------------------------------
__global__ void __launch_bounds__(256)
attn_reduce(const float* __restrict__ from_mask)
{
    const int g  = blockIdx.x;
    const int jb = g >> 5, bh = g & 31;
    const int b  = bh >> 4, h = bh & 15;
    const int t  = threadIdx.x;
    const int row = t >> 2, q = t & 3;
    const int slot0 = jb * 256 + bh * 8;

    float m = -1e30f;
#pragma unroll
    for (int c = 0; c < NSPLIT; c++)
        m = fmaxf(m, g_pm[(slot0 + c) * 64 + row]);

    float l = 0.f;
    float acc[16];
#pragma unroll
    for (int i = 0; i < 16; i++) acc[i] = 0.f;

#pragma unroll
    for (int c = 0; c < NSPLIT; c++) {
        const int sl = slot0 + c;
        const float w = __expf(g_pm[sl * 64 + row] - m);
        l += g_pl[sl * 64 + row] * w;
        const __half* pp = &g_ppv[((size_t)sl * 64 + row) * 64 + q * 16];
#pragma unroll
        for (int i = 0; i < 16; i += 2) {
            const __half2 v = *(const __half2*)(pp + i);
            acc[i]     += __low2float(v)  * w;
            acc[i + 1] += __high2float(v) * w;
        }
    }

    const int srow = jb * 64 + row;
    const float sc = from_mask[b * Sn + srow] / l;
    __half* dst = &g_Chi[(size_t)(b * Sn + srow) * Dn + h * 64 + q * 16];
#pragma unroll
    for (int i = 0; i < 16; i += 2)
        *(__half2*)(dst + i) = __floats2half2_rn(acc[i] * sc, acc[i + 1] * sc);
}

// ---------------------------------------------------------------------------
extern "C" void kernel_launch(void* const* d_in, const int* in_sizes, int n_in,
                              void* d_out, int out_size)
{
    const float* tokens    = (const float*)d_in[0];
    const float* band_mask = (const float*)d_in[1];
    const float* from_mask = (const float*)d_in[2];
    const float* to_mask   = (const float*)d_in[3];
    const float* Wq        = (const float*)d_in[4];
    const float* Wk        = (const float*)d_in[5];
    const float* Wv        = (const float*)d_in[6];
    const float* Wu        = (const float*)d_in[7];
    const float* bu        = (const float*)d_in[8];
    (void)in_sizes; (void)n_in; (void)out_size;

    __half *ahi, *bqh, *buh, *chi;
    cudaGetSymbolAddress((void**)&ahi, g_Ahi);
    cudaGetSymbolAddress((void**)&bqh, g_Bqkv_h);
    cudaGetSymbolAddress((void**)&buh, g_Bu_h);
    cudaGetSymbolAddress((void**)&chi, g_Chi);

    cudaFuncSetAttribute(attn_k, cudaFuncAttributeMaxDynamicSharedMemorySize, ATTN_SMEM);
    cudaFuncSetAttribute(hmma_gemm<0>, cudaFuncAttributeMaxDynamicSharedMemorySize, GEMM_SMEM);
    cudaFuncSetAttribute(hmma_gemm<1>, cudaFuncAttributeMaxDynamicSharedMemorySize, GEMM_SMEM);

    split_k<<<2048, 256>>>(tokens, ahi, Mrows * Dn / 4);
    pen_k<<<1024, 256>>>(to_mask, band_mask);
    packW_all<<<dim3(32, 32, 4), dim3(32, 8)>>>(Wq, Wk, Wv, Wu);

    hmma_gemm<1><<<dim3(24, 64), 256, GEMM_SMEM>>>(ahi, bqh, nullptr, nullptr);
    attn_k<<<NGRID_A, 128, ATTN_SMEM>>>(from_mask);
    attn_reduce<<<64, 256>>>(from_mask);
    hmma_gemm<0><<<dim3(8, 64), 256, GEMM_SMEM>>>(chi, buh, bu, (float*)d_out);
}

// round 17
// speedup vs baseline: 1.9943x; 1.0224x over previous
#include <cuda_runtime.h>
#include <cuda_fp16.h>
#include <cstdint>

// ---------------------------------------------------------------------------
// BigBird transformer block on sm_103 (non-'a' target: no tcgen05/TMEM).
// R17: (1) single-barrier software pipelines (wait->sync->issue->compute)
// in both GEMMs and attention; (2) softmax exp via ex2.approx.f16x2 — the
// result is directly the packed fp16 P MMA operand (halves MUFU ops, kills
// hpack); (3) prep kernels fused into one launch.
// ---------------------------------------------------------------------------

namespace {
constexpr int Bn    = 2;
constexpr int Sn    = 4096;
constexpr int Dn    = 1024;
constexpr int Hn    = 16;
constexpr int DHn   = 64;
constexpr int NBn   = 64;
constexpr int NGn   = 2;
constexpr int NMIDn = 60;
constexpr int Mrows = Bn * Sn;              // 8192

// GEMM tiling
constexpr int BK      = 32;
constexpr int NCHUNK  = Dn / BK;             // 32
constexpr int ROWB    = 80;
constexpr int MATB    = 128 * ROWB;          // 10240
constexpr int STG     = 2 * MATB;            // 20480 B / stage
constexpr int GEMM_SMEM = 3 * STG;           // 61440 B

// attention smem
constexpr int AROW    = 144;
constexpr int AMAT    = 64 * AROW;           // 9216 B
constexpr int ASTAGE  = 2 * AMAT;            // Kh, Vh = 18432 B
constexpr int AQ_BYTES = AMAT;               // Qh only
constexpr int ATTN_SMEM = AQ_BYTES + 2 * ASTAGE;  // 46080 B

// split-K for global blocks
constexpr int NSPLIT  = 8;
constexpr int NPART   = 512;
constexpr int NGRID_A = NPART + (NBn - NGn) * 32;  // 2496

constexpr int BANDSZ  = Bn * NMIDn * 64 * 192;     // 1474560
constexpr float L2E   = 1.4426950408889634f;

// fused prep grid sections
constexpr int PREP_SPLIT = 2048;
constexpr int PREP_PACKW = 4096;
constexpr int PREP_PEN   = 512;
constexpr int PREP_GRID  = PREP_SPLIT + PREP_PACKW + PREP_PEN;  // 6656
}

// ---- scratch (device globals) ----------------------------------------------
__device__ __half g_qhi[Bn * Hn * Sn * DHn];
__device__ __half g_khi[Bn * Hn * Sn * DHn];
__device__ __half g_vhi[Bn * Hn * Sn * DHn];
__device__ __half g_Ahi[Mrows * Dn];
__device__ __half g_Bqkv_h[3 * Dn * Dn];
__device__ __half g_Bu_h[Dn * Dn];
__device__ __half g_Chi[Mrows * Dn];
__device__ float  g_pm[NPART * 64];
__device__ float  g_pl[NPART * 64];
__device__ __half g_ppv[(size_t)NPART * 64 * 64];
__device__ __half g_pen_to[Bn * Sn];
__device__ __half g_pen_band[BANDSZ];

// ---------------------------------------------------------------------------
// PTX helpers
// ---------------------------------------------------------------------------
__device__ __forceinline__ uint32_t smem_u32(const void* p) {
    uint32_t a;
    asm("{ .reg .u64 t; cvta.to.shared.u64 t, %1; cvt.u32.u64 %0, t; }" : "=r"(a) : "l"(p));
    return a;
}
__device__ __forceinline__ void cpa16(uint32_t dst, const void* src) {
    asm volatile("cp.async.cg.shared.global [%0], [%1], 16;" :: "r"(dst), "l"(src));
}
__device__ __forceinline__ void cpa_commit() {
    asm volatile("cp.async.commit_group;" ::: "memory");
}
template <int N>
__device__ __forceinline__ void cpa_wait() {
    asm volatile("cp.async.wait_group %0;" :: "n"(N) : "memory");
}
__device__ __forceinline__ void ldm4(uint32_t* r, uint32_t addr) {
    asm volatile("ldmatrix.sync.aligned.m8n8.x4.shared.b16 {%0,%1,%2,%3}, [%4];"
                 : "=r"(r[0]), "=r"(r[1]), "=r"(r[2]), "=r"(r[3]) : "r"(addr));
}
__device__ __forceinline__ void ldm4t(uint32_t* r, uint32_t addr) {
    asm volatile("ldmatrix.sync.aligned.m8n8.x4.trans.shared.b16 {%0,%1,%2,%3}, [%4];"
                 : "=r"(r[0]), "=r"(r[1]), "=r"(r[2]), "=r"(r[3]) : "r"(addr));
}
__device__ __forceinline__ void mma16816(float* c, const uint32_t* a,
                                         uint32_t b0, uint32_t b1) {
    asm volatile(
        "mma.sync.aligned.m16n8k16.row.col.f32.f16.f16.f32 "
        "{%0,%1,%2,%3}, {%4,%5,%6,%7}, {%8,%9}, {%0,%1,%2,%3};"
        : "+f"(c[0]), "+f"(c[1]), "+f"(c[2]), "+f"(c[3])
        : "r"(a[0]), "r"(a[1]), "r"(a[2]), "r"(a[3]), "r"(b0), "r"(b1));
}
__device__ __forceinline__ uint32_t hpack(float v0, float v1) {
    __half2 h = __floats2half2_rn(v0, v1);
    return *reinterpret_cast<uint32_t*>(&h);
}
__device__ __forceinline__ uint32_t h2exp2(uint32_t x) {  // 2^x on f16x2
    uint32_t r;
    asm("ex2.approx.f16x2 %0, %1;" : "=r"(r) : "r"(x));
    return r;
}
__device__ __forceinline__ float2 h2f2(uint32_t x) {
    return __half22float2(*reinterpret_cast<__half2*>(&x));
}

// ---------------------------------------------------------------------------
// fused prep: [0,2048) token split, [2048,6144) weight packs, [6144,6656) pens
// ---------------------------------------------------------------------------
__global__ void prep_all(const float* __restrict__ tokens,
                         const float* __restrict__ to_mask,
                         const float* __restrict__ band_mask,
                         const float* __restrict__ Wq, const float* __restrict__ Wk,
                         const float* __restrict__ Wv, const float* __restrict__ Wu)
{
    __shared__ float tile[32][33];
    const int bid = blockIdx.x;
    const int t = threadIdx.x;

    if (bid < PREP_SPLIT) {
        const int n4 = Mrows * Dn / 4;
        for (int i = bid * 256 + t; i < n4; i += PREP_SPLIT * 256) {
            float4 v = ((const float4*)tokens)[i];
            *(__half2*)(g_Ahi + 4 * i)     = __floats2half2_rn(v.x, v.y);
            *(__half2*)(g_Ahi + 4 * i + 2) = __floats2half2_rn(v.z, v.w);
        }
    } else if (bid < PREP_SPLIT + PREP_PACKW) {
        const int pb = bid - PREP_SPLIT;
        const int z = pb >> 10;
        const int within = pb & 1023;
        const float* W = (z == 0) ? Wq : (z == 1) ? Wk : (z == 2) ? Wv : Wu;
        __half* Bh = (z < 3) ? g_Bqkv_h : g_Bu_h;
        const int nOff = (z < 3) ? z * 1024 : 0;
        const int n0 = (within & 31) * 32, k0 = (within >> 5) * 32;
        const int tx = t & 31, ty = t >> 5;
#pragma unroll
        for (int j = 0; j < 4; j++)
            tile[ty + j * 8][tx] = W[(size_t)(k0 + ty + j * 8) * Dn + n0 + tx];
        __syncthreads();
        const int kk = k0 + tx;
#pragma unroll
        for (int j = 0; j < 4; j++) {
            const int n = n0 + ty + j * 8;
            Bh[(size_t)(nOff + n) * Dn + kk] = __float2half_rn(tile[tx][ty + j * 8]);
        }
    } else {
        const int pb = bid - PREP_SPLIT - PREP_PACKW;
        const int tid = pb * 256 + t;
        const int stride = PREP_PEN * 256;
        for (int i = tid; i < Bn * Sn / 4; i += stride) {
            float4 v = ((const float4*)to_mask)[i];
            *(__half2*)&g_pen_to[4 * i] =
                __floats2half2_rn((1.f - v.x) * -10000.f, (1.f - v.y) * -10000.f);
            *(__half2*)&g_pen_to[4 * i + 2] =
                __floats2half2_rn((1.f - v.z) * -10000.f, (1.f - v.w) * -10000.f);
        }
        for (int i = tid; i < BANDSZ / 4; i += stride) {
            float4 v = ((const float4*)band_mask)[i];
            *(__half2*)&g_pen_band[4 * i] =
                __floats2half2_rn((1.f - v.x) * -10000.f, (1.f - v.y) * -10000.f);
            *(__half2*)&g_pen_band[4 * i + 2] =
                __floats2half2_rn((1.f - v.z) * -10000.f, (1.f - v.w) * -10000.f);
        }
    }
}

// ---------------------------------------------------------------------------
// fp16 HMMA GEMM, single product, 3-stage single-barrier pipeline, 2 CTAs/SM.
// ---------------------------------------------------------------------------
template <int MODE>
__global__ void __launch_bounds__(256, 2)
hmma_gemm(const __half* __restrict__ Ahi, const __half* __restrict__ Bh,
          const float* __restrict__ bias, float* __restrict__ Cout)
{
    extern __shared__ char smem[];
    const uint32_t sb = smem_u32(smem);
    const int t    = threadIdx.x;
    const int lane = t & 31;
    const int wid  = t >> 5;
    const int wm   = (wid & 1) << 6;
    const int wn   = (wid >> 1) << 5;
    const int m0   = blockIdx.y << 7;
    const int n0   = blockIdx.x << 7;

    auto load_stage = [&](int kc, int s) {
        const int kel = kc * BK;
        const uint32_t stb = sb + s * STG;
#pragma unroll
        for (int j = 0; j < 4; j++) {
            const int idx = t + (j << 8);
            const int mat = idx >> 9;
            const int rr  = (idx >> 2) & 127;
            const int cc  = idx & 3;
            const __half* src = mat
                ? Bh  + (size_t)(n0 + rr) * Dn + kel + (cc << 3)
                : Ahi + (size_t)(m0 + rr) * Dn + kel + (cc << 3);
            cpa16(stb + mat * MATB + rr * ROWB + (cc << 4), src);
        }
        cpa_commit();
    };

    float acc[4][4][4];
#pragma unroll
    for (int i = 0; i < 4; i++)
#pragma unroll
        for (int j = 0; j < 4; j++)
#pragma unroll
            for (int q = 0; q < 4; q++) acc[i][j][q] = 0.f;

    load_stage(0, 0);
    load_stage(1, 1);

    for (int kc = 0; kc < NCHUNK; ++kc) {
        if (kc + 1 < NCHUNK) cpa_wait<1>();
        else cpa_wait<0>();
        __syncthreads();
        if (kc + 2 < NCHUNK) load_stage(kc + 2, (kc + 2) % 3);
        const uint32_t stb = sb + (kc % 3) * STG;

#pragma unroll
        for (int k16 = 0; k16 < 2; k16++) {
            uint32_t ah[16];
            const uint32_t abase = stb + (wm + (lane & 15)) * ROWB +
                                   (k16 << 5) + ((lane >> 4) << 4);
#pragma unroll
            for (int mt = 0; mt < 4; mt++)
                ldm4(ah + 4 * mt, abase + mt * 16 * ROWB);
#pragma unroll
            for (int ng = 0; ng < 2; ng++) {
                uint32_t bh4[4];
                const uint32_t bbase = stb + MATB +
                                       (wn + ng * 16 + (lane & 15)) * ROWB +
                                       (k16 << 5) + ((lane >> 4) << 4);
                ldm4(bh4, bbase);
#pragma unroll
                for (int mt = 0; mt < 4; mt++) {
#pragma unroll
                    for (int nn = 0; nn < 2; nn++) {
                        mma16816(acc[mt][ng * 2 + nn], ah + 4 * mt,
                                 nn ? bh4[1] : bh4[0], nn ? bh4[3] : bh4[2]);
                    }
                }
            }
        }
    }

    const int rbase = m0 + wm + (lane >> 2);
    const int cbase = (lane & 3) << 1;
#pragma unroll
    for (int mt = 0; mt < 4; mt++) {
#pragma unroll
        for (int nf = 0; nf < 4; nf++) {
            const int n = n0 + wn + ((nf >> 1) << 4) + ((nf & 1) << 3) + cbase;
            const float* c = acc[mt][nf];
#pragma unroll
            for (int half = 0; half < 2; half++) {
                const int r = rbase + mt * 16 + half * 8;
                float v0 = c[2 * half], v1 = c[2 * half + 1];
                if (MODE == 0) {
                    *(float2*)&Cout[(size_t)r * Dn + n] =
                        make_float2(v0 + bias[n], v1 + bias[n + 1]);
                } else {
                    const int mat = n >> 10;
                    const int nn  = n & 1023;
                    const int h   = nn >> 6;
                    const int e   = nn & 63;
                    const int b   = r >> 12;
                    const int s   = r & (Sn - 1);
                    const size_t off = ((size_t)(b * Hn + h) * Sn + s) * DHn + e;
                    if (mat == 0) { v0 *= 0.125f; v1 *= 0.125f; }
                    __half* arr = (mat == 0) ? g_qhi : (mat == 1) ? g_khi : g_vhi;
                    *(__half2*)&arr[off] = __floats2half2_rn(v0, v1);
                }
            }
        }
    }
}

// ---------------------------------------------------------------------------
// Flash attention, single product, split-K, single-barrier pipeline,
// ex2.approx.f16x2 softmax producing packed P directly.
// ---------------------------------------------------------------------------
__device__ __forceinline__ int kb_of(int jb, int kt, int& mtype, int& kc0) {
    mtype = 0; kc0 = 0;
    if (jb <= NGn) return kt * 64;
    if (jb == NBn - 1) return (kt < 2) ? kt * 64 : (Sn - 192 + (kt - 2) * 64);
    if (kt < 2) return kt * 64;
    mtype = 1; kc0 = (kt - 2) * 64;
    return (jb - 1) * 64 + (kt - 2) * 64;
}

__global__ void __launch_bounds__(128, 3)
attn_k(const float* __restrict__ from_mask)
{
    extern __shared__ char smem[];
    const uint32_t sb = smem_u32(smem);
    const int t = threadIdx.x, lane = t & 31, wid = t >> 5;
    const int idx = blockIdx.x;

    int jb, bh, kt0, ntiles;
    bool gmode;
    if (idx < NPART) {
        gmode = true;
        jb  = idx >> 8;
        bh  = (idx >> 3) & 31;
        kt0 = (idx & 7) * NSPLIT;
        ntiles = NSPLIT;
    } else {
        gmode = false;
        const int i2 = idx - NPART;
        jb  = (i2 >> 5) + NGn;
        bh  = i2 & 31;
        kt0 = 0;
        ntiles = 5;
    }
    const int b = bh >> 4, h = bh & 15;
    const int wm = wid << 4;

    const size_t hoff = (size_t)(b * Hn + h) * Sn * DHn;
    const __half* qhg = g_qhi + hoff + (size_t)jb * 64 * DHn;
    const __half* khg = g_khi + hoff;
    const __half* vhg = g_vhi + hoff;

#pragma unroll
    for (int j = 0; j < 4; j++) {
        const int i2 = t + (j << 7);
        const int rr  = (i2 >> 3) & 63;
        const int cc  = i2 & 7;
        cpa16(sb + rr * AROW + (cc << 4), qhg + rr * DHn + (cc << 3));
    }
    cpa_commit();

    auto loadKV = [&](int kb, int s) {
        const uint32_t base = sb + AQ_BYTES + s * ASTAGE;
#pragma unroll
        for (int j = 0; j < 8; j++) {
            const int i2 = t + (j << 7);
            const int mat = i2 >> 9;
            const int rr  = (i2 >> 3) & 63;
            const int cc  = i2 & 7;
            const __half* src = (mat ? vhg : khg) +
                (size_t)(kb + rr) * DHn + (cc << 3);
            cpa16(base + mat * AMAT + rr * AROW + (cc << 4), src);
        }
        cpa_commit();
    };

    int mty, kc0_;
    loadKV(kb_of(jb, kt0, mty, kc0_), 0);

    uint32_t qh[4][4];
    float pv[8][4];
#pragma unroll
    for (int f = 0; f < 8; f++)
#pragma unroll
        for (int q = 0; q < 4; q++) pv[f][q] = 0.f;
    float mrow0 = -1e30f, mrow1 = -1e30f, lrow0 = 0.f, lrow1 = 0.f;

    for (int kt = 0; kt < ntiles; ++kt) {
        cpa_wait<0>();
        __syncthreads();
        if (kt + 1 < ntiles) {
            int mt2, kc2;
            loadKV(kb_of(jb, kt0 + kt + 1, mt2, kc2), (kt + 1) & 1);
        }

        if (kt == 0) {
            const uint32_t qbase = sb + (wm + (lane & 15)) * AROW + ((lane >> 4) << 4);
#pragma unroll
            for (int ks = 0; ks < 4; ks++)
                ldm4(qh[ks], qbase + (ks << 5));
        }

        int mtype, kcol0;
        const int kb = kb_of(jb, kt0 + kt, mtype, kcol0);
        const uint32_t SK = sb + AQ_BYTES + (kt & 1) * ASTAGE;
        const uint32_t SV = SK + AMAT;

        float sf[8][4];
#pragma unroll
        for (int f = 0; f < 8; f++)
#pragma unroll
            for (int q = 0; q < 4; q++) sf[f][q] = 0.f;
#pragma unroll
        for (int ks = 0; ks < 4; ks++) {
#pragma unroll
            for (int kg = 0; kg < 4; kg++) {
                uint32_t kh4[4];
                const uint32_t ka = SK + (kg * 16 + (lane & 15)) * AROW +
                                    (ks << 5) + ((lane >> 4) << 4);
                ldm4(kh4, ka);
#pragma unroll
                for (int nn = 0; nn < 2; nn++)
                    mma16816(sf[kg * 2 + nn], qh[ks],
                             nn ? kh4[1] : kh4[0], nn ? kh4[3] : kh4[2]);
            }
        }

        const int colb = (lane & 3) << 1;
        if (mtype == 0) {
            const __half* pt = &g_pen_to[b * Sn + kb + colb];
#pragma unroll
            for (int f = 0; f < 8; f++) {
                const float2 p = __half22float2(*(const __half2*)&pt[f * 8]);
                sf[f][0] += p.x;
                sf[f][1] += p.y;
                sf[f][2] += p.x;
                sf[f][3] += p.y;
            }
        } else {
            const int m_idx = jb - (NGn + 1);
            const int qi0 = wm + (lane >> 2);
            const __half* bm0 = g_pen_band +
                ((size_t)(b * NMIDn + m_idx) * 64 + qi0) * 192 + kcol0 + colb;
#pragma unroll
            for (int f = 0; f < 8; f++) {
                const float2 p0 = __half22float2(*(const __half2*)&bm0[f * 8]);
                const float2 p1 = __half22float2(*(const __half2*)&bm0[8 * 192 + f * 8]);
                sf[f][0] += p0.x;
                sf[f][1] += p0.y;
                sf[f][2] += p1.x;
                sf[f][3] += p1.y;
            }
        }

        float mx0 = -1e30f, mx1 = -1e30f;
#pragma unroll
        for (int f = 0; f < 8; f++) {
            mx0 = fmaxf(mx0, fmaxf(sf[f][0], sf[f][1]));
            mx1 = fmaxf(mx1, fmaxf(sf[f][2], sf[f][3]));
        }
        mx0 = fmaxf(mx0, __shfl_xor_sync(0xffffffffu, mx0, 1));
        mx0 = fmaxf(mx0, __shfl_xor_sync(0xffffffffu, mx0, 2));
        mx1 = fmaxf(mx1, __shfl_xor_sync(0xffffffffu, mx1, 1));
        mx1 = fmaxf(mx1, __shfl_xor_sync(0xffffffffu, mx1, 2));

        const float nm0 = fmaxf(mrow0, mx0), nm1 = fmaxf(mrow1, mx1);
        const float corr0 = __expf(mrow0 - nm0), corr1 = __expf(mrow1 - nm1);
        mrow0 = nm0; mrow1 = nm1;
        lrow0 *= corr0; lrow1 *= corr1;
#pragma unroll
        for (int f = 0; f < 8; f++) {
            pv[f][0] *= corr0; pv[f][1] *= corr0;
            pv[f][2] *= corr1; pv[f][3] *= corr1;
        }

        // P = 2^((s - m) * log2e) on f16x2 -> directly the MMA operand
        const float a0 = -nm0 * L2E, a1 = -nm1 * L2E;
        uint32_t pexp[8][2];
        float rs0 = 0.f, rs1 = 0.f;
#pragma unroll
        for (int f = 0; f < 8; f++) {
            pexp[f][0] = h2exp2(hpack(sf[f][0] * L2E + a0, sf[f][1] * L2E + a0));
            pexp[f][1] = h2exp2(hpack(sf[f][2] * L2E + a1, sf[f][3] * L2E + a1));
            const float2 p0 = h2f2(pexp[f][0]);
            const float2 p1 = h2f2(pexp[f][1]);
            rs0 += p0.x + p0.y;
            rs1 += p1.x + p1.y;
        }
        rs0 += __shfl_xor_sync(0xffffffffu, rs0, 1);
        rs0 += __shfl_xor_sync(0xffffffffu, rs0, 2);
        rs1 += __shfl_xor_sync(0xffffffffu, rs1, 1);
        rs1 += __shfl_xor_sync(0xffffffffu, rs1, 2);
        lrow0 += rs0; lrow1 += rs1;

#pragma unroll
        for (int kg = 0; kg < 4; kg++) {
            uint32_t pa[4];
            pa[0] = pexp[2 * kg][0];
            pa[1] = pexp[2 * kg][1];
            pa[2] = pexp[2 * kg + 1][0];
            pa[3] = pexp[2 * kg + 1][1];
#pragma unroll
            for (int eg = 0; eg < 4; eg++) {
                uint32_t vh4[4];
                const uint32_t va = SV +
                    (kg * 16 + (((lane >> 3) & 1) << 3) + (lane & 7)) * AROW +
                    (eg << 5) + ((lane >> 4) << 4);
                ldm4t(vh4, va);
#pragma unroll
                for (int nn = 0; nn < 2; nn++)
                    mma16816(pv[eg * 2 + nn], pa, vh4[nn * 2], vh4[nn * 2 + 1]);
            }
        }
    }

    const int r0 = wm + (lane >> 2);
    const int r1 = r0 + 8;
    if (gmode) {
        if ((lane & 3) == 0) {
            g_pm[idx * 64 + r0] = mrow0;  g_pl[idx * 64 + r0] = lrow0;
            g_pm[idx * 64 + r1] = mrow1;  g_pl[idx * 64 + r1] = lrow1;
        }
#pragma unroll
        for (int f = 0; f < 8; f++) {
            const int e = f * 8 + ((lane & 3) << 1);
            *(__half2*)&g_ppv[((size_t)idx * 64 + r0) * 64 + e] =
                __floats2half2_rn(pv[f][0], pv[f][1]);
            *(__half2*)&g_ppv[((size_t)idx * 64 + r1) * 64 + e] =
                __floats2half2_rn(pv[f][2], pv[f][3]);
        }
    } else {
        const int srow0 = jb * 64 + r0;
        const int srow1 = jb * 64 + r1;
        const float sc0 = from_mask[b * Sn + srow0] / lrow0;
        const float sc1 = from_mask[b * Sn + srow1] / lrow1;
#pragma unroll
        for (int f = 0; f < 8; f++) {
            const int e = f * 8 + ((lane & 3) << 1);
            const size_t o0 = (size_t)(b * Sn + srow0) * Dn + h * 64 + e;
            const size_t o1 = (size_t)(b * Sn + srow1) * Dn + h * 64 + e;
            *(__half2*)&g_Chi[o0] = __floats2half2_rn(pv[f][0] * sc0, pv[f][1] * sc0);
            *(__half2*)&g_Chi[o1] = __floats2half2_rn(pv[f][2] * sc1, pv[f][3] * sc1);
        }
    }
}

// ---------------------------------------------------------------------------
// Reduce: merge 8 fp16 flash partials per (jb<2, b, h), write ctx.
// ---------------------------------------------------------------------------
__global__ void __launch_bounds__(256)
attn_reduce(const float* __restrict__ from_mask)
{
    const int g  = blockIdx.x;
    const int jb = g >> 5, bh = g & 31;
    const int b  = bh >> 4, h = bh & 15;
    const int t  = threadIdx.x;
    const int row = t >> 2, q = t & 3;
    const int slot0 = jb * 256 + bh * 8;

    float m = -1e30f;
#pragma unroll
    for (int c = 0; c < NSPLIT; c++)
        m = fmaxf(m, g_pm[(slot0 + c) * 64 + row]);

    float l = 0.f;
    float acc[16];
#pragma unroll
    for (int i = 0; i < 16; i++) acc[i] = 0.f;

#pragma unroll
    for (int c = 0; c < NSPLIT; c++) {
        const int sl = slot0 + c;
        const float w = __expf(g_pm[sl * 64 + row] - m);
        l += g_pl[sl * 64 + row] * w;
        const __half* pp = &g_ppv[((size_t)sl * 64 + row) * 64 + q * 16];
#pragma unroll
        for (int i = 0; i < 16; i += 2) {
            const __half2 v = *(const __half2*)(pp + i);
            acc[i]     += __low2float(v)  * w;
            acc[i + 1] += __high2float(v) * w;
        }
    }

    const int srow = jb * 64 + row;
    const float sc = from_mask[b * Sn + srow] / l;
    __half* dst = &g_Chi[(size_t)(b * Sn + srow) * Dn + h * 64 + q * 16];
#pragma unroll
    for (int i = 0; i < 16; i += 2)
        *(__half2*)(dst + i) = __floats2half2_rn(acc[i] * sc, acc[i + 1] * sc);
}

// ---------------------------------------------------------------------------
extern "C" void kernel_launch(void* const* d_in, const int* in_sizes, int n_in,
                              void* d_out, int out_size)
{
    const float* tokens    = (const float*)d_in[0];
    const float* band_mask = (const float*)d_in[1];
    const float* from_mask = (const float*)d_in[2];
    const float* to_mask   = (const float*)d_in[3];
    const float* Wq        = (const float*)d_in[4];
    const float* Wk        = (const float*)d_in[5];
    const float* Wv        = (const float*)d_in[6];
    const float* Wu        = (const float*)d_in[7];
    const float* bu        = (const float*)d_in[8];
    (void)in_sizes; (void)n_in; (void)out_size;

    __half *ahi, *bqh, *buh, *chi;
    cudaGetSymbolAddress((void**)&ahi, g_Ahi);
    cudaGetSymbolAddress((void**)&bqh, g_Bqkv_h);
    cudaGetSymbolAddress((void**)&buh, g_Bu_h);
    cudaGetSymbolAddress((void**)&chi, g_Chi);

    cudaFuncSetAttribute(attn_k, cudaFuncAttributeMaxDynamicSharedMemorySize, ATTN_SMEM);
    cudaFuncSetAttribute(hmma_gemm<0>, cudaFuncAttributeMaxDynamicSharedMemorySize, GEMM_SMEM);
    cudaFuncSetAttribute(hmma_gemm<1>, cudaFuncAttributeMaxDynamicSharedMemorySize, GEMM_SMEM);

    prep_all<<<PREP_GRID, 256>>>(tokens, to_mask, band_mask, Wq, Wk, Wv, Wu);

    hmma_gemm<1><<<dim3(24, 64), 256, GEMM_SMEM>>>(ahi, bqh, nullptr, nullptr);
    attn_k<<<NGRID_A, 128, ATTN_SMEM>>>(from_mask);
    attn_reduce<<<64, 256>>>(from_mask);
    hmma_gemm<0><<<dim3(8, 64), 256, GEMM_SMEM>>>(chi, buh, bu, (float*)d_out);
}